// round 6
// baseline (speedup 1.0000x reference)
#include <cuda_runtime.h>
#include <cuda_bf16.h>
#include <math.h>
#include <stdint.h>

#define B_ 2
#define S_ 2048
#define D_ 2048
#define H_ 16
#define HD_ 128

// ---------------- device scratch (no runtime allocation) ----------------
__device__ float g_Q[B_ * H_ * S_ * HD_];   // [b][h][s][hd] fp32 (pre-rope)
__device__ float g_K[B_ * H_ * S_ * HD_];
__device__ float g_V[B_ * H_ * S_ * HD_];
__device__ float g_AO[B_ * S_ * D_];        // [b][s][d]

__device__ __nv_bfloat16 g_xhi[B_ * S_ * D_];
__device__ __nv_bfloat16 g_xlo[B_ * S_ * D_];
__device__ __nv_bfloat16 g_wqhi[D_ * D_], g_wqlo[D_ * D_];
__device__ __nv_bfloat16 g_wkhi[D_ * D_], g_wklo[D_ * D_];
__device__ __nv_bfloat16 g_wvhi[D_ * D_], g_wvlo[D_ * D_];
__device__ __nv_bfloat16 g_wohi[D_ * D_], g_wolo[D_ * D_];
__device__ __nv_bfloat16 g_aohi[B_ * S_ * D_];
__device__ __nv_bfloat16 g_aolo[B_ * S_ * D_];

// attention operands (bf16 hi/lo, head layout)
__device__ __nv_bfloat16 g_qh[B_ * H_ * S_ * HD_], g_ql[B_ * H_ * S_ * HD_];
__device__ __nv_bfloat16 g_kh[B_ * H_ * S_ * HD_], g_kl[B_ * H_ * S_ * HD_];
__device__ __nv_bfloat16 g_vh[B_ * H_ * S_ * HD_], g_vl[B_ * H_ * S_ * HD_];

__device__ float g_cos[S_ * 64];
__device__ float g_sin[S_ * 64];

// ---------------- helpers ----------------
__device__ __forceinline__ uint32_t smem_u32(const void* p) {
    uint32_t a;
    asm("{ .reg .u64 t; cvta.to.shared.u64 t, %1; cvt.u32.u64 %0, t; }"
        : "=r"(a) : "l"(p));
    return a;
}
// swizzle for 64B rows (256-tile GEMM): XOR col bits[4:5] with row bits[1:2]
static __device__ __forceinline__ uint32_t swz64(uint32_t o) {
    return o ^ ((o >> 3) & 0x30);
}
// swizzle for 256B rows (flash tiles)
static __device__ __forceinline__ uint32_t swzf(uint32_t row, uint32_t colbyte) {
    return row * 256u + (colbyte ^ ((row & 7u) << 4));
}
__device__ __forceinline__ void cp16(uint32_t saddr, const void* gptr) {
    asm volatile("cp.async.cg.shared.global [%0], [%1], 16;"
                 :: "r"(saddr), "l"(gptr) : "memory");
}
#define CP_COMMIT() asm volatile("cp.async.commit_group;" ::: "memory")

__device__ __forceinline__ void ldsm_x4(uint32_t a, uint32_t* r) {
    asm volatile("ldmatrix.sync.aligned.m8n8.x4.shared.b16 {%0,%1,%2,%3}, [%4];"
                 : "=r"(r[0]), "=r"(r[1]), "=r"(r[2]), "=r"(r[3]) : "r"(a));
}
__device__ __forceinline__ void ldsm_x2(uint32_t a, uint32_t* r) {
    asm volatile("ldmatrix.sync.aligned.m8n8.x2.shared.b16 {%0,%1}, [%2];"
                 : "=r"(r[0]), "=r"(r[1]) : "r"(a));
}
__device__ __forceinline__ void ldsm_x2t(uint32_t a, uint32_t* r) {
    asm volatile("ldmatrix.sync.aligned.m8n8.x2.trans.shared.b16 {%0,%1}, [%2];"
                 : "=r"(r[0]), "=r"(r[1]) : "r"(a));
}
__device__ __forceinline__ void mma16816(float* d, const uint32_t* a, const uint32_t* b) {
    asm volatile(
        "mma.sync.aligned.m16n8k16.row.col.f32.bf16.bf16.f32 "
        "{%0,%1,%2,%3}, {%4,%5,%6,%7}, {%8,%9}, {%0,%1,%2,%3};"
        : "+f"(d[0]), "+f"(d[1]), "+f"(d[2]), "+f"(d[3])
        : "r"(a[0]), "r"(a[1]), "r"(a[2]), "r"(a[3]), "r"(b[0]), "r"(b[1]));
}
__device__ __forceinline__ uint32_t pack2(__nv_bfloat16 a, __nv_bfloat16 b) {
    __nv_bfloat162 t(a, b);
    return *(uint32_t*)&t;
}

// ---------------------------------------------------------------------------
// Split fp32 -> bf16 hi/lo (Markidis). Vectorized by 4.
// ---------------------------------------------------------------------------
__global__ void split_bf16(const float* __restrict__ in,
                           __nv_bfloat16* __restrict__ hi,
                           __nv_bfloat16* __restrict__ lo, int n4)
{
    int i = blockIdx.x * blockDim.x + threadIdx.x;
    if (i >= n4) return;
    float4 v = ((const float4*)in)[i];
    __nv_bfloat16 h0 = __float2bfloat16(v.x);
    __nv_bfloat16 h1 = __float2bfloat16(v.y);
    __nv_bfloat16 h2 = __float2bfloat16(v.z);
    __nv_bfloat16 h3 = __float2bfloat16(v.w);
    __nv_bfloat16 l0 = __float2bfloat16(v.x - __bfloat162float(h0));
    __nv_bfloat16 l1 = __float2bfloat16(v.y - __bfloat162float(h1));
    __nv_bfloat16 l2 = __float2bfloat16(v.z - __bfloat162float(h2));
    __nv_bfloat16 l3 = __float2bfloat16(v.w - __bfloat162float(h3));
    __nv_bfloat162* hi2 = (__nv_bfloat162*)hi;
    __nv_bfloat162* lo2 = (__nv_bfloat162*)lo;
    hi2[2 * i]     = __nv_bfloat162(h0, h1);
    hi2[2 * i + 1] = __nv_bfloat162(h2, h3);
    lo2[2 * i]     = __nv_bfloat162(l0, l1);
    lo2[2 * i + 1] = __nv_bfloat162(l2, l3);
}

// ---------------------------------------------------------------------------
// split-bf16 SGEMM, 256x256 block tile (L2-traffic-optimal).
// 512 threads = 16 warps (4x4), warp tile 64x64. K-chunk 32 bf16 (64B rows,
// SW64 swizzle). Double-buffered cp.async (128 KB smem).
// C[m,n] = sum_k A[m,k]*B[n,k]; head_layout=1 -> [b][h][s][hd].
// ---------------------------------------------------------------------------
#define TCT256 16384u                     // bytes per tile (256 rows x 64B)
#define TCBUF  (4u * TCT256)              // 4 tiles per buffer = 64KB
#define TC_SMEM_BYTES (2u * TCBUF)        // 128KB

__global__ void __launch_bounds__(512, 1)
sgemm_tc(const __nv_bfloat16* __restrict__ Ahi, const __nv_bfloat16* __restrict__ Alo,
         const __nv_bfloat16* __restrict__ Bhi, const __nv_bfloat16* __restrict__ Blo,
         float* __restrict__ C, int head_layout)
{
    extern __shared__ char smem[];
    const uint32_t sbase = smem_u32(smem);

    const int tid  = threadIdx.x;
    const int lane = tid & 31;
    const int w    = tid >> 5;
    const int m0w  = (w >> 2) * 64;       // 0..192
    const int n0w  = (w & 3) * 64;        // 0..192

    const int m0 = blockIdx.y * 256;
    const int n0 = blockIdx.x * 256;

    // per-thread cp.async slots: 2 per tile (1024 chunks / 512 threads)
    uint32_t swofs[2];
    int rsl[2], csl[2];
#pragma unroll
    for (int t = 0; t < 2; t++) {
        const int idx = tid + t * 512;
        rsl[t] = idx >> 2;                // 0..255
        csl[t] = idx & 3;                 // 16B col within 64B row
        swofs[t] = swz64((uint32_t)(rsl[t] * 64 + csl[t] * 16));
    }

    float acc[4][8][4];
#pragma unroll
    for (int i = 0; i < 4; i++)
#pragma unroll
        for (int j = 0; j < 8; j++)
#pragma unroll
            for (int r = 0; r < 4; r++) acc[i][j][r] = 0.0f;

    const uint32_t arow = (uint32_t)(m0w + (lane & 15));
    const uint32_t acol = (uint32_t)((lane >> 4) << 4);
    const uint32_t brow = (uint32_t)(n0w + (lane & 7));
    const uint32_t bcol = (uint32_t)(((lane >> 3) & 1) << 4);

#define LOAD_CHUNK(c, buf)                                                     \
    {                                                                          \
        const uint32_t bofs = sbase + (uint32_t)(buf) * TCBUF;                 \
        const int k0 = (c) * 32;                                               \
        _Pragma("unroll")                                                      \
        for (int t = 0; t < 2; t++) {                                          \
            const size_t ga = (size_t)(m0 + rsl[t]) * D_ + k0 + csl[t] * 8;    \
            const size_t gb = (size_t)(n0 + rsl[t]) * D_ + k0 + csl[t] * 8;    \
            cp16(bofs + 0u * TCT256 + swofs[t], Ahi + ga);                     \
            cp16(bofs + 1u * TCT256 + swofs[t], Alo + ga);                     \
            cp16(bofs + 2u * TCT256 + swofs[t], Bhi + gb);                     \
            cp16(bofs + 3u * TCT256 + swofs[t], Blo + gb);                     \
        }                                                                      \
        CP_COMMIT();                                                           \
    }

    LOAD_CHUNK(0, 0);

    for (int c = 0; c < 64; c++) {
        if (c < 63) {
            LOAD_CHUNK(c + 1, (c + 1) & 1);
            asm volatile("cp.async.wait_group 1;" ::: "memory");
        } else {
            asm volatile("cp.async.wait_group 0;" ::: "memory");
        }
        __syncthreads();

        const uint32_t bofs = sbase + (uint32_t)(c & 1) * TCBUF;
        const uint32_t Ab_hi = bofs + 0u * TCT256;
        const uint32_t Ab_lo = bofs + 1u * TCT256;
        const uint32_t Bb_hi = bofs + 2u * TCT256;
        const uint32_t Bb_lo = bofs + 3u * TCT256;

#pragma unroll
        for (int kk = 0; kk < 2; kk++) {
            const uint32_t kb = (uint32_t)(kk * 32);
            uint32_t ah[4][4], al[4][4];
#pragma unroll
            for (int mt = 0; mt < 4; mt++) {
                const uint32_t ofs = swz64((arow + mt * 16u) * 64u + acol + kb);
                ldsm_x4(Ab_hi + ofs, ah[mt]);
                ldsm_x4(Ab_lo + ofs, al[mt]);
            }
#pragma unroll
            for (int nt = 0; nt < 8; nt++) {
                const uint32_t ofs = swz64((brow + nt * 8u) * 64u + bcol + kb);
                uint32_t bhf[2], blf[2];
                ldsm_x2(Bb_hi + ofs, bhf);
                ldsm_x2(Bb_lo + ofs, blf);
#pragma unroll
                for (int mt = 0; mt < 4; mt++) {
                    mma16816(acc[mt][nt], ah[mt], bhf);
                    mma16816(acc[mt][nt], ah[mt], blf);
                    mma16816(acc[mt][nt], al[mt], bhf);
                }
            }
        }
        __syncthreads();
    }

    // epilogue
    const int lr = lane >> 2;
    const int lc = (lane & 3) * 2;
#pragma unroll
    for (int mt = 0; mt < 4; mt++) {
#pragma unroll
        for (int rr = 0; rr < 2; rr++) {
            const int m = m0 + m0w + mt * 16 + rr * 8 + lr;
            const int e = rr * 2;
            if (head_layout) {
                const int bb = m >> 11, s = m & (S_ - 1);
                const size_t rowoff = ((size_t)(bb * H_) * S_ + s) * HD_;
#pragma unroll
                for (int nt = 0; nt < 8; nt++) {
                    const int n = n0 + n0w + nt * 8 + lc;
                    const int h = n >> 7, hd = n & 127;
                    float2 v = make_float2(acc[mt][nt][e], acc[mt][nt][e + 1]);
                    *(float2*)&C[rowoff + (size_t)h * S_ * HD_ + hd] = v;
                }
            } else {
                const size_t dstbase = (size_t)m * D_;
#pragma unroll
                for (int nt = 0; nt < 8; nt++) {
                    const int n = n0 + n0w + nt * 8 + lc;
                    float2 v = make_float2(acc[mt][nt][e], acc[mt][nt][e + 1]);
                    *(float2*)&C[dstbase + n] = v;
                }
            }
        }
    }
}

// ---------------------------------------------------------------------------
// RoPE tables + rope-apply emitting bf16 hi/lo (Q pre-scaled by 1/sqrt(HD))
// ---------------------------------------------------------------------------
__global__ void rope_table_kernel()
{
    int idx = blockIdx.x * blockDim.x + threadIdx.x;
    if (idx >= S_ * 64) return;
    const int i = idx & 63;
    const int s = idx >> 6;
    const float inv_freq = (float)pow(10000.0, -(double)i * (1.0 / 64.0));
    const double ang = (double)s * (double)inv_freq;
    double sd, cd;
    sincos(ang, &sd, &cd);
    g_cos[idx] = (float)cd;
    g_sin[idx] = (float)sd;
}

__device__ __forceinline__ void split1(float x, __nv_bfloat16& h, __nv_bfloat16& l) {
    h = __float2bfloat16(x);
    l = __float2bfloat16(x - __bfloat162float(h));
}

__global__ void rope_split_kernel(const float* __restrict__ Q,
                                  const float* __restrict__ K, int total)
{
    int idx = blockIdx.x * blockDim.x + threadIdx.x;
    if (idx >= total) return;
    const int i  = idx & 63;
    const int s  = (idx >> 6) & (S_ - 1);
    const int bh = idx >> 17;

    const int ti = (s << 6) + i;
    const float c  = g_cos[ti];
    const float sn = g_sin[ti];
    const float sc = 0.08838834764831845f;

    const size_t base = ((size_t)bh * S_ + s) * HD_ + i;
    float q1 = Q[base], q2 = Q[base + 64];
    float r1 = (q1 * c - q2 * sn) * sc;
    float r2 = (q1 * sn + q2 * c) * sc;
    __nv_bfloat16 h, l;
    split1(r1, h, l); g_qh[base] = h;      g_ql[base] = l;
    split1(r2, h, l); g_qh[base + 64] = h; g_ql[base + 64] = l;

    float k1 = K[base], k2 = K[base + 64];
    float t1 = k1 * c - k2 * sn;
    float t2 = k1 * sn + k2 * c;
    split1(t1, h, l); g_kh[base] = h;      g_kl[base] = l;
    split1(t2, h, l); g_kh[base + 64] = h; g_kl[base + 64] = l;
}

// ---------------------------------------------------------------------------
// Tensor-core flash attention (causal), split-bf16 (unchanged from R4).
// ---------------------------------------------------------------------------
#define FL_SMEM (65536 + 2 * 65536)

__global__ void __launch_bounds__(256, 1)
flash_tc(const __nv_bfloat16* __restrict__ Qhi, const __nv_bfloat16* __restrict__ Qlo,
         const __nv_bfloat16* __restrict__ Khi, const __nv_bfloat16* __restrict__ Klo,
         const __nv_bfloat16* __restrict__ Vhi, const __nv_bfloat16* __restrict__ Vlo,
         float* __restrict__ AO)
{
    extern __shared__ char smem[];
    const uint32_t sb = smem_u32(smem);
    const uint32_t sQh = sb;
    const uint32_t sQl = sb + 32768u;

    const int tid  = threadIdx.x;
    const int lane = tid & 31;
    const int w    = tid >> 5;
    const int lr   = lane >> 2;
    const int lc2  = (lane & 3) * 2;

    const int qt = (int)gridDim.x - 1 - (int)blockIdx.x;
    const int h  = blockIdx.y;
    const int b  = blockIdx.z;
    const size_t bh = ((size_t)(b * H_ + h)) * S_ * HD_;

    const __nv_bfloat16* Qhg = Qhi + bh + (size_t)qt * 128 * HD_;
    const __nv_bfloat16* Qlg = Qlo + bh + (size_t)qt * 128 * HD_;

    for (int i = tid; i < 2048; i += 256) {
        const uint32_t r = (uint32_t)(i >> 4);
        const uint32_t cb = (uint32_t)((i & 15) << 4);
        const uint32_t so = swzf(r, cb);
        cp16(sQh + so, Qhg + (size_t)r * HD_ + (i & 15) * 8);
        cp16(sQl + so, Qlg + (size_t)r * HD_ + (i & 15) * 8);
    }

#define LOAD_KV(jj, buf)                                                       \
    {                                                                          \
        const uint32_t kvb = sb + 65536u + (uint32_t)(buf) * 65536u;           \
        const size_t rg0 = (size_t)(jj) * 64;                                  \
        for (int i = tid; i < 1024; i += 256) {                                \
            const uint32_t r = (uint32_t)(i >> 4);                             \
            const uint32_t cb = (uint32_t)((i & 15) << 4);                     \
            const uint32_t so = swzf(r, cb);                                   \
            const size_t g = bh + (rg0 + r) * HD_ + (i & 15) * 8;              \
            cp16(kvb + so, Khi + g);                                           \
            cp16(kvb + 16384u + so, Klo + g);                                  \
            cp16(kvb + 32768u + so, Vhi + g);                                  \
            cp16(kvb + 49152u + so, Vlo + g);                                  \
        }                                                                      \
    }

    LOAD_KV(0, 0);
    CP_COMMIT();

    float o[16][4];
#pragma unroll
    for (int i = 0; i < 16; i++)
#pragma unroll
        for (int e = 0; e < 4; e++) o[i][e] = 0.0f;
    float m0 = -1e30f, m1 = -1e30f, l0 = 0.0f, l1 = 0.0f;

    const int jmax = 2 * qt + 1;
    const int rbase = qt * 128 + w * 16 + lr;

    for (int j = 0; j <= jmax; j++) {
        if (j < jmax) {
            LOAD_KV(j + 1, (j + 1) & 1);
            CP_COMMIT();
            asm volatile("cp.async.wait_group 1;" ::: "memory");
        } else {
            asm volatile("cp.async.wait_group 0;" ::: "memory");
        }
        __syncthreads();

        const uint32_t kvb = sb + 65536u + (uint32_t)(j & 1) * 65536u;
        const uint32_t sKh = kvb;
        const uint32_t sKl = kvb + 16384u;
        const uint32_t sVh = kvb + 32768u;
        const uint32_t sVl = kvb + 49152u;

        float sacc[8][4];
#pragma unroll
        for (int nt = 0; nt < 8; nt++)
#pragma unroll
            for (int e = 0; e < 4; e++) sacc[nt][e] = 0.0f;

#pragma unroll
        for (int kc = 0; kc < 8; kc++) {
            const uint32_t ao_ = swzf((uint32_t)(w * 16 + (lane & 15)),
                                      (uint32_t)(kc * 32 + ((lane >> 4) << 4)));
            uint32_t ah[4], al[4];
            ldsm_x4(sQh + ao_, ah);
            ldsm_x4(sQl + ao_, al);
#pragma unroll
            for (int nt = 0; nt < 8; nt++) {
                const uint32_t bo = swzf((uint32_t)(nt * 8 + (lane & 7)),
                                         (uint32_t)(kc * 32 + (((lane >> 3) & 1) << 4)));
                uint32_t bhf[2], blf[2];
                ldsm_x2(sKh + bo, bhf);
                ldsm_x2(sKl + bo, blf);
                mma16816(sacc[nt], ah, bhf);
                mma16816(sacc[nt], ah, blf);
                mma16816(sacc[nt], al, bhf);
            }
        }

        if (j >= 2 * qt) {
            const int cb0 = j * 64 + lc2;
#pragma unroll
            for (int nt = 0; nt < 8; nt++)
#pragma unroll
                for (int e = 0; e < 4; e++) {
                    const int col = cb0 + nt * 8 + (e & 1);
                    const int row = rbase + 8 * (e >> 1);
                    if (col > row) sacc[nt][e] = -1e30f;
                }
        }

        float mx0 = -1e30f, mx1 = -1e30f;
#pragma unroll
        for (int nt = 0; nt < 8; nt++) {
            mx0 = fmaxf(mx0, fmaxf(sacc[nt][0], sacc[nt][1]));
            mx1 = fmaxf(mx1, fmaxf(sacc[nt][2], sacc[nt][3]));
        }
        mx0 = fmaxf(mx0, __shfl_xor_sync(0xffffffffu, mx0, 1));
        mx0 = fmaxf(mx0, __shfl_xor_sync(0xffffffffu, mx0, 2));
        mx1 = fmaxf(mx1, __shfl_xor_sync(0xffffffffu, mx1, 1));
        mx1 = fmaxf(mx1, __shfl_xor_sync(0xffffffffu, mx1, 2));

        const float mn0 = fmaxf(m0, mx0);
        const float mn1 = fmaxf(m1, mx1);
        const float al0 = __expf(m0 - mn0);
        const float al1 = __expf(m1 - mn1);
        m0 = mn0; m1 = mn1;

        float s0 = 0.0f, s1 = 0.0f;
#pragma unroll
        for (int nt = 0; nt < 8; nt++) {
            sacc[nt][0] = __expf(sacc[nt][0] - mn0); s0 += sacc[nt][0];
            sacc[nt][1] = __expf(sacc[nt][1] - mn0); s0 += sacc[nt][1];
            sacc[nt][2] = __expf(sacc[nt][2] - mn1); s1 += sacc[nt][2];
            sacc[nt][3] = __expf(sacc[nt][3] - mn1); s1 += sacc[nt][3];
        }
        s0 += __shfl_xor_sync(0xffffffffu, s0, 1);
        s0 += __shfl_xor_sync(0xffffffffu, s0, 2);
        s1 += __shfl_xor_sync(0xffffffffu, s1, 1);
        s1 += __shfl_xor_sync(0xffffffffu, s1, 2);
        l0 = l0 * al0 + s0;
        l1 = l1 * al1 + s1;

#pragma unroll
        for (int dt = 0; dt < 16; dt++) {
            o[dt][0] *= al0; o[dt][1] *= al0;
            o[dt][2] *= al1; o[dt][3] *= al1;
        }

#pragma unroll
        for (int t = 0; t < 4; t++) {
            uint32_t ph[4], pl[4];
#pragma unroll
            for (int q2 = 0; q2 < 2; q2++)
#pragma unroll
                for (int rr = 0; rr < 2; rr++) {
                    const float x = sacc[2 * t + q2][2 * rr];
                    const float y = sacc[2 * t + q2][2 * rr + 1];
                    __nv_bfloat16 bx = __float2bfloat16(x);
                    __nv_bfloat16 by = __float2bfloat16(y);
                    __nv_bfloat16 cx = __float2bfloat16(x - __bfloat162float(bx));
                    __nv_bfloat16 cy = __float2bfloat16(y - __bfloat162float(by));
                    ph[q2 * 2 + rr] = pack2(bx, by);
                    pl[q2 * 2 + rr] = pack2(cx, cy);
                }
#pragma unroll
            for (int dt = 0; dt < 16; dt++) {
                const uint32_t bo = swzf((uint32_t)(t * 16 + (lane & 15)),
                                         (uint32_t)(dt * 16));
                uint32_t bvh[2], bvl[2];
                ldsm_x2t(sVh + bo, bvh);
                ldsm_x2t(sVl + bo, bvl);
                mma16816(o[dt], ph, bvh);
                mma16816(o[dt], ph, bvl);
                mma16816(o[dt], pl, bvh);
            }
        }
        __syncthreads();
    }

    const float inv0 = 1.0f / l0;
    const float inv1 = 1.0f / l1;
    const int srow0 = qt * 128 + w * 16 + lr;
    const size_t d0 = ((size_t)(b * S_ + srow0)) * D_ + h * HD_;
    const size_t d1 = ((size_t)(b * S_ + srow0 + 8)) * D_ + h * HD_;
#pragma unroll
    for (int dt = 0; dt < 16; dt++) {
        *(float2*)&AO[d0 + dt * 8 + lc2] = make_float2(o[dt][0] * inv0, o[dt][1] * inv0);
        *(float2*)&AO[d1 + dt * 8 + lc2] = make_float2(o[dt][2] * inv1, o[dt][3] * inv1);
    }
}

// ---------------------------------------------------------------------------
extern "C" void kernel_launch(void* const* d_in, const int* in_sizes, int n_in,
                              void* d_out, int out_size)
{
    (void)in_sizes; (void)n_in; (void)out_size;
    const float* x  = (const float*)d_in[0];
    const float* Wq = (const float*)d_in[2];
    const float* Wk = (const float*)d_in[3];
    const float* Wv = (const float*)d_in[4];
    const float* Wo = (const float*)d_in[5];
    float* out = (float*)d_out;

    float *q, *k, *v, *ao;
    cudaGetSymbolAddress((void**)&q,  g_Q);
    cudaGetSymbolAddress((void**)&k,  g_K);
    cudaGetSymbolAddress((void**)&v,  g_V);
    cudaGetSymbolAddress((void**)&ao, g_AO);

    __nv_bfloat16 *xhi, *xlo, *aohi, *aolo;
    __nv_bfloat16 *wqhi, *wqlo, *wkhi, *wklo, *wvhi, *wvlo, *wohi, *wolo;
    __nv_bfloat16 *qh, *ql, *kh, *kl, *vh, *vl;
    cudaGetSymbolAddress((void**)&xhi, g_xhi);
    cudaGetSymbolAddress((void**)&xlo, g_xlo);
    cudaGetSymbolAddress((void**)&aohi, g_aohi);
    cudaGetSymbolAddress((void**)&aolo, g_aolo);
    cudaGetSymbolAddress((void**)&wqhi, g_wqhi);
    cudaGetSymbolAddress((void**)&wqlo, g_wqlo);
    cudaGetSymbolAddress((void**)&wkhi, g_wkhi);
    cudaGetSymbolAddress((void**)&wklo, g_wklo);
    cudaGetSymbolAddress((void**)&wvhi, g_wvhi);
    cudaGetSymbolAddress((void**)&wvlo, g_wvlo);
    cudaGetSymbolAddress((void**)&wohi, g_wohi);
    cudaGetSymbolAddress((void**)&wolo, g_wolo);
    cudaGetSymbolAddress((void**)&qh, g_qh);
    cudaGetSymbolAddress((void**)&ql, g_ql);
    cudaGetSymbolAddress((void**)&kh, g_kh);
    cudaGetSymbolAddress((void**)&kl, g_kl);
    cudaGetSymbolAddress((void**)&vh, g_vh);
    cudaGetSymbolAddress((void**)&vl, g_vl);

    cudaFuncSetAttribute(sgemm_tc,
                         cudaFuncAttributeMaxDynamicSharedMemorySize, TC_SMEM_BYTES);
    cudaFuncSetAttribute(flash_tc,
                         cudaFuncAttributeMaxDynamicSharedMemorySize, FL_SMEM);

    // 1) splits of inputs
    const int xn4 = (B_ * S_ * D_) / 4;
    const int wn4 = (D_ * D_) / 4;
    split_bf16<<<(xn4 + 255) / 256, 256>>>(x, xhi, xlo, xn4);
    split_bf16<<<(wn4 + 255) / 256, 256>>>(Wq, wqhi, wqlo, wn4);
    split_bf16<<<(wn4 + 255) / 256, 256>>>(Wk, wkhi, wklo, wn4);
    split_bf16<<<(wn4 + 255) / 256, 256>>>(Wv, wvhi, wvlo, wn4);
    split_bf16<<<(wn4 + 255) / 256, 256>>>(Wo, wohi, wolo, wn4);

    // 2) rope tables
    rope_table_kernel<<<(S_ * 64 + 255) / 256, 256>>>();

    // 3) projections (tensor cores, 256x256 tiles)
    dim3 ggrid(D_ / 256, (B_ * S_) / 256);   // (8, 16) = 128 CTAs
    sgemm_tc<<<ggrid, 512, TC_SMEM_BYTES>>>(xhi, xlo, wqhi, wqlo, q, 1);
    sgemm_tc<<<ggrid, 512, TC_SMEM_BYTES>>>(xhi, xlo, wkhi, wklo, k, 1);
    sgemm_tc<<<ggrid, 512, TC_SMEM_BYTES>>>(xhi, xlo, wvhi, wvlo, v, 1);

    // 4) rope + split to bf16 hi/lo for flash
    const int rope_total = B_ * H_ * S_ * 64;
    rope_split_kernel<<<(rope_total + 255) / 256, 256>>>(q, k, rope_total);
    const int vn4 = (B_ * H_ * S_ * HD_) / 4;
    split_bf16<<<(vn4 + 255) / 256, 256>>>(v, vh, vl, vn4);

    // 5) tensor-core flash attention
    flash_tc<<<dim3(S_ / 128, H_, B_), 256, FL_SMEM>>>(qh, ql, kh, kl, vh, vl, ao);

    // 6) output projection
    split_bf16<<<(xn4 + 255) / 256, 256>>>(ao, aohi, aolo, xn4);
    sgemm_tc<<<ggrid, 512, TC_SMEM_BYTES>>>(aohi, aolo, wohi, wolo, out, 0);
}

// round 7
// speedup vs baseline: 1.4610x; 1.4610x over previous
#include <cuda_runtime.h>
#include <cuda_bf16.h>
#include <math.h>
#include <stdint.h>

#define B_ 2
#define S_ 2048
#define D_ 2048
#define H_ 16
#define HD_ 128

// ---------------- device scratch (no runtime allocation) ----------------
__device__ float g_Q[B_ * H_ * S_ * HD_];   // [b][h][s][hd] fp32 (pre-rope)
__device__ float g_K[B_ * H_ * S_ * HD_];
__device__ float g_V[B_ * H_ * S_ * HD_];
__device__ float g_AO[B_ * S_ * D_];        // [b][s][d]

__device__ __nv_bfloat16 g_xhi[B_ * S_ * D_];
__device__ __nv_bfloat16 g_xlo[B_ * S_ * D_];
__device__ __nv_bfloat16 g_wqhi[D_ * D_], g_wqlo[D_ * D_];
__device__ __nv_bfloat16 g_wkhi[D_ * D_], g_wklo[D_ * D_];
__device__ __nv_bfloat16 g_wvhi[D_ * D_], g_wvlo[D_ * D_];
__device__ __nv_bfloat16 g_wohi[D_ * D_], g_wolo[D_ * D_];
__device__ __nv_bfloat16 g_aohi[B_ * S_ * D_];
__device__ __nv_bfloat16 g_aolo[B_ * S_ * D_];

// attention operands (bf16 hi/lo, head layout)
__device__ __nv_bfloat16 g_qh[B_ * H_ * S_ * HD_], g_ql[B_ * H_ * S_ * HD_];
__device__ __nv_bfloat16 g_kh[B_ * H_ * S_ * HD_], g_kl[B_ * H_ * S_ * HD_];
__device__ __nv_bfloat16 g_vh[B_ * H_ * S_ * HD_], g_vl[B_ * H_ * S_ * HD_];

__device__ float g_cos[S_ * 64];
__device__ float g_sin[S_ * 64];

// ---------------- helpers ----------------
__device__ __forceinline__ uint32_t smem_u32(const void* p) {
    uint32_t a;
    asm("{ .reg .u64 t; cvta.to.shared.u64 t, %1; cvt.u32.u64 %0, t; }"
        : "=r"(a) : "l"(p));
    return a;
}
static __device__ __forceinline__ uint32_t swz128(uint32_t o) {
    return o ^ ((o >> 3) & 0x70);
}
// swizzle for 256B rows (flash tiles)
static __device__ __forceinline__ uint32_t swzf(uint32_t row, uint32_t colbyte) {
    return row * 256u + (colbyte ^ ((row & 7u) << 4));
}
__device__ __forceinline__ void cp16(uint32_t saddr, const void* gptr) {
    asm volatile("cp.async.cg.shared.global [%0], [%1], 16;"
                 :: "r"(saddr), "l"(gptr) : "memory");
}
#define CP_COMMIT() asm volatile("cp.async.commit_group;" ::: "memory")

__device__ __forceinline__ void ldsm_x4(uint32_t a, uint32_t* r) {
    asm volatile("ldmatrix.sync.aligned.m8n8.x4.shared.b16 {%0,%1,%2,%3}, [%4];"
                 : "=r"(r[0]), "=r"(r[1]), "=r"(r[2]), "=r"(r[3]) : "r"(a));
}
__device__ __forceinline__ void ldsm_x4t(uint32_t a, uint32_t* r) {
    asm volatile("ldmatrix.sync.aligned.m8n8.x4.trans.shared.b16 {%0,%1,%2,%3}, [%4];"
                 : "=r"(r[0]), "=r"(r[1]), "=r"(r[2]), "=r"(r[3]) : "r"(a));
}
__device__ __forceinline__ void mma16816(float* d, const uint32_t* a, const uint32_t* b) {
    asm volatile(
        "mma.sync.aligned.m16n8k16.row.col.f32.bf16.bf16.f32 "
        "{%0,%1,%2,%3}, {%4,%5,%6,%7}, {%8,%9}, {%0,%1,%2,%3};"
        : "+f"(d[0]), "+f"(d[1]), "+f"(d[2]), "+f"(d[3])
        : "r"(a[0]), "r"(a[1]), "r"(a[2]), "r"(a[3]), "r"(b[0]), "r"(b[1]));
}
__device__ __forceinline__ uint32_t pack2(__nv_bfloat16 a, __nv_bfloat16 b) {
    __nv_bfloat162 t(a, b);
    return *(uint32_t*)&t;
}

// ---------------------------------------------------------------------------
// Split fp32 -> bf16 hi/lo (Markidis). Vectorized by 4.
// ---------------------------------------------------------------------------
__global__ void split_bf16(const float* __restrict__ in,
                           __nv_bfloat16* __restrict__ hi,
                           __nv_bfloat16* __restrict__ lo, int n4)
{
    int i = blockIdx.x * blockDim.x + threadIdx.x;
    if (i >= n4) return;
    float4 v = ((const float4*)in)[i];
    __nv_bfloat16 h0 = __float2bfloat16(v.x);
    __nv_bfloat16 h1 = __float2bfloat16(v.y);
    __nv_bfloat16 h2 = __float2bfloat16(v.z);
    __nv_bfloat16 h3 = __float2bfloat16(v.w);
    __nv_bfloat16 l0 = __float2bfloat16(v.x - __bfloat162float(h0));
    __nv_bfloat16 l1 = __float2bfloat16(v.y - __bfloat162float(h1));
    __nv_bfloat16 l2 = __float2bfloat16(v.z - __bfloat162float(h2));
    __nv_bfloat16 l3 = __float2bfloat16(v.w - __bfloat162float(h3));
    __nv_bfloat162* hi2 = (__nv_bfloat162*)hi;
    __nv_bfloat162* lo2 = (__nv_bfloat162*)lo;
    hi2[2 * i]     = __nv_bfloat162(h0, h1);
    hi2[2 * i + 1] = __nv_bfloat162(h2, h3);
    lo2[2 * i]     = __nv_bfloat162(l0, l1);
    lo2[2 * i + 1] = __nv_bfloat162(l2, l3);
}

// ---------------------------------------------------------------------------
// mma.sync split-bf16 SGEMM: 128x128 tile, BK=64, 256 threads (R4 geometry),
// upgraded: 3-stage cp.async pipeline + x4-paired B ldmatrix.
// ---------------------------------------------------------------------------
#define TCT16 16384u                      // bytes per smem tile (128 x 128B)
#define TCBUF (4u * TCT16)                // 4 tiles per stage = 64KB
#define TC_SMEM_BYTES (3u * TCBUF)        // 3 stages = 192KB

__global__ void __launch_bounds__(256, 1)
sgemm_tc(const __nv_bfloat16* __restrict__ Ahi, const __nv_bfloat16* __restrict__ Alo,
         const __nv_bfloat16* __restrict__ Bhi, const __nv_bfloat16* __restrict__ Blo,
         float* __restrict__ C, int head_layout)
{
    extern __shared__ char smem[];
    const uint32_t sbase = smem_u32(smem);

    const int tid  = threadIdx.x;
    const int lane = tid & 31;
    const int w    = tid >> 5;
    const int m0w  = (w >> 2) * 64;
    const int n0w  = (w & 3) * 32;

    const int m0 = blockIdx.y * 128;
    const int n0 = blockIdx.x * 128;

    uint32_t swofs[4];
#pragma unroll
    for (int t = 0; t < 4; t++) {
        const int u = tid + (t << 8);
        swofs[t] = swz128((uint32_t)((u >> 3) * 128 + (u & 7) * 16));
    }

    float acc[4][4][4];
#pragma unroll
    for (int i = 0; i < 4; i++)
#pragma unroll
        for (int j = 0; j < 4; j++)
#pragma unroll
            for (int r = 0; r < 4; r++) acc[i][j][r] = 0.0f;

    const uint32_t arow = (uint32_t)(m0w + (lane & 15));
    const uint32_t acol = (uint32_t)((lane >> 4) << 4);
    // x4-paired B: lanes 0-15 -> nt pair low, 16-31 -> pair high
    const uint32_t browx = (uint32_t)(n0w + (lane & 7) + ((lane >> 4) << 3));
    const uint32_t bcol  = (uint32_t)(((lane >> 3) & 1) << 4);

#define LOAD_CHUNK(c, buf)                                                     \
    {                                                                          \
        const uint32_t bofs = sbase + (uint32_t)(buf) * TCBUF;                 \
        const int k0 = (c) * 64;                                               \
        _Pragma("unroll")                                                      \
        for (int t = 0; t < 4; t++) {                                          \
            const int u = tid + (t << 8);                                      \
            const int r = u >> 3;                                              \
            const int c16 = u & 7;                                             \
            const size_t ga = (size_t)(m0 + r) * D_ + k0 + c16 * 8;            \
            const size_t gb = (size_t)(n0 + r) * D_ + k0 + c16 * 8;            \
            cp16(bofs + 0u * TCT16 + swofs[t], Ahi + ga);                      \
            cp16(bofs + 1u * TCT16 + swofs[t], Alo + ga);                      \
            cp16(bofs + 2u * TCT16 + swofs[t], Bhi + gb);                      \
            cp16(bofs + 3u * TCT16 + swofs[t], Blo + gb);                      \
        }                                                                      \
        CP_COMMIT();                                                           \
    }

    LOAD_CHUNK(0, 0);
    LOAD_CHUNK(1, 1);

    int buf = 0;
    for (int c = 0; c < 32; c++) {
        if (c < 31) {
            asm volatile("cp.async.wait_group 1;" ::: "memory");
        } else {
            asm volatile("cp.async.wait_group 0;" ::: "memory");
        }
        __syncthreads();
        if (c + 2 < 32) {
            const int nb = (buf + 2 >= 3) ? buf - 1 : buf + 2;
            LOAD_CHUNK(c + 2, nb);
        }

        const uint32_t bofs = sbase + (uint32_t)buf * TCBUF;
        const uint32_t Ab_hi = bofs + 0u * TCT16;
        const uint32_t Ab_lo = bofs + 1u * TCT16;
        const uint32_t Bb_hi = bofs + 2u * TCT16;
        const uint32_t Bb_lo = bofs + 3u * TCT16;

#pragma unroll
        for (int kk = 0; kk < 4; kk++) {
            uint32_t ah[4][4], al[4][4], bh[4][2], bl[4][2];
            const uint32_t kb = (uint32_t)(kk * 32);
#pragma unroll
            for (int mt = 0; mt < 4; mt++) {
                const uint32_t ofs = swz128((arow + mt * 16u) * 128u + acol + kb);
                ldsm_x4(Ab_hi + ofs, ah[mt]);
                ldsm_x4(Ab_lo + ofs, al[mt]);
            }
#pragma unroll
            for (int ntp = 0; ntp < 2; ntp++) {
                const uint32_t ofs = swz128((browx + ntp * 16u) * 128u + bcol + kb);
                uint32_t b4h[4], b4l[4];
                ldsm_x4(Bb_hi + ofs, b4h);
                ldsm_x4(Bb_lo + ofs, b4l);
                bh[2 * ntp][0] = b4h[0];     bh[2 * ntp][1] = b4h[1];
                bh[2 * ntp + 1][0] = b4h[2]; bh[2 * ntp + 1][1] = b4h[3];
                bl[2 * ntp][0] = b4l[0];     bl[2 * ntp][1] = b4l[1];
                bl[2 * ntp + 1][0] = b4l[2]; bl[2 * ntp + 1][1] = b4l[3];
            }
#pragma unroll
            for (int mt = 0; mt < 4; mt++)
#pragma unroll
                for (int nt = 0; nt < 4; nt++) {
                    mma16816(acc[mt][nt], ah[mt], bh[nt]);
                    mma16816(acc[mt][nt], ah[mt], bl[nt]);
                    mma16816(acc[mt][nt], al[mt], bh[nt]);
                }
        }
        __syncthreads();
        buf = (buf + 1 >= 3) ? 0 : buf + 1;
    }

    const int lr = lane >> 2;
    const int lc = (lane & 3) * 2;
#pragma unroll
    for (int mt = 0; mt < 4; mt++) {
#pragma unroll
        for (int rr = 0; rr < 2; rr++) {
            const int m = m0 + m0w + mt * 16 + rr * 8 + lr;
            const int e = rr * 2;
            if (head_layout) {
                const int bb = m >> 11, s = m & (S_ - 1);
                const size_t rowoff = ((size_t)(bb * H_) * S_ + s) * HD_;
#pragma unroll
                for (int nt = 0; nt < 4; nt++) {
                    const int n = n0 + n0w + nt * 8 + lc;
                    const int h = n >> 7, hd = n & 127;
                    float2 v = make_float2(acc[mt][nt][e], acc[mt][nt][e + 1]);
                    *(float2*)&C[rowoff + (size_t)h * S_ * HD_ + hd] = v;
                }
            } else {
                const size_t dstbase = (size_t)m * D_;
#pragma unroll
                for (int nt = 0; nt < 4; nt++) {
                    const int n = n0 + n0w + nt * 8 + lc;
                    float2 v = make_float2(acc[mt][nt][e], acc[mt][nt][e + 1]);
                    *(float2*)&C[dstbase + n] = v;
                }
            }
        }
    }
}

// ---------------------------------------------------------------------------
// RoPE tables + rope-apply emitting bf16 hi/lo (Q pre-scaled by 1/sqrt(HD))
// ---------------------------------------------------------------------------
__global__ void rope_table_kernel()
{
    int idx = blockIdx.x * blockDim.x + threadIdx.x;
    if (idx >= S_ * 64) return;
    const int i = idx & 63;
    const int s = idx >> 6;
    const float inv_freq = (float)pow(10000.0, -(double)i * (1.0 / 64.0));
    const double ang = (double)s * (double)inv_freq;
    double sd, cd;
    sincos(ang, &sd, &cd);
    g_cos[idx] = (float)cd;
    g_sin[idx] = (float)sd;
}

__device__ __forceinline__ void split1(float x, __nv_bfloat16& h, __nv_bfloat16& l) {
    h = __float2bfloat16(x);
    l = __float2bfloat16(x - __bfloat162float(h));
}

__global__ void rope_split_kernel(const float* __restrict__ Q,
                                  const float* __restrict__ K, int total)
{
    int idx = blockIdx.x * blockDim.x + threadIdx.x;
    if (idx >= total) return;
    const int i  = idx & 63;
    const int s  = (idx >> 6) & (S_ - 1);
    const int bh = idx >> 17;

    const int ti = (s << 6) + i;
    const float c  = g_cos[ti];
    const float sn = g_sin[ti];
    const float sc = 0.08838834764831845f;

    const size_t base = ((size_t)bh * S_ + s) * HD_ + i;
    float q1 = Q[base], q2 = Q[base + 64];
    float r1 = (q1 * c - q2 * sn) * sc;
    float r2 = (q1 * sn + q2 * c) * sc;
    __nv_bfloat16 h, l;
    split1(r1, h, l); g_qh[base] = h;      g_ql[base] = l;
    split1(r2, h, l); g_qh[base + 64] = h; g_ql[base + 64] = l;

    float k1 = K[base], k2 = K[base + 64];
    float t1 = k1 * c - k2 * sn;
    float t2 = k1 * sn + k2 * c;
    split1(t1, h, l); g_kh[base] = h;      g_kl[base] = l;
    split1(t2, h, l); g_kh[base + 64] = h; g_kl[base + 64] = l;
}

// ---------------------------------------------------------------------------
// Tensor-core flash attention (causal), split-bf16; x4-paired ldmatrix.
// ---------------------------------------------------------------------------
#define FL_SMEM (65536 + 2 * 65536)

__global__ void __launch_bounds__(256, 1)
flash_tc(const __nv_bfloat16* __restrict__ Qhi, const __nv_bfloat16* __restrict__ Qlo,
         const __nv_bfloat16* __restrict__ Khi, const __nv_bfloat16* __restrict__ Klo,
         const __nv_bfloat16* __restrict__ Vhi, const __nv_bfloat16* __restrict__ Vlo,
         float* __restrict__ AO)
{
    extern __shared__ char smem[];
    const uint32_t sb = smem_u32(smem);
    const uint32_t sQh = sb;
    const uint32_t sQl = sb + 32768u;

    const int tid  = threadIdx.x;
    const int lane = tid & 31;
    const int w    = tid >> 5;
    const int lr   = lane >> 2;
    const int lc2  = (lane & 3) * 2;

    const int qt = (int)gridDim.x - 1 - (int)blockIdx.x;
    const int h  = blockIdx.y;
    const int b  = blockIdx.z;
    const size_t bh = ((size_t)(b * H_ + h)) * S_ * HD_;

    const __nv_bfloat16* Qhg = Qhi + bh + (size_t)qt * 128 * HD_;
    const __nv_bfloat16* Qlg = Qlo + bh + (size_t)qt * 128 * HD_;

    for (int i = tid; i < 2048; i += 256) {
        const uint32_t r = (uint32_t)(i >> 4);
        const uint32_t cb = (uint32_t)((i & 15) << 4);
        const uint32_t so = swzf(r, cb);
        cp16(sQh + so, Qhg + (size_t)r * HD_ + (i & 15) * 8);
        cp16(sQl + so, Qlg + (size_t)r * HD_ + (i & 15) * 8);
    }

#define LOAD_KV(jj, buf)                                                       \
    {                                                                          \
        const uint32_t kvb = sb + 65536u + (uint32_t)(buf) * 65536u;           \
        const size_t rg0 = (size_t)(jj) * 64;                                  \
        for (int i = tid; i < 1024; i += 256) {                                \
            const uint32_t r = (uint32_t)(i >> 4);                             \
            const uint32_t cb = (uint32_t)((i & 15) << 4);                     \
            const uint32_t so = swzf(r, cb);                                   \
            const size_t g = bh + (rg0 + r) * HD_ + (i & 15) * 8;              \
            cp16(kvb + so, Khi + g);                                           \
            cp16(kvb + 16384u + so, Klo + g);                                  \
            cp16(kvb + 32768u + so, Vhi + g);                                  \
            cp16(kvb + 49152u + so, Vlo + g);                                  \
        }                                                                      \
    }

    LOAD_KV(0, 0);
    CP_COMMIT();

    float o[16][4];
#pragma unroll
    for (int i = 0; i < 16; i++)
#pragma unroll
        for (int e = 0; e < 4; e++) o[i][e] = 0.0f;
    float m0 = -1e30f, m1 = -1e30f, l0 = 0.0f, l1 = 0.0f;

    const int jmax = 2 * qt + 1;
    const int rbase = qt * 128 + w * 16 + lr;

    // x4-paired K row base: lanes 0-15 pair-low, 16-31 pair-high
    const uint32_t krowx = (uint32_t)((lane & 7) + ((lane >> 4) << 3));
    const uint32_t kcolx = (uint32_t)(((lane >> 3) & 1) << 4);

    for (int j = 0; j <= jmax; j++) {
        if (j < jmax) {
            LOAD_KV(j + 1, (j + 1) & 1);
            CP_COMMIT();
            asm volatile("cp.async.wait_group 1;" ::: "memory");
        } else {
            asm volatile("cp.async.wait_group 0;" ::: "memory");
        }
        __syncthreads();

        const uint32_t kvb = sb + 65536u + (uint32_t)(j & 1) * 65536u;
        const uint32_t sKh = kvb;
        const uint32_t sKl = kvb + 16384u;
        const uint32_t sVh = kvb + 32768u;
        const uint32_t sVl = kvb + 49152u;

        float sacc[8][4];
#pragma unroll
        for (int nt = 0; nt < 8; nt++)
#pragma unroll
            for (int e = 0; e < 4; e++) sacc[nt][e] = 0.0f;

#pragma unroll
        for (int kc = 0; kc < 8; kc++) {
            const uint32_t ao_ = swzf((uint32_t)(w * 16 + (lane & 15)),
                                      (uint32_t)(kc * 32 + ((lane >> 4) << 4)));
            uint32_t ah[4], al[4];
            ldsm_x4(sQh + ao_, ah);
            ldsm_x4(sQl + ao_, al);
#pragma unroll
            for (int ntp = 0; ntp < 4; ntp++) {
                const uint32_t bo = swzf(krowx + ntp * 16u,
                                         (uint32_t)(kc * 32) + kcolx);
                uint32_t b4h[4], b4l[4];
                ldsm_x4(sKh + bo, b4h);
                ldsm_x4(sKl + bo, b4l);
                mma16816(sacc[2 * ntp],     ah, &b4h[0]);
                mma16816(sacc[2 * ntp],     ah, &b4l[0]);
                mma16816(sacc[2 * ntp],     al, &b4h[0]);
                mma16816(sacc[2 * ntp + 1], ah, &b4h[2]);
                mma16816(sacc[2 * ntp + 1], ah, &b4l[2]);
                mma16816(sacc[2 * ntp + 1], al, &b4h[2]);
            }
        }

        if (j >= 2 * qt) {
            const int cb0 = j * 64 + lc2;
#pragma unroll
            for (int nt = 0; nt < 8; nt++)
#pragma unroll
                for (int e = 0; e < 4; e++) {
                    const int col = cb0 + nt * 8 + (e & 1);
                    const int row = rbase + 8 * (e >> 1);
                    if (col > row) sacc[nt][e] = -1e30f;
                }
        }

        float mx0 = -1e30f, mx1 = -1e30f;
#pragma unroll
        for (int nt = 0; nt < 8; nt++) {
            mx0 = fmaxf(mx0, fmaxf(sacc[nt][0], sacc[nt][1]));
            mx1 = fmaxf(mx1, fmaxf(sacc[nt][2], sacc[nt][3]));
        }
        mx0 = fmaxf(mx0, __shfl_xor_sync(0xffffffffu, mx0, 1));
        mx0 = fmaxf(mx0, __shfl_xor_sync(0xffffffffu, mx0, 2));
        mx1 = fmaxf(mx1, __shfl_xor_sync(0xffffffffu, mx1, 1));
        mx1 = fmaxf(mx1, __shfl_xor_sync(0xffffffffu, mx1, 2));

        const float mn0 = fmaxf(m0, mx0);
        const float mn1 = fmaxf(m1, mx1);
        const float al0 = __expf(m0 - mn0);
        const float al1 = __expf(m1 - mn1);
        m0 = mn0; m1 = mn1;

        float s0 = 0.0f, s1 = 0.0f;
#pragma unroll
        for (int nt = 0; nt < 8; nt++) {
            sacc[nt][0] = __expf(sacc[nt][0] - mn0); s0 += sacc[nt][0];
            sacc[nt][1] = __expf(sacc[nt][1] - mn0); s0 += sacc[nt][1];
            sacc[nt][2] = __expf(sacc[nt][2] - mn1); s1 += sacc[nt][2];
            sacc[nt][3] = __expf(sacc[nt][3] - mn1); s1 += sacc[nt][3];
        }
        s0 += __shfl_xor_sync(0xffffffffu, s0, 1);
        s0 += __shfl_xor_sync(0xffffffffu, s0, 2);
        s1 += __shfl_xor_sync(0xffffffffu, s1, 1);
        s1 += __shfl_xor_sync(0xffffffffu, s1, 2);
        l0 = l0 * al0 + s0;
        l1 = l1 * al1 + s1;

#pragma unroll
        for (int dt = 0; dt < 16; dt++) {
            o[dt][0] *= al0; o[dt][1] *= al0;
            o[dt][2] *= al1; o[dt][3] *= al1;
        }

#pragma unroll
        for (int t = 0; t < 4; t++) {
            uint32_t ph[4], pl[4];
#pragma unroll
            for (int q2 = 0; q2 < 2; q2++)
#pragma unroll
                for (int rr = 0; rr < 2; rr++) {
                    const float x = sacc[2 * t + q2][2 * rr];
                    const float y = sacc[2 * t + q2][2 * rr + 1];
                    __nv_bfloat16 bx = __float2bfloat16(x);
                    __nv_bfloat16 by = __float2bfloat16(y);
                    __nv_bfloat16 cx = __float2bfloat16(x - __bfloat162float(bx));
                    __nv_bfloat16 cy = __float2bfloat16(y - __bfloat162float(by));
                    ph[q2 * 2 + rr] = pack2(bx, by);
                    pl[q2 * 2 + rr] = pack2(cx, cy);
                }
            // V loads: x4.trans covers dt pair (dt = 2*dtp + (lane>>4))
#pragma unroll
            for (int dtp = 0; dtp < 8; dtp++) {
                const uint32_t bo = swzf((uint32_t)(t * 16 + (lane & 15)),
                                         (uint32_t)((2 * dtp + (lane >> 4)) * 16));
                uint32_t b4h[4], b4l[4];
                ldsm_x4t(sVh + bo, b4h);
                ldsm_x4t(sVl + bo, b4l);
                mma16816(o[2 * dtp],     ph, &b4h[0]);
                mma16816(o[2 * dtp],     ph, &b4l[0]);
                mma16816(o[2 * dtp],     pl, &b4h[0]);
                mma16816(o[2 * dtp + 1], ph, &b4h[2]);
                mma16816(o[2 * dtp + 1], ph, &b4l[2]);
                mma16816(o[2 * dtp + 1], pl, &b4h[2]);
            }
        }
        __syncthreads();
    }

    const float inv0 = 1.0f / l0;
    const float inv1 = 1.0f / l1;
    const int srow0 = qt * 128 + w * 16 + lr;
    const size_t d0 = ((size_t)(b * S_ + srow0)) * D_ + h * HD_;
    const size_t d1 = ((size_t)(b * S_ + srow0 + 8)) * D_ + h * HD_;
#pragma unroll
    for (int dt = 0; dt < 16; dt++) {
        *(float2*)&AO[d0 + dt * 8 + lc2] = make_float2(o[dt][0] * inv0, o[dt][1] * inv0);
        *(float2*)&AO[d1 + dt * 8 + lc2] = make_float2(o[dt][2] * inv1, o[dt][3] * inv1);
    }
}

// ---------------------------------------------------------------------------
extern "C" void kernel_launch(void* const* d_in, const int* in_sizes, int n_in,
                              void* d_out, int out_size)
{
    (void)in_sizes; (void)n_in; (void)out_size;
    const float* x  = (const float*)d_in[0];
    const float* Wq = (const float*)d_in[2];
    const float* Wk = (const float*)d_in[3];
    const float* Wv = (const float*)d_in[4];
    const float* Wo = (const float*)d_in[5];
    float* out = (float*)d_out;

    float *q, *k, *v, *ao;
    cudaGetSymbolAddress((void**)&q,  g_Q);
    cudaGetSymbolAddress((void**)&k,  g_K);
    cudaGetSymbolAddress((void**)&v,  g_V);
    cudaGetSymbolAddress((void**)&ao, g_AO);

    __nv_bfloat16 *xhi, *xlo, *aohi, *aolo;
    __nv_bfloat16 *wqhi, *wqlo, *wkhi, *wklo, *wvhi, *wvlo, *wohi, *wolo;
    __nv_bfloat16 *qh, *ql, *kh, *kl, *vh, *vl;
    cudaGetSymbolAddress((void**)&xhi, g_xhi);
    cudaGetSymbolAddress((void**)&xlo, g_xlo);
    cudaGetSymbolAddress((void**)&aohi, g_aohi);
    cudaGetSymbolAddress((void**)&aolo, g_aolo);
    cudaGetSymbolAddress((void**)&wqhi, g_wqhi);
    cudaGetSymbolAddress((void**)&wqlo, g_wqlo);
    cudaGetSymbolAddress((void**)&wkhi, g_wkhi);
    cudaGetSymbolAddress((void**)&wklo, g_wklo);
    cudaGetSymbolAddress((void**)&wvhi, g_wvhi);
    cudaGetSymbolAddress((void**)&wvlo, g_wvlo);
    cudaGetSymbolAddress((void**)&wohi, g_wohi);
    cudaGetSymbolAddress((void**)&wolo, g_wolo);
    cudaGetSymbolAddress((void**)&qh, g_qh);
    cudaGetSymbolAddress((void**)&ql, g_ql);
    cudaGetSymbolAddress((void**)&kh, g_kh);
    cudaGetSymbolAddress((void**)&kl, g_kl);
    cudaGetSymbolAddress((void**)&vh, g_vh);
    cudaGetSymbolAddress((void**)&vl, g_vl);

    cudaFuncSetAttribute(sgemm_tc,
                         cudaFuncAttributeMaxDynamicSharedMemorySize, TC_SMEM_BYTES);
    cudaFuncSetAttribute(flash_tc,
                         cudaFuncAttributeMaxDynamicSharedMemorySize, FL_SMEM);

    // 1) splits of inputs
    const int xn4 = (B_ * S_ * D_) / 4;
    const int wn4 = (D_ * D_) / 4;
    split_bf16<<<(xn4 + 255) / 256, 256>>>(x, xhi, xlo, xn4);
    split_bf16<<<(wn4 + 255) / 256, 256>>>(Wq, wqhi, wqlo, wn4);
    split_bf16<<<(wn4 + 255) / 256, 256>>>(Wk, wkhi, wklo, wn4);
    split_bf16<<<(wn4 + 255) / 256, 256>>>(Wv, wvhi, wvlo, wn4);
    split_bf16<<<(wn4 + 255) / 256, 256>>>(Wo, wohi, wolo, wn4);

    // 2) rope tables
    rope_table_kernel<<<(S_ * 64 + 255) / 256, 256>>>();

    // 3) projections (tensor cores, R4 geometry + 3-stage pipeline)
    dim3 ggrid(D_ / 128, (B_ * S_) / 128);   // (16, 32)
    sgemm_tc<<<ggrid, 256, TC_SMEM_BYTES>>>(xhi, xlo, wqhi, wqlo, q, 1);
    sgemm_tc<<<ggrid, 256, TC_SMEM_BYTES>>>(xhi, xlo, wkhi, wklo, k, 1);
    sgemm_tc<<<ggrid, 256, TC_SMEM_BYTES>>>(xhi, xlo, wvhi, wvlo, v, 1);

    // 4) rope + split to bf16 hi/lo for flash
    const int rope_total = B_ * H_ * S_ * 64;
    rope_split_kernel<<<(rope_total + 255) / 256, 256>>>(q, k, rope_total);
    const int vn4 = (B_ * H_ * S_ * HD_) / 4;
    split_bf16<<<(vn4 + 255) / 256, 256>>>(v, vh, vl, vn4);

    // 5) tensor-core flash attention
    flash_tc<<<dim3(S_ / 128, H_, B_), 256, FL_SMEM>>>(qh, ql, kh, kl, vh, vl, ao);

    // 6) output projection
    split_bf16<<<(xn4 + 255) / 256, 256>>>(ao, aohi, aolo, xn4);
    sgemm_tc<<<ggrid, 256, TC_SMEM_BYTES>>>(aohi, aolo, wohi, wolo, out, 0);
}

// round 8
// speedup vs baseline: 1.5252x; 1.0440x over previous
#include <cuda_runtime.h>
#include <cuda_bf16.h>
#include <math.h>
#include <stdint.h>

#define B_ 2
#define S_ 2048
#define D_ 2048
#define H_ 16
#define HD_ 128

// ---------------- device scratch (no runtime allocation) ----------------
__device__ __nv_bfloat16 g_xhi[B_ * S_ * D_];
__device__ __nv_bfloat16 g_xlo[B_ * S_ * D_];
__device__ __nv_bfloat16 g_wqhi[D_ * D_], g_wqlo[D_ * D_];
__device__ __nv_bfloat16 g_wkhi[D_ * D_], g_wklo[D_ * D_];
__device__ __nv_bfloat16 g_wvhi[D_ * D_], g_wvlo[D_ * D_];
__device__ __nv_bfloat16 g_wohi[D_ * D_], g_wolo[D_ * D_];
__device__ __nv_bfloat16 g_aohi[B_ * S_ * D_];
__device__ __nv_bfloat16 g_aolo[B_ * S_ * D_];

// attention operands (bf16 hi/lo, head layout [b][h][s][hd])
__device__ __nv_bfloat16 g_qh[B_ * H_ * S_ * HD_], g_ql[B_ * H_ * S_ * HD_];
__device__ __nv_bfloat16 g_kh[B_ * H_ * S_ * HD_], g_kl[B_ * H_ * S_ * HD_];
__device__ __nv_bfloat16 g_vh[B_ * H_ * S_ * HD_], g_vl[B_ * H_ * S_ * HD_];

__device__ float g_cos[S_ * 64];
__device__ float g_sin[S_ * 64];

// ---------------- helpers ----------------
__device__ __forceinline__ uint32_t smem_u32(const void* p) {
    uint32_t a;
    asm("{ .reg .u64 t; cvta.to.shared.u64 t, %1; cvt.u32.u64 %0, t; }"
        : "=r"(a) : "l"(p));
    return a;
}
static __device__ __forceinline__ uint32_t swz128(uint32_t o) {
    return o ^ ((o >> 3) & 0x70);
}
// swizzle for 256B rows (flash tiles)
static __device__ __forceinline__ uint32_t swzf(uint32_t row, uint32_t colbyte) {
    return row * 256u + (colbyte ^ ((row & 7u) << 4));
}
__device__ __forceinline__ void cp16(uint32_t saddr, const void* gptr) {
    asm volatile("cp.async.cg.shared.global [%0], [%1], 16;"
                 :: "r"(saddr), "l"(gptr) : "memory");
}
#define CP_COMMIT() asm volatile("cp.async.commit_group;" ::: "memory")

__device__ __forceinline__ void ldsm_x4(uint32_t a, uint32_t* r) {
    asm volatile("ldmatrix.sync.aligned.m8n8.x4.shared.b16 {%0,%1,%2,%3}, [%4];"
                 : "=r"(r[0]), "=r"(r[1]), "=r"(r[2]), "=r"(r[3]) : "r"(a));
}
__device__ __forceinline__ void ldsm_x4t(uint32_t a, uint32_t* r) {
    asm volatile("ldmatrix.sync.aligned.m8n8.x4.trans.shared.b16 {%0,%1,%2,%3}, [%4];"
                 : "=r"(r[0]), "=r"(r[1]), "=r"(r[2]), "=r"(r[3]) : "r"(a));
}
__device__ __forceinline__ void mma16816(float* d, const uint32_t* a, const uint32_t* b) {
    asm volatile(
        "mma.sync.aligned.m16n8k16.row.col.f32.bf16.bf16.f32 "
        "{%0,%1,%2,%3}, {%4,%5,%6,%7}, {%8,%9}, {%0,%1,%2,%3};"
        : "+f"(d[0]), "+f"(d[1]), "+f"(d[2]), "+f"(d[3])
        : "r"(a[0]), "r"(a[1]), "r"(a[2]), "r"(a[3]), "r"(b[0]), "r"(b[1]));
}
__device__ __forceinline__ uint32_t pack2(__nv_bfloat16 a, __nv_bfloat16 b) {
    __nv_bfloat162 t(a, b);
    return *(uint32_t*)&t;
}
__device__ __forceinline__ void split1(float x, __nv_bfloat16& h, __nv_bfloat16& l) {
    h = __float2bfloat16(x);
    l = __float2bfloat16(x - __bfloat162float(h));
}

// ---------------------------------------------------------------------------
// Split fp32 -> bf16 hi/lo (Markidis). Vectorized by 4.
// ---------------------------------------------------------------------------
__global__ void split_bf16(const float* __restrict__ in,
                           __nv_bfloat16* __restrict__ hi,
                           __nv_bfloat16* __restrict__ lo, int n4)
{
    int i = blockIdx.x * blockDim.x + threadIdx.x;
    if (i >= n4) return;
    float4 v = ((const float4*)in)[i];
    __nv_bfloat16 h0 = __float2bfloat16(v.x);
    __nv_bfloat16 h1 = __float2bfloat16(v.y);
    __nv_bfloat16 h2 = __float2bfloat16(v.z);
    __nv_bfloat16 h3 = __float2bfloat16(v.w);
    __nv_bfloat16 l0 = __float2bfloat16(v.x - __bfloat162float(h0));
    __nv_bfloat16 l1 = __float2bfloat16(v.y - __bfloat162float(h1));
    __nv_bfloat16 l2 = __float2bfloat16(v.z - __bfloat162float(h2));
    __nv_bfloat16 l3 = __float2bfloat16(v.w - __bfloat162float(h3));
    __nv_bfloat162* hi2 = (__nv_bfloat162*)hi;
    __nv_bfloat162* lo2 = (__nv_bfloat162*)lo;
    hi2[2 * i]     = __nv_bfloat162(h0, h1);
    hi2[2 * i + 1] = __nv_bfloat162(h2, h3);
    lo2[2 * i]     = __nv_bfloat162(l0, l1);
    lo2[2 * i + 1] = __nv_bfloat162(l2, l3);
}

// ---------------------------------------------------------------------------
// RoPE tables (once; double math)
// ---------------------------------------------------------------------------
__global__ void rope_table_kernel()
{
    int idx = blockIdx.x * blockDim.x + threadIdx.x;
    if (idx >= S_ * 64) return;
    const int i = idx & 63;
    const int s = idx >> 6;
    const float inv_freq = (float)pow(10000.0, -(double)i * (1.0 / 64.0));
    const double ang = (double)s * (double)inv_freq;
    double sd, cd;
    sincos(ang, &sd, &cd);
    g_cos[idx] = (float)cd;
    g_sin[idx] = (float)sd;
}

// ---------------------------------------------------------------------------
// Merged QKV GEMM: z = blockIdx.z selects weight + destination.
// Mainloop = R7 geometry (128x128 tile, BK=64, 3-stage cp.async, x4 ldmatrix).
// Epilogue: stage fp32 tile in smem, apply RoPE (Q,K) / identity (V),
// emit bf16 hi/lo directly to head-layout operand arrays.
// ---------------------------------------------------------------------------
#define TCT16 16384u
#define TCBUF (4u * TCT16)
#define TC_SMEM_BYTES (3u * TCBUF)

struct QKVPtrs {
    const __nv_bfloat16* bhi[3];
    const __nv_bfloat16* blo[3];
    __nv_bfloat16* dhi[3];
    __nv_bfloat16* dlo[3];
};

__global__ void __launch_bounds__(256, 1)
sgemm_qkv(const __nv_bfloat16* __restrict__ Ahi, const __nv_bfloat16* __restrict__ Alo,
          QKVPtrs P)
{
    extern __shared__ char smem[];
    const uint32_t sbase = smem_u32(smem);

    const int z = blockIdx.z;
    const __nv_bfloat16* __restrict__ Bhi = P.bhi[z];
    const __nv_bfloat16* __restrict__ Blo = P.blo[z];
    __nv_bfloat16* __restrict__ Dhi = P.dhi[z];
    __nv_bfloat16* __restrict__ Dlo = P.dlo[z];

    const int tid  = threadIdx.x;
    const int lane = tid & 31;
    const int w    = tid >> 5;
    const int m0w  = (w >> 2) * 64;
    const int n0w  = (w & 3) * 32;

    const int m0 = blockIdx.y * 128;
    const int n0 = blockIdx.x * 128;
    const int h  = blockIdx.x;           // n tile == head (HD==128)

    uint32_t swofs[4];
#pragma unroll
    for (int t = 0; t < 4; t++) {
        const int u = tid + (t << 8);
        swofs[t] = swz128((uint32_t)((u >> 3) * 128 + (u & 7) * 16));
    }

    float acc[4][4][4];
#pragma unroll
    for (int i = 0; i < 4; i++)
#pragma unroll
        for (int j = 0; j < 4; j++)
#pragma unroll
            for (int r = 0; r < 4; r++) acc[i][j][r] = 0.0f;

    const uint32_t arow = (uint32_t)(m0w + (lane & 15));
    const uint32_t acol = (uint32_t)((lane >> 4) << 4);
    const uint32_t browx = (uint32_t)(n0w + (lane & 7) + ((lane >> 4) << 3));
    const uint32_t bcol  = (uint32_t)(((lane >> 3) & 1) << 4);

#define LOAD_CHUNK(c, buf)                                                     \
    {                                                                          \
        const uint32_t bofs = sbase + (uint32_t)(buf) * TCBUF;                 \
        const int k0 = (c) * 64;                                               \
        _Pragma("unroll")                                                      \
        for (int t = 0; t < 4; t++) {                                          \
            const int u = tid + (t << 8);                                      \
            const int r = u >> 3;                                              \
            const int c16 = u & 7;                                             \
            const size_t ga = (size_t)(m0 + r) * D_ + k0 + c16 * 8;            \
            const size_t gb = (size_t)(n0 + r) * D_ + k0 + c16 * 8;            \
            cp16(bofs + 0u * TCT16 + swofs[t], Ahi + ga);                      \
            cp16(bofs + 1u * TCT16 + swofs[t], Alo + ga);                      \
            cp16(bofs + 2u * TCT16 + swofs[t], Bhi + gb);                      \
            cp16(bofs + 3u * TCT16 + swofs[t], Blo + gb);                      \
        }                                                                      \
        CP_COMMIT();                                                           \
    }

    LOAD_CHUNK(0, 0);
    LOAD_CHUNK(1, 1);

    int buf = 0;
    for (int c = 0; c < 32; c++) {
        if (c < 31) {
            asm volatile("cp.async.wait_group 1;" ::: "memory");
        } else {
            asm volatile("cp.async.wait_group 0;" ::: "memory");
        }
        __syncthreads();
        if (c + 2 < 32) {
            const int nb = (buf + 2 >= 3) ? buf - 1 : buf + 2;
            LOAD_CHUNK(c + 2, nb);
        }

        const uint32_t bofs = sbase + (uint32_t)buf * TCBUF;
        const uint32_t Ab_hi = bofs + 0u * TCT16;
        const uint32_t Ab_lo = bofs + 1u * TCT16;
        const uint32_t Bb_hi = bofs + 2u * TCT16;
        const uint32_t Bb_lo = bofs + 3u * TCT16;

#pragma unroll
        for (int kk = 0; kk < 4; kk++) {
            uint32_t ah[4][4], al[4][4], bh[4][2], bl[4][2];
            const uint32_t kb = (uint32_t)(kk * 32);
#pragma unroll
            for (int mt = 0; mt < 4; mt++) {
                const uint32_t ofs = swz128((arow + mt * 16u) * 128u + acol + kb);
                ldsm_x4(Ab_hi + ofs, ah[mt]);
                ldsm_x4(Ab_lo + ofs, al[mt]);
            }
#pragma unroll
            for (int ntp = 0; ntp < 2; ntp++) {
                const uint32_t ofs = swz128((browx + ntp * 16u) * 128u + bcol + kb);
                uint32_t b4h[4], b4l[4];
                ldsm_x4(Bb_hi + ofs, b4h);
                ldsm_x4(Bb_lo + ofs, b4l);
                bh[2 * ntp][0] = b4h[0];     bh[2 * ntp][1] = b4h[1];
                bh[2 * ntp + 1][0] = b4h[2]; bh[2 * ntp + 1][1] = b4h[3];
                bl[2 * ntp][0] = b4l[0];     bl[2 * ntp][1] = b4l[1];
                bl[2 * ntp + 1][0] = b4l[2]; bl[2 * ntp + 1][1] = b4l[3];
            }
#pragma unroll
            for (int mt = 0; mt < 4; mt++)
#pragma unroll
                for (int nt = 0; nt < 4; nt++) {
                    mma16816(acc[mt][nt], ah[mt], bh[nt]);
                    mma16816(acc[mt][nt], ah[mt], bl[nt]);
                    mma16816(acc[mt][nt], al[mt], bh[nt]);
                }
        }
        __syncthreads();
        buf = (buf + 1 >= 3) ? 0 : buf + 1;
    }

    // ---- epilogue: stage fp32 tile, rope, split, store bf16 hi/lo ----
    float* Cs = (float*)smem;                 // [128][132] = 67.6 KB
    const int lr = lane >> 2;
    const int lc = (lane & 3) * 2;
#pragma unroll
    for (int mt = 0; mt < 4; mt++)
#pragma unroll
        for (int rr = 0; rr < 2; rr++) {
            const int rloc = m0w + mt * 16 + rr * 8 + lr;
            const int e = rr * 2;
#pragma unroll
            for (int nt = 0; nt < 4; nt++) {
                const int nloc = n0w + nt * 8 + lc;
                *(float2*)&Cs[rloc * 132 + nloc] =
                    make_float2(acc[mt][nt][e], acc[mt][nt][e + 1]);
            }
        }
    __syncthreads();

    const float scq = (z == 0) ? 0.08838834764831845f : 1.0f;
    const bool do_rope = (z < 2);
    for (int i = tid; i < 128 * 32; i += 256) {
        const int r  = i >> 5;
        const int c0 = (i & 31) * 2;
        const int m  = m0 + r;
        const int s  = m & (S_ - 1);
        const int bb = m >> 11;
        const float2 v1 = *(float2*)&Cs[r * 132 + c0];        // cols c0, c0+1
        const float2 v2 = *(float2*)&Cs[r * 132 + c0 + 64];   // cols c0+64, c0+65
        float c_0 = 1.0f, s_0 = 0.0f, c_1 = 1.0f, s_1 = 0.0f;
        if (do_rope) {
            const int ti = (s << 6) + c0;
            c_0 = g_cos[ti];     s_0 = g_sin[ti];
            c_1 = g_cos[ti + 1]; s_1 = g_sin[ti + 1];
        }
        const float o1_0 = (v1.x * c_0 - v2.x * s_0) * scq;
        const float o1_1 = (v1.y * c_1 - v2.y * s_1) * scq;
        const float o2_0 = (v1.x * s_0 + v2.x * c_0) * scq;
        const float o2_1 = (v1.y * s_1 + v2.y * c_1) * scq;

        __nv_bfloat16 h0, l0, h1, l1, h2, l2, h3, l3;
        split1(o1_0, h0, l0); split1(o1_1, h1, l1);
        split1(o2_0, h2, l2); split1(o2_1, h3, l3);

        const size_t base = ((size_t)(bb * H_ + h) * S_ + s) * HD_;
        *(__nv_bfloat162*)&Dhi[base + c0]      = __nv_bfloat162(h0, h1);
        *(__nv_bfloat162*)&Dlo[base + c0]      = __nv_bfloat162(l0, l1);
        *(__nv_bfloat162*)&Dhi[base + c0 + 64] = __nv_bfloat162(h2, h3);
        *(__nv_bfloat162*)&Dlo[base + c0 + 64] = __nv_bfloat162(l2, l3);
    }
}

// ---------------------------------------------------------------------------
// Output-projection GEMM (row-major epilogue to fp32) — R7 kernel.
// ---------------------------------------------------------------------------
__global__ void __launch_bounds__(256, 1)
sgemm_tc(const __nv_bfloat16* __restrict__ Ahi, const __nv_bfloat16* __restrict__ Alo,
         const __nv_bfloat16* __restrict__ Bhi, const __nv_bfloat16* __restrict__ Blo,
         float* __restrict__ C)
{
    extern __shared__ char smem[];
    const uint32_t sbase = smem_u32(smem);

    const int tid  = threadIdx.x;
    const int lane = tid & 31;
    const int w    = tid >> 5;
    const int m0w  = (w >> 2) * 64;
    const int n0w  = (w & 3) * 32;

    const int m0 = blockIdx.y * 128;
    const int n0 = blockIdx.x * 128;

    uint32_t swofs[4];
#pragma unroll
    for (int t = 0; t < 4; t++) {
        const int u = tid + (t << 8);
        swofs[t] = swz128((uint32_t)((u >> 3) * 128 + (u & 7) * 16));
    }

    float acc[4][4][4];
#pragma unroll
    for (int i = 0; i < 4; i++)
#pragma unroll
        for (int j = 0; j < 4; j++)
#pragma unroll
            for (int r = 0; r < 4; r++) acc[i][j][r] = 0.0f;

    const uint32_t arow = (uint32_t)(m0w + (lane & 15));
    const uint32_t acol = (uint32_t)((lane >> 4) << 4);
    const uint32_t browx = (uint32_t)(n0w + (lane & 7) + ((lane >> 4) << 3));
    const uint32_t bcol  = (uint32_t)(((lane >> 3) & 1) << 4);

    LOAD_CHUNK(0, 0);
    LOAD_CHUNK(1, 1);

    int buf = 0;
    for (int c = 0; c < 32; c++) {
        if (c < 31) {
            asm volatile("cp.async.wait_group 1;" ::: "memory");
        } else {
            asm volatile("cp.async.wait_group 0;" ::: "memory");
        }
        __syncthreads();
        if (c + 2 < 32) {
            const int nb = (buf + 2 >= 3) ? buf - 1 : buf + 2;
            LOAD_CHUNK(c + 2, nb);
        }

        const uint32_t bofs = sbase + (uint32_t)buf * TCBUF;
        const uint32_t Ab_hi = bofs + 0u * TCT16;
        const uint32_t Ab_lo = bofs + 1u * TCT16;
        const uint32_t Bb_hi = bofs + 2u * TCT16;
        const uint32_t Bb_lo = bofs + 3u * TCT16;

#pragma unroll
        for (int kk = 0; kk < 4; kk++) {
            uint32_t ah[4][4], al[4][4], bh[4][2], bl[4][2];
            const uint32_t kb = (uint32_t)(kk * 32);
#pragma unroll
            for (int mt = 0; mt < 4; mt++) {
                const uint32_t ofs = swz128((arow + mt * 16u) * 128u + acol + kb);
                ldsm_x4(Ab_hi + ofs, ah[mt]);
                ldsm_x4(Ab_lo + ofs, al[mt]);
            }
#pragma unroll
            for (int ntp = 0; ntp < 2; ntp++) {
                const uint32_t ofs = swz128((browx + ntp * 16u) * 128u + bcol + kb);
                uint32_t b4h[4], b4l[4];
                ldsm_x4(Bb_hi + ofs, b4h);
                ldsm_x4(Bb_lo + ofs, b4l);
                bh[2 * ntp][0] = b4h[0];     bh[2 * ntp][1] = b4h[1];
                bh[2 * ntp + 1][0] = b4h[2]; bh[2 * ntp + 1][1] = b4h[3];
                bl[2 * ntp][0] = b4l[0];     bl[2 * ntp][1] = b4l[1];
                bl[2 * ntp + 1][0] = b4l[2]; bl[2 * ntp + 1][1] = b4l[3];
            }
#pragma unroll
            for (int mt = 0; mt < 4; mt++)
#pragma unroll
                for (int nt = 0; nt < 4; nt++) {
                    mma16816(acc[mt][nt], ah[mt], bh[nt]);
                    mma16816(acc[mt][nt], ah[mt], bl[nt]);
                    mma16816(acc[mt][nt], al[mt], bh[nt]);
                }
        }
        __syncthreads();
        buf = (buf + 1 >= 3) ? 0 : buf + 1;
    }

    const int lr = lane >> 2;
    const int lc = (lane & 3) * 2;
#pragma unroll
    for (int mt = 0; mt < 4; mt++) {
#pragma unroll
        for (int rr = 0; rr < 2; rr++) {
            const int m = m0 + m0w + mt * 16 + rr * 8 + lr;
            const int e = rr * 2;
            const size_t dstbase = (size_t)m * D_;
#pragma unroll
            for (int nt = 0; nt < 4; nt++) {
                const int n = n0 + n0w + nt * 8 + lc;
                *(float2*)&C[dstbase + n] =
                    make_float2(acc[mt][nt][e], acc[mt][nt][e + 1]);
            }
        }
    }
}

// ---------------------------------------------------------------------------
// Tensor-core flash attention (causal), split-bf16; epilogue emits bf16 hi/lo.
// ---------------------------------------------------------------------------
#define FL_SMEM (65536 + 2 * 65536)

__global__ void __launch_bounds__(256, 1)
flash_tc(const __nv_bfloat16* __restrict__ Qhi, const __nv_bfloat16* __restrict__ Qlo,
         const __nv_bfloat16* __restrict__ Khi, const __nv_bfloat16* __restrict__ Klo,
         const __nv_bfloat16* __restrict__ Vhi, const __nv_bfloat16* __restrict__ Vlo,
         __nv_bfloat16* __restrict__ AOhi, __nv_bfloat16* __restrict__ AOlo)
{
    extern __shared__ char smem[];
    const uint32_t sb = smem_u32(smem);
    const uint32_t sQh = sb;
    const uint32_t sQl = sb + 32768u;

    const int tid  = threadIdx.x;
    const int lane = tid & 31;
    const int w    = tid >> 5;
    const int lr   = lane >> 2;
    const int lc2  = (lane & 3) * 2;

    const int qt = (int)gridDim.x - 1 - (int)blockIdx.x;
    const int h  = blockIdx.y;
    const int b  = blockIdx.z;
    const size_t bh = ((size_t)(b * H_ + h)) * S_ * HD_;

    const __nv_bfloat16* Qhg = Qhi + bh + (size_t)qt * 128 * HD_;
    const __nv_bfloat16* Qlg = Qlo + bh + (size_t)qt * 128 * HD_;

    for (int i = tid; i < 2048; i += 256) {
        const uint32_t r = (uint32_t)(i >> 4);
        const uint32_t cb = (uint32_t)((i & 15) << 4);
        const uint32_t so = swzf(r, cb);
        cp16(sQh + so, Qhg + (size_t)r * HD_ + (i & 15) * 8);
        cp16(sQl + so, Qlg + (size_t)r * HD_ + (i & 15) * 8);
    }

#define LOAD_KV(jj, buf)                                                       \
    {                                                                          \
        const uint32_t kvb = sb + 65536u + (uint32_t)(buf) * 65536u;           \
        const size_t rg0 = (size_t)(jj) * 64;                                  \
        for (int i = tid; i < 1024; i += 256) {                                \
            const uint32_t r = (uint32_t)(i >> 4);                             \
            const uint32_t cb = (uint32_t)((i & 15) << 4);                     \
            const uint32_t so = swzf(r, cb);                                   \
            const size_t g = bh + (rg0 + r) * HD_ + (i & 15) * 8;              \
            cp16(kvb + so, Khi + g);                                           \
            cp16(kvb + 16384u + so, Klo + g);                                  \
            cp16(kvb + 32768u + so, Vhi + g);                                  \
            cp16(kvb + 49152u + so, Vlo + g);                                  \
        }                                                                      \
    }

    LOAD_KV(0, 0);
    CP_COMMIT();

    float o[16][4];
#pragma unroll
    for (int i = 0; i < 16; i++)
#pragma unroll
        for (int e = 0; e < 4; e++) o[i][e] = 0.0f;
    float m0 = -1e30f, m1 = -1e30f, l0 = 0.0f, l1 = 0.0f;

    const int jmax = 2 * qt + 1;
    const int rbase = qt * 128 + w * 16 + lr;

    const uint32_t krowx = (uint32_t)((lane & 7) + ((lane >> 4) << 3));
    const uint32_t kcolx = (uint32_t)(((lane >> 3) & 1) << 4);

    for (int j = 0; j <= jmax; j++) {
        if (j < jmax) {
            LOAD_KV(j + 1, (j + 1) & 1);
            CP_COMMIT();
            asm volatile("cp.async.wait_group 1;" ::: "memory");
        } else {
            asm volatile("cp.async.wait_group 0;" ::: "memory");
        }
        __syncthreads();

        const uint32_t kvb = sb + 65536u + (uint32_t)(j & 1) * 65536u;
        const uint32_t sKh = kvb;
        const uint32_t sKl = kvb + 16384u;
        const uint32_t sVh = kvb + 32768u;
        const uint32_t sVl = kvb + 49152u;

        float sacc[8][4];
#pragma unroll
        for (int nt = 0; nt < 8; nt++)
#pragma unroll
            for (int e = 0; e < 4; e++) sacc[nt][e] = 0.0f;

#pragma unroll
        for (int kc = 0; kc < 8; kc++) {
            const uint32_t ao_ = swzf((uint32_t)(w * 16 + (lane & 15)),
                                      (uint32_t)(kc * 32 + ((lane >> 4) << 4)));
            uint32_t ah[4], al[4];
            ldsm_x4(sQh + ao_, ah);
            ldsm_x4(sQl + ao_, al);
#pragma unroll
            for (int ntp = 0; ntp < 4; ntp++) {
                const uint32_t bo = swzf(krowx + ntp * 16u,
                                         (uint32_t)(kc * 32) + kcolx);
                uint32_t b4h[4], b4l[4];
                ldsm_x4(sKh + bo, b4h);
                ldsm_x4(sKl + bo, b4l);
                mma16816(sacc[2 * ntp],     ah, &b4h[0]);
                mma16816(sacc[2 * ntp],     ah, &b4l[0]);
                mma16816(sacc[2 * ntp],     al, &b4h[0]);
                mma16816(sacc[2 * ntp + 1], ah, &b4h[2]);
                mma16816(sacc[2 * ntp + 1], ah, &b4l[2]);
                mma16816(sacc[2 * ntp + 1], al, &b4h[2]);
            }
        }

        if (j >= 2 * qt) {
            const int cb0 = j * 64 + lc2;
#pragma unroll
            for (int nt = 0; nt < 8; nt++)
#pragma unroll
                for (int e = 0; e < 4; e++) {
                    const int col = cb0 + nt * 8 + (e & 1);
                    const int row = rbase + 8 * (e >> 1);
                    if (col > row) sacc[nt][e] = -1e30f;
                }
        }

        float mx0 = -1e30f, mx1 = -1e30f;
#pragma unroll
        for (int nt = 0; nt < 8; nt++) {
            mx0 = fmaxf(mx0, fmaxf(sacc[nt][0], sacc[nt][1]));
            mx1 = fmaxf(mx1, fmaxf(sacc[nt][2], sacc[nt][3]));
        }
        mx0 = fmaxf(mx0, __shfl_xor_sync(0xffffffffu, mx0, 1));
        mx0 = fmaxf(mx0, __shfl_xor_sync(0xffffffffu, mx0, 2));
        mx1 = fmaxf(mx1, __shfl_xor_sync(0xffffffffu, mx1, 1));
        mx1 = fmaxf(mx1, __shfl_xor_sync(0xffffffffu, mx1, 2));

        const float mn0 = fmaxf(m0, mx0);
        const float mn1 = fmaxf(m1, mx1);
        const float al0 = __expf(m0 - mn0);
        const float al1 = __expf(m1 - mn1);
        m0 = mn0; m1 = mn1;

        float s0 = 0.0f, s1 = 0.0f;
#pragma unroll
        for (int nt = 0; nt < 8; nt++) {
            sacc[nt][0] = __expf(sacc[nt][0] - mn0); s0 += sacc[nt][0];
            sacc[nt][1] = __expf(sacc[nt][1] - mn0); s0 += sacc[nt][1];
            sacc[nt][2] = __expf(sacc[nt][2] - mn1); s1 += sacc[nt][2];
            sacc[nt][3] = __expf(sacc[nt][3] - mn1); s1 += sacc[nt][3];
        }
        s0 += __shfl_xor_sync(0xffffffffu, s0, 1);
        s0 += __shfl_xor_sync(0xffffffffu, s0, 2);
        s1 += __shfl_xor_sync(0xffffffffu, s1, 1);
        s1 += __shfl_xor_sync(0xffffffffu, s1, 2);
        l0 = l0 * al0 + s0;
        l1 = l1 * al1 + s1;

#pragma unroll
        for (int dt = 0; dt < 16; dt++) {
            o[dt][0] *= al0; o[dt][1] *= al0;
            o[dt][2] *= al1; o[dt][3] *= al1;
        }

#pragma unroll
        for (int t = 0; t < 4; t++) {
            uint32_t ph[4], pl[4];
#pragma unroll
            for (int q2 = 0; q2 < 2; q2++)
#pragma unroll
                for (int rr = 0; rr < 2; rr++) {
                    const float x = sacc[2 * t + q2][2 * rr];
                    const float y = sacc[2 * t + q2][2 * rr + 1];
                    __nv_bfloat16 bx = __float2bfloat16(x);
                    __nv_bfloat16 by = __float2bfloat16(y);
                    __nv_bfloat16 cx = __float2bfloat16(x - __bfloat162float(bx));
                    __nv_bfloat16 cy = __float2bfloat16(y - __bfloat162float(by));
                    ph[q2 * 2 + rr] = pack2(bx, by);
                    pl[q2 * 2 + rr] = pack2(cx, cy);
                }
#pragma unroll
            for (int dtp = 0; dtp < 8; dtp++) {
                const uint32_t bo = swzf((uint32_t)(t * 16 + (lane & 15)),
                                         (uint32_t)((2 * dtp + (lane >> 4)) * 16));
                uint32_t b4h[4], b4l[4];
                ldsm_x4t(sVh + bo, b4h);
                ldsm_x4t(sVl + bo, b4l);
                mma16816(o[2 * dtp],     ph, &b4h[0]);
                mma16816(o[2 * dtp],     ph, &b4l[0]);
                mma16816(o[2 * dtp],     pl, &b4h[0]);
                mma16816(o[2 * dtp + 1], ph, &b4h[2]);
                mma16816(o[2 * dtp + 1], ph, &b4l[2]);
                mma16816(o[2 * dtp + 1], pl, &b4h[2]);
            }
        }
        __syncthreads();
    }

    // epilogue: normalize, split to bf16 hi/lo, store to AO operand arrays
    const float inv0 = 1.0f / l0;
    const float inv1 = 1.0f / l1;
    const int srow0 = qt * 128 + w * 16 + lr;
    const size_t d0 = ((size_t)(b * S_ + srow0)) * D_ + h * HD_;
    const size_t d1 = ((size_t)(b * S_ + srow0 + 8)) * D_ + h * HD_;
#pragma unroll
    for (int dt = 0; dt < 16; dt++) {
        __nv_bfloat16 h0, l0b, h1, l1b;
        split1(o[dt][0] * inv0, h0, l0b);
        split1(o[dt][1] * inv0, h1, l1b);
        *(__nv_bfloat162*)&AOhi[d0 + dt * 8 + lc2] = __nv_bfloat162(h0, h1);
        *(__nv_bfloat162*)&AOlo[d0 + dt * 8 + lc2] = __nv_bfloat162(l0b, l1b);
        split1(o[dt][2] * inv1, h0, l0b);
        split1(o[dt][3] * inv1, h1, l1b);
        *(__nv_bfloat162*)&AOhi[d1 + dt * 8 + lc2] = __nv_bfloat162(h0, h1);
        *(__nv_bfloat162*)&AOlo[d1 + dt * 8 + lc2] = __nv_bfloat162(l0b, l1b);
    }
}

// ---------------------------------------------------------------------------
extern "C" void kernel_launch(void* const* d_in, const int* in_sizes, int n_in,
                              void* d_out, int out_size)
{
    (void)in_sizes; (void)n_in; (void)out_size;
    const float* x  = (const float*)d_in[0];
    const float* Wq = (const float*)d_in[2];
    const float* Wk = (const float*)d_in[3];
    const float* Wv = (const float*)d_in[4];
    const float* Wo = (const float*)d_in[5];
    float* out = (float*)d_out;

    __nv_bfloat16 *xhi, *xlo, *aohi, *aolo;
    __nv_bfloat16 *wqhi, *wqlo, *wkhi, *wklo, *wvhi, *wvlo, *wohi, *wolo;
    __nv_bfloat16 *qh, *ql, *kh, *kl, *vh, *vl;
    cudaGetSymbolAddress((void**)&xhi, g_xhi);
    cudaGetSymbolAddress((void**)&xlo, g_xlo);
    cudaGetSymbolAddress((void**)&aohi, g_aohi);
    cudaGetSymbolAddress((void**)&aolo, g_aolo);
    cudaGetSymbolAddress((void**)&wqhi, g_wqhi);
    cudaGetSymbolAddress((void**)&wqlo, g_wqlo);
    cudaGetSymbolAddress((void**)&wkhi, g_wkhi);
    cudaGetSymbolAddress((void**)&wklo, g_wklo);
    cudaGetSymbolAddress((void**)&wvhi, g_wvhi);
    cudaGetSymbolAddress((void**)&wvlo, g_wvlo);
    cudaGetSymbolAddress((void**)&wohi, g_wohi);
    cudaGetSymbolAddress((void**)&wolo, g_wolo);
    cudaGetSymbolAddress((void**)&qh, g_qh);
    cudaGetSymbolAddress((void**)&ql, g_ql);
    cudaGetSymbolAddress((void**)&kh, g_kh);
    cudaGetSymbolAddress((void**)&kl, g_kl);
    cudaGetSymbolAddress((void**)&vh, g_vh);
    cudaGetSymbolAddress((void**)&vl, g_vl);

    cudaFuncSetAttribute(sgemm_qkv,
                         cudaFuncAttributeMaxDynamicSharedMemorySize, TC_SMEM_BYTES);
    cudaFuncSetAttribute(sgemm_tc,
                         cudaFuncAttributeMaxDynamicSharedMemorySize, TC_SMEM_BYTES);
    cudaFuncSetAttribute(flash_tc,
                         cudaFuncAttributeMaxDynamicSharedMemorySize, FL_SMEM);

    // 1) splits of inputs
    const int xn4 = (B_ * S_ * D_) / 4;
    const int wn4 = (D_ * D_) / 4;
    split_bf16<<<(xn4 + 255) / 256, 256>>>(x, xhi, xlo, xn4);
    split_bf16<<<(wn4 + 255) / 256, 256>>>(Wq, wqhi, wqlo, wn4);
    split_bf16<<<(wn4 + 255) / 256, 256>>>(Wk, wkhi, wklo, wn4);
    split_bf16<<<(wn4 + 255) / 256, 256>>>(Wv, wvhi, wvlo, wn4);
    split_bf16<<<(wn4 + 255) / 256, 256>>>(Wo, wohi, wolo, wn4);

    // 2) rope tables
    rope_table_kernel<<<(S_ * 64 + 255) / 256, 256>>>();

    // 3) merged QKV projection with fused rope+split epilogue
    QKVPtrs P;
    P.bhi[0] = wqhi; P.blo[0] = wqlo; P.dhi[0] = qh; P.dlo[0] = ql;
    P.bhi[1] = wkhi; P.blo[1] = wklo; P.dhi[1] = kh; P.dlo[1] = kl;
    P.bhi[2] = wvhi; P.blo[2] = wvlo; P.dhi[2] = vh; P.dlo[2] = vl;
    dim3 qkvgrid(D_ / 128, (B_ * S_) / 128, 3);   // (16, 32, 3)
    sgemm_qkv<<<qkvgrid, 256, TC_SMEM_BYTES>>>(xhi, xlo, P);

    // 4) tensor-core flash attention (emits AO bf16 hi/lo directly)
    flash_tc<<<dim3(S_ / 128, H_, B_), 256, FL_SMEM>>>(qh, ql, kh, kl, vh, vl,
                                                        aohi, aolo);

    // 5) output projection
    dim3 ggrid(D_ / 128, (B_ * S_) / 128);
    sgemm_tc<<<ggrid, 256, TC_SMEM_BYTES>>>(aohi, aolo, wohi, wolo, out);
}

// round 9
// speedup vs baseline: 1.6977x; 1.1131x over previous
#include <cuda_runtime.h>
#include <cuda_bf16.h>
#include <cuda_fp16.h>
#include <math.h>
#include <stdint.h>

#define B_ 2
#define S_ 2048
#define D_ 2048
#define H_ 16
#define HD_ 128

// ---------------- device scratch (no runtime allocation) ----------------
__device__ __nv_bfloat16 g_xhi[B_ * S_ * D_];
__device__ __nv_bfloat16 g_xlo[B_ * S_ * D_];
__device__ __nv_bfloat16 g_wqhi[D_ * D_], g_wqlo[D_ * D_];
__device__ __nv_bfloat16 g_wkhi[D_ * D_], g_wklo[D_ * D_];
__device__ __nv_bfloat16 g_wvhi[D_ * D_], g_wvlo[D_ * D_];
__device__ __half g_wo16[D_ * D_];
__device__ __half g_ao16[B_ * S_ * D_];

// attention operands (bf16 hi/lo, head layout [b][h][s][hd])
__device__ __nv_bfloat16 g_qh[B_ * H_ * S_ * HD_], g_ql[B_ * H_ * S_ * HD_];
__device__ __nv_bfloat16 g_kh[B_ * H_ * S_ * HD_], g_kl[B_ * H_ * S_ * HD_];
__device__ __nv_bfloat16 g_vh[B_ * H_ * S_ * HD_], g_vl[B_ * H_ * S_ * HD_];

__device__ float g_cos[S_ * 64];
__device__ float g_sin[S_ * 64];

// ---------------- helpers ----------------
__device__ __forceinline__ uint32_t smem_u32(const void* p) {
    uint32_t a;
    asm("{ .reg .u64 t; cvta.to.shared.u64 t, %1; cvt.u32.u64 %0, t; }"
        : "=r"(a) : "l"(p));
    return a;
}
static __device__ __forceinline__ uint32_t swz128(uint32_t o) {
    return o ^ ((o >> 3) & 0x70);
}
static __device__ __forceinline__ uint32_t swzf(uint32_t row, uint32_t colbyte) {
    return row * 256u + (colbyte ^ ((row & 7u) << 4));
}
__device__ __forceinline__ void cp16(uint32_t saddr, const void* gptr) {
    asm volatile("cp.async.cg.shared.global [%0], [%1], 16;"
                 :: "r"(saddr), "l"(gptr) : "memory");
}
#define CP_COMMIT() asm volatile("cp.async.commit_group;" ::: "memory")

__device__ __forceinline__ void ldsm_x4(uint32_t a, uint32_t* r) {
    asm volatile("ldmatrix.sync.aligned.m8n8.x4.shared.b16 {%0,%1,%2,%3}, [%4];"
                 : "=r"(r[0]), "=r"(r[1]), "=r"(r[2]), "=r"(r[3]) : "r"(a));
}
__device__ __forceinline__ void ldsm_x4t(uint32_t a, uint32_t* r) {
    asm volatile("ldmatrix.sync.aligned.m8n8.x4.trans.shared.b16 {%0,%1,%2,%3}, [%4];"
                 : "=r"(r[0]), "=r"(r[1]), "=r"(r[2]), "=r"(r[3]) : "r"(a));
}
__device__ __forceinline__ void mma16816(float* d, const uint32_t* a, const uint32_t* b) {
    asm volatile(
        "mma.sync.aligned.m16n8k16.row.col.f32.bf16.bf16.f32 "
        "{%0,%1,%2,%3}, {%4,%5,%6,%7}, {%8,%9}, {%0,%1,%2,%3};"
        : "+f"(d[0]), "+f"(d[1]), "+f"(d[2]), "+f"(d[3])
        : "r"(a[0]), "r"(a[1]), "r"(a[2]), "r"(a[3]), "r"(b[0]), "r"(b[1]));
}
__device__ __forceinline__ void mma16816h(float* d, const uint32_t* a, const uint32_t* b) {
    asm volatile(
        "mma.sync.aligned.m16n8k16.row.col.f32.f16.f16.f32 "
        "{%0,%1,%2,%3}, {%4,%5,%6,%7}, {%8,%9}, {%0,%1,%2,%3};"
        : "+f"(d[0]), "+f"(d[1]), "+f"(d[2]), "+f"(d[3])
        : "r"(a[0]), "r"(a[1]), "r"(a[2]), "r"(a[3]), "r"(b[0]), "r"(b[1]));
}
__device__ __forceinline__ uint32_t pack2(__nv_bfloat16 a, __nv_bfloat16 b) {
    __nv_bfloat162 t(a, b);
    return *(uint32_t*)&t;
}
__device__ __forceinline__ void split1(float x, __nv_bfloat16& h, __nv_bfloat16& l) {
    h = __float2bfloat16(x);
    l = __float2bfloat16(x - __bfloat162float(h));
}

// ---------------------------------------------------------------------------
// RoPE tables (once; double math)
// ---------------------------------------------------------------------------
__global__ void rope_table_kernel()
{
    int idx = blockIdx.x * blockDim.x + threadIdx.x;
    if (idx >= S_ * 64) return;
    const int i = idx & 63;
    const int s = idx >> 6;
    const float inv_freq = (float)pow(10000.0, -(double)i * (1.0 / 64.0));
    const double ang = (double)s * (double)inv_freq;
    double sd, cd;
    sincos(ang, &sd, &cd);
    g_cos[idx] = (float)cd;
    g_sin[idx] = (float)sd;
}

// ---------------------------------------------------------------------------
// Split fp32 -> bf16 hi/lo (x input)
// ---------------------------------------------------------------------------
__global__ void split_bf16(const float* __restrict__ in,
                           __nv_bfloat16* __restrict__ hi,
                           __nv_bfloat16* __restrict__ lo, int n4)
{
    int i = blockIdx.x * blockDim.x + threadIdx.x;
    if (i >= n4) return;
    float4 v = ((const float4*)in)[i];
    __nv_bfloat16 h0, h1, h2, h3, l0, l1, l2, l3;
    split1(v.x, h0, l0); split1(v.y, h1, l1);
    split1(v.z, h2, l2); split1(v.w, h3, l3);
    __nv_bfloat162* hi2 = (__nv_bfloat162*)hi;
    __nv_bfloat162* lo2 = (__nv_bfloat162*)lo;
    hi2[2 * i]     = __nv_bfloat162(h0, h1);
    hi2[2 * i + 1] = __nv_bfloat162(h2, h3);
    lo2[2 * i]     = __nv_bfloat162(l0, l1);
    lo2[2 * i + 1] = __nv_bfloat162(l2, l3);
}

// Batched: split Wq/Wk/Wv (z = 0..2) to bf16 hi/lo
struct WSplitPtrs {
    const float* w[3];
    __nv_bfloat16* hi[3];
    __nv_bfloat16* lo[3];
};
__global__ void split_w3(WSplitPtrs P, int n4)
{
    int i = blockIdx.x * blockDim.x + threadIdx.x;
    if (i >= n4) return;
    const int z = blockIdx.y;
    float4 v = ((const float4*)P.w[z])[i];
    __nv_bfloat16 h0, h1, h2, h3, l0, l1, l2, l3;
    split1(v.x, h0, l0); split1(v.y, h1, l1);
    split1(v.z, h2, l2); split1(v.w, h3, l3);
    __nv_bfloat162* hi2 = (__nv_bfloat162*)P.hi[z];
    __nv_bfloat162* lo2 = (__nv_bfloat162*)P.lo[z];
    hi2[2 * i]     = __nv_bfloat162(h0, h1);
    hi2[2 * i + 1] = __nv_bfloat162(h2, h3);
    lo2[2 * i]     = __nv_bfloat162(l0, l1);
    lo2[2 * i + 1] = __nv_bfloat162(l2, l3);
}

// Wo: fp32 -> fp16 (single limb)
__global__ void split_wo_f16(const float* __restrict__ in, __half* __restrict__ o, int n4)
{
    int i = blockIdx.x * blockDim.x + threadIdx.x;
    if (i >= n4) return;
    float4 v = ((const float4*)in)[i];
    half2* o2 = (half2*)o;
    o2[2 * i]     = __halves2half2(__float2half(v.x), __float2half(v.y));
    o2[2 * i + 1] = __halves2half2(__float2half(v.z), __float2half(v.w));
}

// ---------------------------------------------------------------------------
// Merged QKV GEMM (bf16 3-product), fused rope+split epilogue — R8 kernel.
// ---------------------------------------------------------------------------
#define TCT16 16384u
#define TCBUF (4u * TCT16)
#define TC_SMEM_BYTES (3u * TCBUF)

struct QKVPtrs {
    const __nv_bfloat16* bhi[3];
    const __nv_bfloat16* blo[3];
    __nv_bfloat16* dhi[3];
    __nv_bfloat16* dlo[3];
};

__global__ void __launch_bounds__(256, 1)
sgemm_qkv(const __nv_bfloat16* __restrict__ Ahi, const __nv_bfloat16* __restrict__ Alo,
          QKVPtrs P)
{
    extern __shared__ char smem[];
    const uint32_t sbase = smem_u32(smem);

    const int z = blockIdx.z;
    const __nv_bfloat16* __restrict__ Bhi = P.bhi[z];
    const __nv_bfloat16* __restrict__ Blo = P.blo[z];
    __nv_bfloat16* __restrict__ Dhi = P.dhi[z];
    __nv_bfloat16* __restrict__ Dlo = P.dlo[z];

    const int tid  = threadIdx.x;
    const int lane = tid & 31;
    const int w    = tid >> 5;
    const int m0w  = (w >> 2) * 64;
    const int n0w  = (w & 3) * 32;

    const int m0 = blockIdx.y * 128;
    const int n0 = blockIdx.x * 128;
    const int h  = blockIdx.x;

    uint32_t swofs[4];
#pragma unroll
    for (int t = 0; t < 4; t++) {
        const int u = tid + (t << 8);
        swofs[t] = swz128((uint32_t)((u >> 3) * 128 + (u & 7) * 16));
    }

    float acc[4][4][4];
#pragma unroll
    for (int i = 0; i < 4; i++)
#pragma unroll
        for (int j = 0; j < 4; j++)
#pragma unroll
            for (int r = 0; r < 4; r++) acc[i][j][r] = 0.0f;

    const uint32_t arow = (uint32_t)(m0w + (lane & 15));
    const uint32_t acol = (uint32_t)((lane >> 4) << 4);
    const uint32_t browx = (uint32_t)(n0w + (lane & 7) + ((lane >> 4) << 3));
    const uint32_t bcol  = (uint32_t)(((lane >> 3) & 1) << 4);

#define LOAD_CHUNK(c, buf)                                                     \
    {                                                                          \
        const uint32_t bofs = sbase + (uint32_t)(buf) * TCBUF;                 \
        const int k0 = (c) * 64;                                               \
        _Pragma("unroll")                                                      \
        for (int t = 0; t < 4; t++) {                                          \
            const int u = tid + (t << 8);                                      \
            const int r = u >> 3;                                              \
            const int c16 = u & 7;                                             \
            const size_t ga = (size_t)(m0 + r) * D_ + k0 + c16 * 8;            \
            const size_t gb = (size_t)(n0 + r) * D_ + k0 + c16 * 8;            \
            cp16(bofs + 0u * TCT16 + swofs[t], Ahi + ga);                      \
            cp16(bofs + 1u * TCT16 + swofs[t], Alo + ga);                      \
            cp16(bofs + 2u * TCT16 + swofs[t], Bhi + gb);                      \
            cp16(bofs + 3u * TCT16 + swofs[t], Blo + gb);                      \
        }                                                                      \
        CP_COMMIT();                                                           \
    }

    LOAD_CHUNK(0, 0);
    LOAD_CHUNK(1, 1);

    int buf = 0;
    for (int c = 0; c < 32; c++) {
        if (c < 31) {
            asm volatile("cp.async.wait_group 1;" ::: "memory");
        } else {
            asm volatile("cp.async.wait_group 0;" ::: "memory");
        }
        __syncthreads();
        if (c + 2 < 32) {
            const int nb = (buf + 2 >= 3) ? buf - 1 : buf + 2;
            LOAD_CHUNK(c + 2, nb);
        }

        const uint32_t bofs = sbase + (uint32_t)buf * TCBUF;
        const uint32_t Ab_hi = bofs + 0u * TCT16;
        const uint32_t Ab_lo = bofs + 1u * TCT16;
        const uint32_t Bb_hi = bofs + 2u * TCT16;
        const uint32_t Bb_lo = bofs + 3u * TCT16;

#pragma unroll
        for (int kk = 0; kk < 4; kk++) {
            uint32_t ah[4][4], al[4][4], bh[4][2], bl[4][2];
            const uint32_t kb = (uint32_t)(kk * 32);
#pragma unroll
            for (int mt = 0; mt < 4; mt++) {
                const uint32_t ofs = swz128((arow + mt * 16u) * 128u + acol + kb);
                ldsm_x4(Ab_hi + ofs, ah[mt]);
                ldsm_x4(Ab_lo + ofs, al[mt]);
            }
#pragma unroll
            for (int ntp = 0; ntp < 2; ntp++) {
                const uint32_t ofs = swz128((browx + ntp * 16u) * 128u + bcol + kb);
                uint32_t b4h[4], b4l[4];
                ldsm_x4(Bb_hi + ofs, b4h);
                ldsm_x4(Bb_lo + ofs, b4l);
                bh[2 * ntp][0] = b4h[0];     bh[2 * ntp][1] = b4h[1];
                bh[2 * ntp + 1][0] = b4h[2]; bh[2 * ntp + 1][1] = b4h[3];
                bl[2 * ntp][0] = b4l[0];     bl[2 * ntp][1] = b4l[1];
                bl[2 * ntp + 1][0] = b4l[2]; bl[2 * ntp + 1][1] = b4l[3];
            }
#pragma unroll
            for (int mt = 0; mt < 4; mt++)
#pragma unroll
                for (int nt = 0; nt < 4; nt++) {
                    mma16816(acc[mt][nt], ah[mt], bh[nt]);
                    mma16816(acc[mt][nt], ah[mt], bl[nt]);
                    mma16816(acc[mt][nt], al[mt], bh[nt]);
                }
        }
        __syncthreads();
        buf = (buf + 1 >= 3) ? 0 : buf + 1;
    }

    // ---- epilogue: stage fp32 tile, rope, split, store bf16 hi/lo ----
    float* Cs = (float*)smem;
    const int lr = lane >> 2;
    const int lc = (lane & 3) * 2;
#pragma unroll
    for (int mt = 0; mt < 4; mt++)
#pragma unroll
        for (int rr = 0; rr < 2; rr++) {
            const int rloc = m0w + mt * 16 + rr * 8 + lr;
            const int e = rr * 2;
#pragma unroll
            for (int nt = 0; nt < 4; nt++) {
                const int nloc = n0w + nt * 8 + lc;
                *(float2*)&Cs[rloc * 132 + nloc] =
                    make_float2(acc[mt][nt][e], acc[mt][nt][e + 1]);
            }
        }
    __syncthreads();

    const float scq = (z == 0) ? 0.08838834764831845f : 1.0f;
    const bool do_rope = (z < 2);
    for (int i = tid; i < 128 * 32; i += 256) {
        const int r  = i >> 5;
        const int c0 = (i & 31) * 2;
        const int m  = m0 + r;
        const int s  = m & (S_ - 1);
        const int bb = m >> 11;
        const float2 v1 = *(float2*)&Cs[r * 132 + c0];
        const float2 v2 = *(float2*)&Cs[r * 132 + c0 + 64];
        float c_0 = 1.0f, s_0 = 0.0f, c_1 = 1.0f, s_1 = 0.0f;
        if (do_rope) {
            const int ti = (s << 6) + c0;
            c_0 = g_cos[ti];     s_0 = g_sin[ti];
            c_1 = g_cos[ti + 1]; s_1 = g_sin[ti + 1];
        }
        const float o1_0 = (v1.x * c_0 - v2.x * s_0) * scq;
        const float o1_1 = (v1.y * c_1 - v2.y * s_1) * scq;
        const float o2_0 = (v1.x * s_0 + v2.x * c_0) * scq;
        const float o2_1 = (v1.y * s_1 + v2.y * c_1) * scq;

        __nv_bfloat16 h0, l0, h1, l1, h2, l2, h3, l3;
        split1(o1_0, h0, l0); split1(o1_1, h1, l1);
        split1(o2_0, h2, l2); split1(o2_1, h3, l3);

        const size_t base = ((size_t)(bb * H_ + h) * S_ + s) * HD_;
        *(__nv_bfloat162*)&Dhi[base + c0]      = __nv_bfloat162(h0, h1);
        *(__nv_bfloat162*)&Dlo[base + c0]      = __nv_bfloat162(l0, l1);
        *(__nv_bfloat162*)&Dhi[base + c0 + 64] = __nv_bfloat162(h2, h3);
        *(__nv_bfloat162*)&Dlo[base + c0 + 64] = __nv_bfloat162(l2, l3);
    }
}

// ---------------------------------------------------------------------------
// Output projection: PURE fp16 single-product GEMM. out = AO16 @ Wo16^T.
// 128x128 tile, BK=64, 3-stage cp.async (2 tiles/stage = 32KB; 96KB total).
// ---------------------------------------------------------------------------
#define TCBUF16 (2u * TCT16)
#define TC16_SMEM_BYTES (3u * TCBUF16)

__global__ void __launch_bounds__(256)
sgemm_out_f16(const __half* __restrict__ A16, const __half* __restrict__ B16,
              float* __restrict__ C)
{
    extern __shared__ char smem[];
    const uint32_t sbase = smem_u32(smem);

    const int tid  = threadIdx.x;
    const int lane = tid & 31;
    const int w    = tid >> 5;
    const int m0w  = (w >> 2) * 64;
    const int n0w  = (w & 3) * 32;

    const int m0 = blockIdx.y * 128;
    const int n0 = blockIdx.x * 128;

    uint32_t swofs[4];
#pragma unroll
    for (int t = 0; t < 4; t++) {
        const int u = tid + (t << 8);
        swofs[t] = swz128((uint32_t)((u >> 3) * 128 + (u & 7) * 16));
    }

    float acc[4][4][4];
#pragma unroll
    for (int i = 0; i < 4; i++)
#pragma unroll
        for (int j = 0; j < 4; j++)
#pragma unroll
            for (int r = 0; r < 4; r++) acc[i][j][r] = 0.0f;

    const uint32_t arow = (uint32_t)(m0w + (lane & 15));
    const uint32_t acol = (uint32_t)((lane >> 4) << 4);
    const uint32_t browx = (uint32_t)(n0w + (lane & 7) + ((lane >> 4) << 3));
    const uint32_t bcol  = (uint32_t)(((lane >> 3) & 1) << 4);

#define LOAD_CHUNK16(c, buf)                                                   \
    {                                                                          \
        const uint32_t bofs = sbase + (uint32_t)(buf) * TCBUF16;               \
        const int k0 = (c) * 64;                                               \
        _Pragma("unroll")                                                      \
        for (int t = 0; t < 4; t++) {                                          \
            const int u = tid + (t << 8);                                      \
            const int r = u >> 3;                                              \
            const int c16 = u & 7;                                             \
            const size_t ga = (size_t)(m0 + r) * D_ + k0 + c16 * 8;            \
            const size_t gb = (size_t)(n0 + r) * D_ + k0 + c16 * 8;            \
            cp16(bofs + 0u * TCT16 + swofs[t], A16 + ga);                      \
            cp16(bofs + 1u * TCT16 + swofs[t], B16 + gb);                      \
        }                                                                      \
        CP_COMMIT();                                                           \
    }

    LOAD_CHUNK16(0, 0);
    LOAD_CHUNK16(1, 1);

    int buf = 0;
    for (int c = 0; c < 32; c++) {
        if (c < 31) {
            asm volatile("cp.async.wait_group 1;" ::: "memory");
        } else {
            asm volatile("cp.async.wait_group 0;" ::: "memory");
        }
        __syncthreads();
        if (c + 2 < 32) {
            const int nb = (buf + 2 >= 3) ? buf - 1 : buf + 2;
            LOAD_CHUNK16(c + 2, nb);
        }

        const uint32_t bofs = sbase + (uint32_t)buf * TCBUF16;
        const uint32_t Ab = bofs + 0u * TCT16;
        const uint32_t Bb = bofs + 1u * TCT16;

#pragma unroll
        for (int kk = 0; kk < 4; kk++) {
            uint32_t ah[4][4], bh[4][2];
            const uint32_t kb = (uint32_t)(kk * 32);
#pragma unroll
            for (int mt = 0; mt < 4; mt++) {
                const uint32_t ofs = swz128((arow + mt * 16u) * 128u + acol + kb);
                ldsm_x4(Ab + ofs, ah[mt]);
            }
#pragma unroll
            for (int ntp = 0; ntp < 2; ntp++) {
                const uint32_t ofs = swz128((browx + ntp * 16u) * 128u + bcol + kb);
                uint32_t b4[4];
                ldsm_x4(Bb + ofs, b4);
                bh[2 * ntp][0] = b4[0];     bh[2 * ntp][1] = b4[1];
                bh[2 * ntp + 1][0] = b4[2]; bh[2 * ntp + 1][1] = b4[3];
            }
#pragma unroll
            for (int mt = 0; mt < 4; mt++)
#pragma unroll
                for (int nt = 0; nt < 4; nt++)
                    mma16816h(acc[mt][nt], ah[mt], bh[nt]);
        }
        __syncthreads();
        buf = (buf + 1 >= 3) ? 0 : buf + 1;
    }

    const int lr = lane >> 2;
    const int lc = (lane & 3) * 2;
#pragma unroll
    for (int mt = 0; mt < 4; mt++) {
#pragma unroll
        for (int rr = 0; rr < 2; rr++) {
            const int m = m0 + m0w + mt * 16 + rr * 8 + lr;
            const int e = rr * 2;
            const size_t dstbase = (size_t)m * D_;
#pragma unroll
            for (int nt = 0; nt < 4; nt++) {
                const int n = n0 + n0w + nt * 8 + lc;
                *(float2*)&C[dstbase + n] =
                    make_float2(acc[mt][nt][e], acc[mt][nt][e + 1]);
            }
        }
    }
}

// ---------------------------------------------------------------------------
// Tensor-core flash attention (causal), split-bf16; fp16 AO epilogue;
// dead-warp skip on diagonal tiles.
// ---------------------------------------------------------------------------
#define FL_SMEM (65536 + 2 * 65536)

__global__ void __launch_bounds__(256, 1)
flash_tc(const __nv_bfloat16* __restrict__ Qhi, const __nv_bfloat16* __restrict__ Qlo,
         const __nv_bfloat16* __restrict__ Khi, const __nv_bfloat16* __restrict__ Klo,
         const __nv_bfloat16* __restrict__ Vhi, const __nv_bfloat16* __restrict__ Vlo,
         __half* __restrict__ AO16)
{
    extern __shared__ char smem[];
    const uint32_t sb = smem_u32(smem);
    const uint32_t sQh = sb;
    const uint32_t sQl = sb + 32768u;

    const int tid  = threadIdx.x;
    const int lane = tid & 31;
    const int w    = tid >> 5;
    const int lr   = lane >> 2;
    const int lc2  = (lane & 3) * 2;

    const int qt = (int)gridDim.x - 1 - (int)blockIdx.x;
    const int h  = blockIdx.y;
    const int b  = blockIdx.z;
    const size_t bh = ((size_t)(b * H_ + h)) * S_ * HD_;

    const __nv_bfloat16* Qhg = Qhi + bh + (size_t)qt * 128 * HD_;
    const __nv_bfloat16* Qlg = Qlo + bh + (size_t)qt * 128 * HD_;

    for (int i = tid; i < 2048; i += 256) {
        const uint32_t r = (uint32_t)(i >> 4);
        const uint32_t cb = (uint32_t)((i & 15) << 4);
        const uint32_t so = swzf(r, cb);
        cp16(sQh + so, Qhg + (size_t)r * HD_ + (i & 15) * 8);
        cp16(sQl + so, Qlg + (size_t)r * HD_ + (i & 15) * 8);
    }

#define LOAD_KV(jj, buf)                                                       \
    {                                                                          \
        const uint32_t kvb = sb + 65536u + (uint32_t)(buf) * 65536u;           \
        const size_t rg0 = (size_t)(jj) * 64;                                  \
        for (int i = tid; i < 1024; i += 256) {                                \
            const uint32_t r = (uint32_t)(i >> 4);                             \
            const uint32_t cb = (uint32_t)((i & 15) << 4);                     \
            const uint32_t so = swzf(r, cb);                                   \
            const size_t g = bh + (rg0 + r) * HD_ + (i & 15) * 8;              \
            cp16(kvb + so, Khi + g);                                           \
            cp16(kvb + 16384u + so, Klo + g);                                  \
            cp16(kvb + 32768u + so, Vhi + g);                                  \
            cp16(kvb + 49152u + so, Vlo + g);                                  \
        }                                                                      \
    }

    LOAD_KV(0, 0);
    CP_COMMIT();

    float o[16][4];
#pragma unroll
    for (int i = 0; i < 16; i++)
#pragma unroll
        for (int e = 0; e < 4; e++) o[i][e] = 0.0f;
    float m0 = -1e30f, m1 = -1e30f, l0 = 0.0f, l1 = 0.0f;

    const int jmax = 2 * qt + 1;
    const int rbase = qt * 128 + w * 16 + lr;

    const uint32_t krowx = (uint32_t)((lane & 7) + ((lane >> 4) << 3));
    const uint32_t kcolx = (uint32_t)(((lane >> 3) & 1) << 4);

    for (int j = 0; j <= jmax; j++) {
        if (j < jmax) {
            LOAD_KV(j + 1, (j + 1) & 1);
            CP_COMMIT();
            asm volatile("cp.async.wait_group 1;" ::: "memory");
        } else {
            asm volatile("cp.async.wait_group 0;" ::: "memory");
        }
        __syncthreads();

        // dead-warp skip: last (diagonal) tile covers cols >= qt*128+64;
        // warps 0-3 own rows qt*128 + [0,64) -> fully masked, exact no-op.
        const bool active = !(j == jmax && w < 4);
        if (active) {
        const uint32_t kvb = sb + 65536u + (uint32_t)(j & 1) * 65536u;
        const uint32_t sKh = kvb;
        const uint32_t sKl = kvb + 16384u;
        const uint32_t sVh = kvb + 32768u;
        const uint32_t sVl = kvb + 49152u;

        float sacc[8][4];
#pragma unroll
        for (int nt = 0; nt < 8; nt++)
#pragma unroll
            for (int e = 0; e < 4; e++) sacc[nt][e] = 0.0f;

#pragma unroll
        for (int kc = 0; kc < 8; kc++) {
            const uint32_t ao_ = swzf((uint32_t)(w * 16 + (lane & 15)),
                                      (uint32_t)(kc * 32 + ((lane >> 4) << 4)));
            uint32_t ah[4], al[4];
            ldsm_x4(sQh + ao_, ah);
            ldsm_x4(sQl + ao_, al);
#pragma unroll
            for (int ntp = 0; ntp < 4; ntp++) {
                const uint32_t bo = swzf(krowx + ntp * 16u,
                                         (uint32_t)(kc * 32) + kcolx);
                uint32_t b4h[4], b4l[4];
                ldsm_x4(sKh + bo, b4h);
                ldsm_x4(sKl + bo, b4l);
                mma16816(sacc[2 * ntp],     ah, &b4h[0]);
                mma16816(sacc[2 * ntp],     ah, &b4l[0]);
                mma16816(sacc[2 * ntp],     al, &b4h[0]);
                mma16816(sacc[2 * ntp + 1], ah, &b4h[2]);
                mma16816(sacc[2 * ntp + 1], ah, &b4l[2]);
                mma16816(sacc[2 * ntp + 1], al, &b4h[2]);
            }
        }

        if (j >= 2 * qt) {
            const int cb0 = j * 64 + lc2;
#pragma unroll
            for (int nt = 0; nt < 8; nt++)
#pragma unroll
                for (int e = 0; e < 4; e++) {
                    const int col = cb0 + nt * 8 + (e & 1);
                    const int row = rbase + 8 * (e >> 1);
                    if (col > row) sacc[nt][e] = -1e30f;
                }
        }

        float mx0 = -1e30f, mx1 = -1e30f;
#pragma unroll
        for (int nt = 0; nt < 8; nt++) {
            mx0 = fmaxf(mx0, fmaxf(sacc[nt][0], sacc[nt][1]));
            mx1 = fmaxf(mx1, fmaxf(sacc[nt][2], sacc[nt][3]));
        }
        mx0 = fmaxf(mx0, __shfl_xor_sync(0xffffffffu, mx0, 1));
        mx0 = fmaxf(mx0, __shfl_xor_sync(0xffffffffu, mx0, 2));
        mx1 = fmaxf(mx1, __shfl_xor_sync(0xffffffffu, mx1, 1));
        mx1 = fmaxf(mx1, __shfl_xor_sync(0xffffffffu, mx1, 2));

        const float mn0 = fmaxf(m0, mx0);
        const float mn1 = fmaxf(m1, mx1);
        const float al0 = __expf(m0 - mn0);
        const float al1 = __expf(m1 - mn1);
        m0 = mn0; m1 = mn1;

        float s0 = 0.0f, s1 = 0.0f;
#pragma unroll
        for (int nt = 0; nt < 8; nt++) {
            sacc[nt][0] = __expf(sacc[nt][0] - mn0); s0 += sacc[nt][0];
            sacc[nt][1] = __expf(sacc[nt][1] - mn0); s0 += sacc[nt][1];
            sacc[nt][2] = __expf(sacc[nt][2] - mn1); s1 += sacc[nt][2];
            sacc[nt][3] = __expf(sacc[nt][3] - mn1); s1 += sacc[nt][3];
        }
        s0 += __shfl_xor_sync(0xffffffffu, s0, 1);
        s0 += __shfl_xor_sync(0xffffffffu, s0, 2);
        s1 += __shfl_xor_sync(0xffffffffu, s1, 1);
        s1 += __shfl_xor_sync(0xffffffffu, s1, 2);
        l0 = l0 * al0 + s0;
        l1 = l1 * al1 + s1;

#pragma unroll
        for (int dt = 0; dt < 16; dt++) {
            o[dt][0] *= al0; o[dt][1] *= al0;
            o[dt][2] *= al1; o[dt][3] *= al1;
        }

#pragma unroll
        for (int t = 0; t < 4; t++) {
            uint32_t ph[4], pl[4];
#pragma unroll
            for (int q2 = 0; q2 < 2; q2++)
#pragma unroll
                for (int rr = 0; rr < 2; rr++) {
                    const float x = sacc[2 * t + q2][2 * rr];
                    const float y = sacc[2 * t + q2][2 * rr + 1];
                    __nv_bfloat16 bx = __float2bfloat16(x);
                    __nv_bfloat16 by = __float2bfloat16(y);
                    __nv_bfloat16 cx = __float2bfloat16(x - __bfloat162float(bx));
                    __nv_bfloat16 cy = __float2bfloat16(y - __bfloat162float(by));
                    ph[q2 * 2 + rr] = pack2(bx, by);
                    pl[q2 * 2 + rr] = pack2(cx, cy);
                }
#pragma unroll
            for (int dtp = 0; dtp < 8; dtp++) {
                const uint32_t bo = swzf((uint32_t)(t * 16 + (lane & 15)),
                                         (uint32_t)((2 * dtp + (lane >> 4)) * 16));
                uint32_t b4h[4], b4l[4];
                ldsm_x4t(sVh + bo, b4h);
                ldsm_x4t(sVl + bo, b4l);
                mma16816(o[2 * dtp],     ph, &b4h[0]);
                mma16816(o[2 * dtp],     ph, &b4l[0]);
                mma16816(o[2 * dtp],     pl, &b4h[0]);
                mma16816(o[2 * dtp + 1], ph, &b4h[2]);
                mma16816(o[2 * dtp + 1], ph, &b4l[2]);
                mma16816(o[2 * dtp + 1], pl, &b4h[2]);
            }
        }
        } // active
        __syncthreads();
    }

    // epilogue: normalize, convert to fp16, store
    const float inv0 = 1.0f / l0;
    const float inv1 = 1.0f / l1;
    const int srow0 = qt * 128 + w * 16 + lr;
    const size_t d0 = ((size_t)(b * S_ + srow0)) * D_ + h * HD_;
    const size_t d1 = ((size_t)(b * S_ + srow0 + 8)) * D_ + h * HD_;
#pragma unroll
    for (int dt = 0; dt < 16; dt++) {
        *(half2*)&AO16[d0 + dt * 8 + lc2] = __halves2half2(
            __float2half(o[dt][0] * inv0), __float2half(o[dt][1] * inv0));
        *(half2*)&AO16[d1 + dt * 8 + lc2] = __halves2half2(
            __float2half(o[dt][2] * inv1), __float2half(o[dt][3] * inv1));
    }
}

// ---------------------------------------------------------------------------
extern "C" void kernel_launch(void* const* d_in, const int* in_sizes, int n_in,
                              void* d_out, int out_size)
{
    (void)in_sizes; (void)n_in; (void)out_size;
    const float* x  = (const float*)d_in[0];
    const float* Wq = (const float*)d_in[2];
    const float* Wk = (const float*)d_in[3];
    const float* Wv = (const float*)d_in[4];
    const float* Wo = (const float*)d_in[5];
    float* out = (float*)d_out;

    __nv_bfloat16 *xhi, *xlo;
    __nv_bfloat16 *wqhi, *wqlo, *wkhi, *wklo, *wvhi, *wvlo;
    __nv_bfloat16 *qh, *ql, *kh, *kl, *vh, *vl;
    __half *wo16, *ao16;
    cudaGetSymbolAddress((void**)&xhi, g_xhi);
    cudaGetSymbolAddress((void**)&xlo, g_xlo);
    cudaGetSymbolAddress((void**)&wqhi, g_wqhi);
    cudaGetSymbolAddress((void**)&wqlo, g_wqlo);
    cudaGetSymbolAddress((void**)&wkhi, g_wkhi);
    cudaGetSymbolAddress((void**)&wklo, g_wklo);
    cudaGetSymbolAddress((void**)&wvhi, g_wvhi);
    cudaGetSymbolAddress((void**)&wvlo, g_wvlo);
    cudaGetSymbolAddress((void**)&wo16, g_wo16);
    cudaGetSymbolAddress((void**)&ao16, g_ao16);
    cudaGetSymbolAddress((void**)&qh, g_qh);
    cudaGetSymbolAddress((void**)&ql, g_ql);
    cudaGetSymbolAddress((void**)&kh, g_kh);
    cudaGetSymbolAddress((void**)&kl, g_kl);
    cudaGetSymbolAddress((void**)&vh, g_vh);
    cudaGetSymbolAddress((void**)&vl, g_vl);

    cudaFuncSetAttribute(sgemm_qkv,
                         cudaFuncAttributeMaxDynamicSharedMemorySize, TC_SMEM_BYTES);
    cudaFuncSetAttribute(sgemm_out_f16,
                         cudaFuncAttributeMaxDynamicSharedMemorySize, TC16_SMEM_BYTES);
    cudaFuncSetAttribute(flash_tc,
                         cudaFuncAttributeMaxDynamicSharedMemorySize, FL_SMEM);

    const int xn4 = (B_ * S_ * D_) / 4;
    const int wn4 = (D_ * D_) / 4;

    // launch order chosen so ncu (-s 5 -c 1) captures flash_tc (index 5)
    rope_table_kernel<<<(S_ * 64 + 255) / 256, 256>>>();              // 0
    split_bf16<<<(xn4 + 255) / 256, 256>>>(x, xhi, xlo, xn4);         // 1

    WSplitPtrs WS;
    WS.w[0] = Wq; WS.hi[0] = wqhi; WS.lo[0] = wqlo;
    WS.w[1] = Wk; WS.hi[1] = wkhi; WS.lo[1] = wklo;
    WS.w[2] = Wv; WS.hi[2] = wvhi; WS.lo[2] = wvlo;
    split_w3<<<dim3((wn4 + 255) / 256, 3), 256>>>(WS, wn4);           // 2
    split_wo_f16<<<(wn4 + 255) / 256, 256>>>(Wo, wo16, wn4);          // 3

    QKVPtrs P;
    P.bhi[0] = wqhi; P.blo[0] = wqlo; P.dhi[0] = qh; P.dlo[0] = ql;
    P.bhi[1] = wkhi; P.blo[1] = wklo; P.dhi[1] = kh; P.dlo[1] = kl;
    P.bhi[2] = wvhi; P.blo[2] = wvlo; P.dhi[2] = vh; P.dlo[2] = vl;
    dim3 qkvgrid(D_ / 128, (B_ * S_) / 128, 3);
    sgemm_qkv<<<qkvgrid, 256, TC_SMEM_BYTES>>>(xhi, xlo, P);          // 4

    flash_tc<<<dim3(S_ / 128, H_, B_), 256, FL_SMEM>>>(qh, ql, kh, kl, vh, vl,
                                                        ao16);        // 5 (ncu)

    dim3 ggrid(D_ / 128, (B_ * S_) / 128);
    sgemm_out_f16<<<ggrid, 256, TC16_SMEM_BYTES>>>(ao16, wo16, out);  // 6
}

// round 10
// speedup vs baseline: 1.8273x; 1.0763x over previous
#include <cuda_runtime.h>
#include <cuda_bf16.h>
#include <cuda_fp16.h>
#include <math.h>
#include <stdint.h>

#define B_ 2
#define S_ 2048
#define D_ 2048
#define H_ 16
#define HD_ 128

// ---------------- device scratch (no runtime allocation) ----------------
__device__ __nv_bfloat16 g_xhi[B_ * S_ * D_];
__device__ __nv_bfloat16 g_xlo[B_ * S_ * D_];
__device__ __nv_bfloat16 g_wqhi[D_ * D_], g_wqlo[D_ * D_];
__device__ __nv_bfloat16 g_wkhi[D_ * D_], g_wklo[D_ * D_];
__device__ __nv_bfloat16 g_wvhi[D_ * D_], g_wvlo[D_ * D_];
__device__ __half g_wo16[D_ * D_];
__device__ __half g_ao16[B_ * S_ * D_];

// attention operands (head layout [b][h][s][hd])
__device__ __nv_bfloat16 g_qh[B_ * H_ * S_ * HD_], g_ql[B_ * H_ * S_ * HD_];
__device__ __nv_bfloat16 g_kh[B_ * H_ * S_ * HD_], g_kl[B_ * H_ * S_ * HD_];
__device__ __half g_v16[B_ * H_ * S_ * HD_];

__device__ float g_cos[S_ * 64];
__device__ float g_sin[S_ * 64];

// ---------------- helpers ----------------
__device__ __forceinline__ uint32_t smem_u32(const void* p) {
    uint32_t a;
    asm("{ .reg .u64 t; cvta.to.shared.u64 t, %1; cvt.u32.u64 %0, t; }"
        : "=r"(a) : "l"(p));
    return a;
}
static __device__ __forceinline__ uint32_t swz128(uint32_t o) {
    return o ^ ((o >> 3) & 0x70);
}
static __device__ __forceinline__ uint32_t swzf(uint32_t row, uint32_t colbyte) {
    return row * 256u + (colbyte ^ ((row & 7u) << 4));
}
__device__ __forceinline__ void cp16(uint32_t saddr, const void* gptr) {
    asm volatile("cp.async.cg.shared.global [%0], [%1], 16;"
                 :: "r"(saddr), "l"(gptr) : "memory");
}
#define CP_COMMIT() asm volatile("cp.async.commit_group;" ::: "memory")

__device__ __forceinline__ void ldsm_x4(uint32_t a, uint32_t* r) {
    asm volatile("ldmatrix.sync.aligned.m8n8.x4.shared.b16 {%0,%1,%2,%3}, [%4];"
                 : "=r"(r[0]), "=r"(r[1]), "=r"(r[2]), "=r"(r[3]) : "r"(a));
}
__device__ __forceinline__ void ldsm_x4t(uint32_t a, uint32_t* r) {
    asm volatile("ldmatrix.sync.aligned.m8n8.x4.trans.shared.b16 {%0,%1,%2,%3}, [%4];"
                 : "=r"(r[0]), "=r"(r[1]), "=r"(r[2]), "=r"(r[3]) : "r"(a));
}
__device__ __forceinline__ void mma16816(float* d, const uint32_t* a, const uint32_t* b) {
    asm volatile(
        "mma.sync.aligned.m16n8k16.row.col.f32.bf16.bf16.f32 "
        "{%0,%1,%2,%3}, {%4,%5,%6,%7}, {%8,%9}, {%0,%1,%2,%3};"
        : "+f"(d[0]), "+f"(d[1]), "+f"(d[2]), "+f"(d[3])
        : "r"(a[0]), "r"(a[1]), "r"(a[2]), "r"(a[3]), "r"(b[0]), "r"(b[1]));
}
__device__ __forceinline__ void mma16816h(float* d, const uint32_t* a, const uint32_t* b) {
    asm volatile(
        "mma.sync.aligned.m16n8k16.row.col.f32.f16.f16.f32 "
        "{%0,%1,%2,%3}, {%4,%5,%6,%7}, {%8,%9}, {%0,%1,%2,%3};"
        : "+f"(d[0]), "+f"(d[1]), "+f"(d[2]), "+f"(d[3])
        : "r"(a[0]), "r"(a[1]), "r"(a[2]), "r"(a[3]), "r"(b[0]), "r"(b[1]));
}
__device__ __forceinline__ uint32_t packh2(float x, float y) {
    half2 t = __floats2half2_rn(x, y);
    return *(uint32_t*)&t;
}
__device__ __forceinline__ void split1(float x, __nv_bfloat16& h, __nv_bfloat16& l) {
    h = __float2bfloat16(x);
    l = __float2bfloat16(x - __bfloat162float(h));
}

// ---------------------------------------------------------------------------
// RoPE tables (once; double math)
// ---------------------------------------------------------------------------
__global__ void rope_table_kernel()
{
    int idx = blockIdx.x * blockDim.x + threadIdx.x;
    if (idx >= S_ * 64) return;
    const int i = idx & 63;
    const int s = idx >> 6;
    const float inv_freq = (float)pow(10000.0, -(double)i * (1.0 / 64.0));
    const double ang = (double)s * (double)inv_freq;
    double sd, cd;
    sincos(ang, &sd, &cd);
    g_cos[idx] = (float)cd;
    g_sin[idx] = (float)sd;
}

// ---------------------------------------------------------------------------
// Split fp32 -> bf16 hi/lo (x input)
// ---------------------------------------------------------------------------
__global__ void split_bf16(const float* __restrict__ in,
                           __nv_bfloat16* __restrict__ hi,
                           __nv_bfloat16* __restrict__ lo, int n4)
{
    int i = blockIdx.x * blockDim.x + threadIdx.x;
    if (i >= n4) return;
    float4 v = ((const float4*)in)[i];
    __nv_bfloat16 h0, h1, h2, h3, l0, l1, l2, l3;
    split1(v.x, h0, l0); split1(v.y, h1, l1);
    split1(v.z, h2, l2); split1(v.w, h3, l3);
    __nv_bfloat162* hi2 = (__nv_bfloat162*)hi;
    __nv_bfloat162* lo2 = (__nv_bfloat162*)lo;
    hi2[2 * i]     = __nv_bfloat162(h0, h1);
    hi2[2 * i + 1] = __nv_bfloat162(h2, h3);
    lo2[2 * i]     = __nv_bfloat162(l0, l1);
    lo2[2 * i + 1] = __nv_bfloat162(l2, l3);
}

// Batched: split Wq/Wk/Wv (z = 0..2) to bf16 hi/lo
struct WSplitPtrs {
    const float* w[3];
    __nv_bfloat16* hi[3];
    __nv_bfloat16* lo[3];
};
__global__ void split_w3(WSplitPtrs P, int n4)
{
    int i = blockIdx.x * blockDim.x + threadIdx.x;
    if (i >= n4) return;
    const int z = blockIdx.y;
    float4 v = ((const float4*)P.w[z])[i];
    __nv_bfloat16 h0, h1, h2, h3, l0, l1, l2, l3;
    split1(v.x, h0, l0); split1(v.y, h1, l1);
    split1(v.z, h2, l2); split1(v.w, h3, l3);
    __nv_bfloat162* hi2 = (__nv_bfloat162*)P.hi[z];
    __nv_bfloat162* lo2 = (__nv_bfloat162*)P.lo[z];
    hi2[2 * i]     = __nv_bfloat162(h0, h1);
    hi2[2 * i + 1] = __nv_bfloat162(h2, h3);
    lo2[2 * i]     = __nv_bfloat162(l0, l1);
    lo2[2 * i + 1] = __nv_bfloat162(l2, l3);
}

// Wo: fp32 -> fp16 (single limb)
__global__ void split_wo_f16(const float* __restrict__ in, __half* __restrict__ o, int n4)
{
    int i = blockIdx.x * blockDim.x + threadIdx.x;
    if (i >= n4) return;
    float4 v = ((const float4*)in)[i];
    half2* o2 = (half2*)o;
    o2[2 * i]     = __floats2half2_rn(v.x, v.y);
    o2[2 * i + 1] = __floats2half2_rn(v.z, v.w);
}

// ---------------------------------------------------------------------------
// Merged QKV GEMM (bf16 3-product), fused epilogue:
//   z=0: rope+scale -> bf16 hi/lo (Q)
//   z=1: rope       -> bf16 hi/lo (K)
//   z=2: identity   -> fp16 single (V)
// ---------------------------------------------------------------------------
#define TCT16 16384u
#define TCBUF (4u * TCT16)
#define TC_SMEM_BYTES (3u * TCBUF)

struct QKVPtrs {
    const __nv_bfloat16* bhi[3];
    const __nv_bfloat16* blo[3];
    __nv_bfloat16* dhi[2];
    __nv_bfloat16* dlo[2];
    __half* d16;            // V destination
};

__global__ void __launch_bounds__(256, 1)
sgemm_qkv(const __nv_bfloat16* __restrict__ Ahi, const __nv_bfloat16* __restrict__ Alo,
          QKVPtrs P)
{
    extern __shared__ char smem[];
    const uint32_t sbase = smem_u32(smem);

    const int z = blockIdx.z;
    const __nv_bfloat16* __restrict__ Bhi = P.bhi[z];
    const __nv_bfloat16* __restrict__ Blo = P.blo[z];

    const int tid  = threadIdx.x;
    const int lane = tid & 31;
    const int w    = tid >> 5;
    const int m0w  = (w >> 2) * 64;
    const int n0w  = (w & 3) * 32;

    const int m0 = blockIdx.y * 128;
    const int n0 = blockIdx.x * 128;
    const int h  = blockIdx.x;

    uint32_t swofs[4];
#pragma unroll
    for (int t = 0; t < 4; t++) {
        const int u = tid + (t << 8);
        swofs[t] = swz128((uint32_t)((u >> 3) * 128 + (u & 7) * 16));
    }

    float acc[4][4][4];
#pragma unroll
    for (int i = 0; i < 4; i++)
#pragma unroll
        for (int j = 0; j < 4; j++)
#pragma unroll
            for (int r = 0; r < 4; r++) acc[i][j][r] = 0.0f;

    const uint32_t arow = (uint32_t)(m0w + (lane & 15));
    const uint32_t acol = (uint32_t)((lane >> 4) << 4);
    const uint32_t browx = (uint32_t)(n0w + (lane & 7) + ((lane >> 4) << 3));
    const uint32_t bcol  = (uint32_t)(((lane >> 3) & 1) << 4);

#define LOAD_CHUNK(c, buf)                                                     \
    {                                                                          \
        const uint32_t bofs = sbase + (uint32_t)(buf) * TCBUF;                 \
        const int k0 = (c) * 64;                                               \
        _Pragma("unroll")                                                      \
        for (int t = 0; t < 4; t++) {                                          \
            const int u = tid + (t << 8);                                      \
            const int r = u >> 3;                                              \
            const int c16 = u & 7;                                             \
            const size_t ga = (size_t)(m0 + r) * D_ + k0 + c16 * 8;            \
            const size_t gb = (size_t)(n0 + r) * D_ + k0 + c16 * 8;            \
            cp16(bofs + 0u * TCT16 + swofs[t], Ahi + ga);                      \
            cp16(bofs + 1u * TCT16 + swofs[t], Alo + ga);                      \
            cp16(bofs + 2u * TCT16 + swofs[t], Bhi + gb);                      \
            cp16(bofs + 3u * TCT16 + swofs[t], Blo + gb);                      \
        }                                                                      \
        CP_COMMIT();                                                           \
    }

    LOAD_CHUNK(0, 0);
    LOAD_CHUNK(1, 1);

    int buf = 0;
    for (int c = 0; c < 32; c++) {
        if (c < 31) {
            asm volatile("cp.async.wait_group 1;" ::: "memory");
        } else {
            asm volatile("cp.async.wait_group 0;" ::: "memory");
        }
        __syncthreads();
        if (c + 2 < 32) {
            const int nb = (buf + 2 >= 3) ? buf - 1 : buf + 2;
            LOAD_CHUNK(c + 2, nb);
        }

        const uint32_t bofs = sbase + (uint32_t)buf * TCBUF;
        const uint32_t Ab_hi = bofs + 0u * TCT16;
        const uint32_t Ab_lo = bofs + 1u * TCT16;
        const uint32_t Bb_hi = bofs + 2u * TCT16;
        const uint32_t Bb_lo = bofs + 3u * TCT16;

#pragma unroll
        for (int kk = 0; kk < 4; kk++) {
            uint32_t ah[4][4], al[4][4], bh[4][2], bl[4][2];
            const uint32_t kb = (uint32_t)(kk * 32);
#pragma unroll
            for (int mt = 0; mt < 4; mt++) {
                const uint32_t ofs = swz128((arow + mt * 16u) * 128u + acol + kb);
                ldsm_x4(Ab_hi + ofs, ah[mt]);
                ldsm_x4(Ab_lo + ofs, al[mt]);
            }
#pragma unroll
            for (int ntp = 0; ntp < 2; ntp++) {
                const uint32_t ofs = swz128((browx + ntp * 16u) * 128u + bcol + kb);
                uint32_t b4h[4], b4l[4];
                ldsm_x4(Bb_hi + ofs, b4h);
                ldsm_x4(Bb_lo + ofs, b4l);
                bh[2 * ntp][0] = b4h[0];     bh[2 * ntp][1] = b4h[1];
                bh[2 * ntp + 1][0] = b4h[2]; bh[2 * ntp + 1][1] = b4h[3];
                bl[2 * ntp][0] = b4l[0];     bl[2 * ntp][1] = b4l[1];
                bl[2 * ntp + 1][0] = b4l[2]; bl[2 * ntp + 1][1] = b4l[3];
            }
#pragma unroll
            for (int mt = 0; mt < 4; mt++)
#pragma unroll
                for (int nt = 0; nt < 4; nt++) {
                    mma16816(acc[mt][nt], ah[mt], bh[nt]);
                    mma16816(acc[mt][nt], ah[mt], bl[nt]);
                    mma16816(acc[mt][nt], al[mt], bh[nt]);
                }
        }
        __syncthreads();
        buf = (buf + 1 >= 3) ? 0 : buf + 1;
    }

    // ---- epilogue: stage fp32 tile, rope/identity, emit operands ----
    float* Cs = (float*)smem;
    const int lr = lane >> 2;
    const int lc = (lane & 3) * 2;
#pragma unroll
    for (int mt = 0; mt < 4; mt++)
#pragma unroll
        for (int rr = 0; rr < 2; rr++) {
            const int rloc = m0w + mt * 16 + rr * 8 + lr;
            const int e = rr * 2;
#pragma unroll
            for (int nt = 0; nt < 4; nt++) {
                const int nloc = n0w + nt * 8 + lc;
                *(float2*)&Cs[rloc * 132 + nloc] =
                    make_float2(acc[mt][nt][e], acc[mt][nt][e + 1]);
            }
        }
    __syncthreads();

    if (z == 2) {
        // V: identity, fp16 single
        __half* __restrict__ D16 = P.d16;
        for (int i = tid; i < 128 * 32; i += 256) {
            const int r  = i >> 5;
            const int c0 = (i & 31) * 2;
            const int m  = m0 + r;
            const int s  = m & (S_ - 1);
            const int bb = m >> 11;
            const float2 v1 = *(float2*)&Cs[r * 132 + c0];
            const float2 v2 = *(float2*)&Cs[r * 132 + c0 + 64];
            const size_t base = ((size_t)(bb * H_ + h) * S_ + s) * HD_;
            *(half2*)&D16[base + c0]      = __floats2half2_rn(v1.x, v1.y);
            *(half2*)&D16[base + c0 + 64] = __floats2half2_rn(v2.x, v2.y);
        }
        return;
    }

    __nv_bfloat16* __restrict__ Dhi = P.dhi[z];
    __nv_bfloat16* __restrict__ Dlo = P.dlo[z];
    const float scq = (z == 0) ? 0.08838834764831845f : 1.0f;
    for (int i = tid; i < 128 * 32; i += 256) {
        const int r  = i >> 5;
        const int c0 = (i & 31) * 2;
        const int m  = m0 + r;
        const int s  = m & (S_ - 1);
        const int bb = m >> 11;
        const float2 v1 = *(float2*)&Cs[r * 132 + c0];
        const float2 v2 = *(float2*)&Cs[r * 132 + c0 + 64];
        const int ti = (s << 6) + c0;
        const float c_0 = g_cos[ti],     s_0 = g_sin[ti];
        const float c_1 = g_cos[ti + 1], s_1 = g_sin[ti + 1];
        const float o1_0 = (v1.x * c_0 - v2.x * s_0) * scq;
        const float o1_1 = (v1.y * c_1 - v2.y * s_1) * scq;
        const float o2_0 = (v1.x * s_0 + v2.x * c_0) * scq;
        const float o2_1 = (v1.y * s_1 + v2.y * c_1) * scq;

        __nv_bfloat16 h0, l0, h1, l1, h2, l2, h3, l3;
        split1(o1_0, h0, l0); split1(o1_1, h1, l1);
        split1(o2_0, h2, l2); split1(o2_1, h3, l3);

        const size_t base = ((size_t)(bb * H_ + h) * S_ + s) * HD_;
        *(__nv_bfloat162*)&Dhi[base + c0]      = __nv_bfloat162(h0, h1);
        *(__nv_bfloat162*)&Dlo[base + c0]      = __nv_bfloat162(l0, l1);
        *(__nv_bfloat162*)&Dhi[base + c0 + 64] = __nv_bfloat162(h2, h3);
        *(__nv_bfloat162*)&Dlo[base + c0 + 64] = __nv_bfloat162(l2, l3);
    }
}

// ---------------------------------------------------------------------------
// Output projection: pure fp16 single-product GEMM (R9 kernel, verified).
// ---------------------------------------------------------------------------
#define TCBUF16 (2u * TCT16)
#define TC16_SMEM_BYTES (3u * TCBUF16)

__global__ void __launch_bounds__(256)
sgemm_out_f16(const __half* __restrict__ A16, const __half* __restrict__ B16,
              float* __restrict__ C)
{
    extern __shared__ char smem[];
    const uint32_t sbase = smem_u32(smem);

    const int tid  = threadIdx.x;
    const int lane = tid & 31;
    const int w    = tid >> 5;
    const int m0w  = (w >> 2) * 64;
    const int n0w  = (w & 3) * 32;

    const int m0 = blockIdx.y * 128;
    const int n0 = blockIdx.x * 128;

    uint32_t swofs[4];
#pragma unroll
    for (int t = 0; t < 4; t++) {
        const int u = tid + (t << 8);
        swofs[t] = swz128((uint32_t)((u >> 3) * 128 + (u & 7) * 16));
    }

    float acc[4][4][4];
#pragma unroll
    for (int i = 0; i < 4; i++)
#pragma unroll
        for (int j = 0; j < 4; j++)
#pragma unroll
            for (int r = 0; r < 4; r++) acc[i][j][r] = 0.0f;

    const uint32_t arow = (uint32_t)(m0w + (lane & 15));
    const uint32_t acol = (uint32_t)((lane >> 4) << 4);
    const uint32_t browx = (uint32_t)(n0w + (lane & 7) + ((lane >> 4) << 3));
    const uint32_t bcol  = (uint32_t)(((lane >> 3) & 1) << 4);

#define LOAD_CHUNK16(c, buf)                                                   \
    {                                                                          \
        const uint32_t bofs = sbase + (uint32_t)(buf) * TCBUF16;               \
        const int k0 = (c) * 64;                                               \
        _Pragma("unroll")                                                      \
        for (int t = 0; t < 4; t++) {                                          \
            const int u = tid + (t << 8);                                      \
            const int r = u >> 3;                                              \
            const int c16 = u & 7;                                             \
            const size_t ga = (size_t)(m0 + r) * D_ + k0 + c16 * 8;            \
            const size_t gb = (size_t)(n0 + r) * D_ + k0 + c16 * 8;            \
            cp16(bofs + 0u * TCT16 + swofs[t], A16 + ga);                      \
            cp16(bofs + 1u * TCT16 + swofs[t], B16 + gb);                      \
        }                                                                      \
        CP_COMMIT();                                                           \
    }

    LOAD_CHUNK16(0, 0);
    LOAD_CHUNK16(1, 1);

    int buf = 0;
    for (int c = 0; c < 32; c++) {
        if (c < 31) {
            asm volatile("cp.async.wait_group 1;" ::: "memory");
        } else {
            asm volatile("cp.async.wait_group 0;" ::: "memory");
        }
        __syncthreads();
        if (c + 2 < 32) {
            const int nb = (buf + 2 >= 3) ? buf - 1 : buf + 2;
            LOAD_CHUNK16(c + 2, nb);
        }

        const uint32_t bofs = sbase + (uint32_t)buf * TCBUF16;
        const uint32_t Ab = bofs + 0u * TCT16;
        const uint32_t Bb = bofs + 1u * TCT16;

#pragma unroll
        for (int kk = 0; kk < 4; kk++) {
            uint32_t ah[4][4], bh[4][2];
            const uint32_t kb = (uint32_t)(kk * 32);
#pragma unroll
            for (int mt = 0; mt < 4; mt++) {
                const uint32_t ofs = swz128((arow + mt * 16u) * 128u + acol + kb);
                ldsm_x4(Ab + ofs, ah[mt]);
            }
#pragma unroll
            for (int ntp = 0; ntp < 2; ntp++) {
                const uint32_t ofs = swz128((browx + ntp * 16u) * 128u + bcol + kb);
                uint32_t b4[4];
                ldsm_x4(Bb + ofs, b4);
                bh[2 * ntp][0] = b4[0];     bh[2 * ntp][1] = b4[1];
                bh[2 * ntp + 1][0] = b4[2]; bh[2 * ntp + 1][1] = b4[3];
            }
#pragma unroll
            for (int mt = 0; mt < 4; mt++)
#pragma unroll
                for (int nt = 0; nt < 4; nt++)
                    mma16816h(acc[mt][nt], ah[mt], bh[nt]);
        }
        __syncthreads();
        buf = (buf + 1 >= 3) ? 0 : buf + 1;
    }

    const int lr = lane >> 2;
    const int lc = (lane & 3) * 2;
#pragma unroll
    for (int mt = 0; mt < 4; mt++) {
#pragma unroll
        for (int rr = 0; rr < 2; rr++) {
            const int m = m0 + m0w + mt * 16 + rr * 8 + lr;
            const int e = rr * 2;
            const size_t dstbase = (size_t)m * D_;
#pragma unroll
            for (int nt = 0; nt < 4; nt++) {
                const int n = n0 + n0w + nt * 8 + lc;
                *(float2*)&C[dstbase + n] =
                    make_float2(acc[mt][nt][e], acc[mt][nt][e + 1]);
            }
        }
    }
}

// ---------------------------------------------------------------------------
// Tensor-core flash attention (causal): QK bf16 3-product, PV fp16 1-product.
// smem: Qhi/Qlo 32KB each; 2 stages x {Khi 16K, Klo 16K, V16 16K} = 96KB.
// ---------------------------------------------------------------------------
#define KVSTAGE 49152u
#define FL_SMEM (65536 + 2 * KVSTAGE)

__global__ void __launch_bounds__(256, 1)
flash_tc(const __nv_bfloat16* __restrict__ Qhi, const __nv_bfloat16* __restrict__ Qlo,
         const __nv_bfloat16* __restrict__ Khi, const __nv_bfloat16* __restrict__ Klo,
         const __half* __restrict__ V16,
         __half* __restrict__ AO16)
{
    extern __shared__ char smem[];
    const uint32_t sb = smem_u32(smem);
    const uint32_t sQh = sb;
    const uint32_t sQl = sb + 32768u;

    const int tid  = threadIdx.x;
    const int lane = tid & 31;
    const int w    = tid >> 5;
    const int lr   = lane >> 2;
    const int lc2  = (lane & 3) * 2;

    const int qt = (int)gridDim.x - 1 - (int)blockIdx.x;
    const int h  = blockIdx.y;
    const int b  = blockIdx.z;
    const size_t bh = ((size_t)(b * H_ + h)) * S_ * HD_;

    const __nv_bfloat16* Qhg = Qhi + bh + (size_t)qt * 128 * HD_;
    const __nv_bfloat16* Qlg = Qlo + bh + (size_t)qt * 128 * HD_;

    for (int i = tid; i < 2048; i += 256) {
        const uint32_t r = (uint32_t)(i >> 4);
        const uint32_t cb = (uint32_t)((i & 15) << 4);
        const uint32_t so = swzf(r, cb);
        cp16(sQh + so, Qhg + (size_t)r * HD_ + (i & 15) * 8);
        cp16(sQl + so, Qlg + (size_t)r * HD_ + (i & 15) * 8);
    }

#define LOAD_KV(jj, buf)                                                       \
    {                                                                          \
        const uint32_t kvb = sb + 65536u + (uint32_t)(buf) * KVSTAGE;          \
        const size_t rg0 = (size_t)(jj) * 64;                                  \
        for (int i = tid; i < 1024; i += 256) {                                \
            const uint32_t r = (uint32_t)(i >> 4);                             \
            const uint32_t cb = (uint32_t)((i & 15) << 4);                     \
            const uint32_t so = swzf(r, cb);                                   \
            const size_t g = bh + (rg0 + r) * HD_ + (i & 15) * 8;              \
            cp16(kvb + so, Khi + g);                                           \
            cp16(kvb + 16384u + so, Klo + g);                                  \
            cp16(kvb + 32768u + so, V16 + g);                                  \
        }                                                                      \
    }

    LOAD_KV(0, 0);
    CP_COMMIT();

    float o[16][4];
#pragma unroll
    for (int i = 0; i < 16; i++)
#pragma unroll
        for (int e = 0; e < 4; e++) o[i][e] = 0.0f;
    float m0 = -1e30f, m1 = -1e30f, l0 = 0.0f, l1 = 0.0f;

    const int jmax = 2 * qt + 1;
    const int rbase = qt * 128 + w * 16 + lr;

    const uint32_t krowx = (uint32_t)((lane & 7) + ((lane >> 4) << 3));
    const uint32_t kcolx = (uint32_t)(((lane >> 3) & 1) << 4);

    for (int j = 0; j <= jmax; j++) {
        if (j < jmax) {
            LOAD_KV(j + 1, (j + 1) & 1);
            CP_COMMIT();
            asm volatile("cp.async.wait_group 1;" ::: "memory");
        } else {
            asm volatile("cp.async.wait_group 0;" ::: "memory");
        }
        __syncthreads();

        const bool active = !(j == jmax && w < 4);
        if (active) {
        const uint32_t kvb = sb + 65536u + (uint32_t)(j & 1) * KVSTAGE;
        const uint32_t sKh = kvb;
        const uint32_t sKl = kvb + 16384u;
        const uint32_t sV  = kvb + 32768u;

        float sacc[8][4];
#pragma unroll
        for (int nt = 0; nt < 8; nt++)
#pragma unroll
            for (int e = 0; e < 4; e++) sacc[nt][e] = 0.0f;

#pragma unroll
        for (int kc = 0; kc < 8; kc++) {
            const uint32_t ao_ = swzf((uint32_t)(w * 16 + (lane & 15)),
                                      (uint32_t)(kc * 32 + ((lane >> 4) << 4)));
            uint32_t ah[4], al[4];
            ldsm_x4(sQh + ao_, ah);
            ldsm_x4(sQl + ao_, al);
#pragma unroll
            for (int ntp = 0; ntp < 4; ntp++) {
                const uint32_t bo = swzf(krowx + ntp * 16u,
                                         (uint32_t)(kc * 32) + kcolx);
                uint32_t b4h[4], b4l[4];
                ldsm_x4(sKh + bo, b4h);
                ldsm_x4(sKl + bo, b4l);
                mma16816(sacc[2 * ntp],     ah, &b4h[0]);
                mma16816(sacc[2 * ntp],     ah, &b4l[0]);
                mma16816(sacc[2 * ntp],     al, &b4h[0]);
                mma16816(sacc[2 * ntp + 1], ah, &b4h[2]);
                mma16816(sacc[2 * ntp + 1], ah, &b4l[2]);
                mma16816(sacc[2 * ntp + 1], al, &b4h[2]);
            }
        }

        if (j >= 2 * qt) {
            const int cb0 = j * 64 + lc2;
#pragma unroll
            for (int nt = 0; nt < 8; nt++)
#pragma unroll
                for (int e = 0; e < 4; e++) {
                    const int col = cb0 + nt * 8 + (e & 1);
                    const int row = rbase + 8 * (e >> 1);
                    if (col > row) sacc[nt][e] = -1e30f;
                }
        }

        float mx0 = -1e30f, mx1 = -1e30f;
#pragma unroll
        for (int nt = 0; nt < 8; nt++) {
            mx0 = fmaxf(mx0, fmaxf(sacc[nt][0], sacc[nt][1]));
            mx1 = fmaxf(mx1, fmaxf(sacc[nt][2], sacc[nt][3]));
        }
        mx0 = fmaxf(mx0, __shfl_xor_sync(0xffffffffu, mx0, 1));
        mx0 = fmaxf(mx0, __shfl_xor_sync(0xffffffffu, mx0, 2));
        mx1 = fmaxf(mx1, __shfl_xor_sync(0xffffffffu, mx1, 1));
        mx1 = fmaxf(mx1, __shfl_xor_sync(0xffffffffu, mx1, 2));

        const float mn0 = fmaxf(m0, mx0);
        const float mn1 = fmaxf(m1, mx1);
        const float al0 = __expf(m0 - mn0);
        const float al1 = __expf(m1 - mn1);
        m0 = mn0; m1 = mn1;

        float s0 = 0.0f, s1 = 0.0f;
#pragma unroll
        for (int nt = 0; nt < 8; nt++) {
            sacc[nt][0] = __expf(sacc[nt][0] - mn0); s0 += sacc[nt][0];
            sacc[nt][1] = __expf(sacc[nt][1] - mn0); s0 += sacc[nt][1];
            sacc[nt][2] = __expf(sacc[nt][2] - mn1); s1 += sacc[nt][2];
            sacc[nt][3] = __expf(sacc[nt][3] - mn1); s1 += sacc[nt][3];
        }
        s0 += __shfl_xor_sync(0xffffffffu, s0, 1);
        s0 += __shfl_xor_sync(0xffffffffu, s0, 2);
        s1 += __shfl_xor_sync(0xffffffffu, s1, 1);
        s1 += __shfl_xor_sync(0xffffffffu, s1, 2);
        l0 = l0 * al0 + s0;
        l1 = l1 * al1 + s1;

#pragma unroll
        for (int dt = 0; dt < 16; dt++) {
            o[dt][0] *= al0; o[dt][1] *= al0;
            o[dt][2] *= al1; o[dt][3] *= al1;
        }

        // ---- O += P V  (P fp16 1-product) ----
#pragma unroll
        for (int t = 0; t < 4; t++) {
            uint32_t ph[4];
#pragma unroll
            for (int q2 = 0; q2 < 2; q2++)
#pragma unroll
                for (int rr = 0; rr < 2; rr++)
                    ph[q2 * 2 + rr] = packh2(sacc[2 * t + q2][2 * rr],
                                             sacc[2 * t + q2][2 * rr + 1]);
#pragma unroll
            for (int dtp = 0; dtp < 8; dtp++) {
                const uint32_t bo = swzf((uint32_t)(t * 16 + (lane & 15)),
                                         (uint32_t)((2 * dtp + (lane >> 4)) * 16));
                uint32_t b4[4];
                ldsm_x4t(sV + bo, b4);
                mma16816h(o[2 * dtp],     ph, &b4[0]);
                mma16816h(o[2 * dtp + 1], ph, &b4[2]);
            }
        }
        } // active
        __syncthreads();
    }

    const float inv0 = 1.0f / l0;
    const float inv1 = 1.0f / l1;
    const int srow0 = qt * 128 + w * 16 + lr;
    const size_t d0 = ((size_t)(b * S_ + srow0)) * D_ + h * HD_;
    const size_t d1 = ((size_t)(b * S_ + srow0 + 8)) * D_ + h * HD_;
#pragma unroll
    for (int dt = 0; dt < 16; dt++) {
        *(half2*)&AO16[d0 + dt * 8 + lc2] =
            __floats2half2_rn(o[dt][0] * inv0, o[dt][1] * inv0);
        *(half2*)&AO16[d1 + dt * 8 + lc2] =
            __floats2half2_rn(o[dt][2] * inv1, o[dt][3] * inv1);
    }
}

// ---------------------------------------------------------------------------
extern "C" void kernel_launch(void* const* d_in, const int* in_sizes, int n_in,
                              void* d_out, int out_size)
{
    (void)in_sizes; (void)n_in; (void)out_size;
    const float* x  = (const float*)d_in[0];
    const float* Wq = (const float*)d_in[2];
    const float* Wk = (const float*)d_in[3];
    const float* Wv = (const float*)d_in[4];
    const float* Wo = (const float*)d_in[5];
    float* out = (float*)d_out;

    __nv_bfloat16 *xhi, *xlo;
    __nv_bfloat16 *wqhi, *wqlo, *wkhi, *wklo, *wvhi, *wvlo;
    __nv_bfloat16 *qh, *ql, *kh, *kl;
    __half *wo16, *ao16, *v16;
    cudaGetSymbolAddress((void**)&xhi, g_xhi);
    cudaGetSymbolAddress((void**)&xlo, g_xlo);
    cudaGetSymbolAddress((void**)&wqhi, g_wqhi);
    cudaGetSymbolAddress((void**)&wqlo, g_wqlo);
    cudaGetSymbolAddress((void**)&wkhi, g_wkhi);
    cudaGetSymbolAddress((void**)&wklo, g_wklo);
    cudaGetSymbolAddress((void**)&wvhi, g_wvhi);
    cudaGetSymbolAddress((void**)&wvlo, g_wvlo);
    cudaGetSymbolAddress((void**)&wo16, g_wo16);
    cudaGetSymbolAddress((void**)&ao16, g_ao16);
    cudaGetSymbolAddress((void**)&v16, g_v16);
    cudaGetSymbolAddress((void**)&qh, g_qh);
    cudaGetSymbolAddress((void**)&ql, g_ql);
    cudaGetSymbolAddress((void**)&kh, g_kh);
    cudaGetSymbolAddress((void**)&kl, g_kl);

    cudaFuncSetAttribute(sgemm_qkv,
                         cudaFuncAttributeMaxDynamicSharedMemorySize, TC_SMEM_BYTES);
    cudaFuncSetAttribute(sgemm_out_f16,
                         cudaFuncAttributeMaxDynamicSharedMemorySize, TC16_SMEM_BYTES);
    cudaFuncSetAttribute(flash_tc,
                         cudaFuncAttributeMaxDynamicSharedMemorySize, FL_SMEM);

    const int xn4 = (B_ * S_ * D_) / 4;
    const int wn4 = (D_ * D_) / 4;

    rope_table_kernel<<<(S_ * 64 + 255) / 256, 256>>>();              // 0
    split_bf16<<<(xn4 + 255) / 256, 256>>>(x, xhi, xlo, xn4);         // 1

    WSplitPtrs WS;
    WS.w[0] = Wq; WS.hi[0] = wqhi; WS.lo[0] = wqlo;
    WS.w[1] = Wk; WS.hi[1] = wkhi; WS.lo[1] = wklo;
    WS.w[2] = Wv; WS.hi[2] = wvhi; WS.lo[2] = wvlo;
    split_w3<<<dim3((wn4 + 255) / 256, 3), 256>>>(WS, wn4);           // 2
    split_wo_f16<<<(wn4 + 255) / 256, 256>>>(Wo, wo16, wn4);          // 3

    QKVPtrs P;
    P.bhi[0] = wqhi; P.blo[0] = wqlo; P.dhi[0] = qh; P.dlo[0] = ql;
    P.bhi[1] = wkhi; P.blo[1] = wklo; P.dhi[1] = kh; P.dlo[1] = kl;
    P.bhi[2] = wvhi; P.blo[2] = wvlo; P.d16 = v16;
    dim3 qkvgrid(D_ / 128, (B_ * S_) / 128, 3);
    sgemm_qkv<<<qkvgrid, 256, TC_SMEM_BYTES>>>(xhi, xlo, P);          // 4

    flash_tc<<<dim3(S_ / 128, H_, B_), 256, FL_SMEM>>>(qh, ql, kh, kl, v16,
                                                        ao16);        // 5 (ncu)

    dim3 ggrid(D_ / 128, (B_ * S_) / 128);
    sgemm_out_f16<<<ggrid, 256, TC16_SMEM_BYTES>>>(ao16, wo16, out);  // 6
}

// round 11
// speedup vs baseline: 2.0683x; 1.1319x over previous
#include <cuda_runtime.h>
#include <cuda_bf16.h>
#include <cuda_fp16.h>
#include <math.h>
#include <stdint.h>

#define B_ 2
#define S_ 2048
#define D_ 2048
#define H_ 16
#define HD_ 128

// ---------------- device scratch (no runtime allocation) ----------------
__device__ __nv_bfloat16 g_xhi[B_ * S_ * D_];
__device__ __nv_bfloat16 g_xlo[B_ * S_ * D_];
__device__ __half g_x16[B_ * S_ * D_];
__device__ __nv_bfloat16 g_wqhi[D_ * D_], g_wqlo[D_ * D_];
__device__ __nv_bfloat16 g_wkhi[D_ * D_], g_wklo[D_ * D_];
__device__ __half g_wv16[D_ * D_];
__device__ __half g_wo16[D_ * D_];
__device__ __half g_ao16[B_ * S_ * D_];

// attention operands (head layout [b][h][s][hd])
__device__ __nv_bfloat16 g_qh[B_ * H_ * S_ * HD_], g_ql[B_ * H_ * S_ * HD_];
__device__ __nv_bfloat16 g_kh[B_ * H_ * S_ * HD_], g_kl[B_ * H_ * S_ * HD_];
__device__ __half g_v16[B_ * H_ * S_ * HD_];

__device__ float g_cos[S_ * 64];
__device__ float g_sin[S_ * 64];

// ---------------- helpers ----------------
__device__ __forceinline__ uint32_t smem_u32(const void* p) {
    uint32_t a;
    asm("{ .reg .u64 t; cvta.to.shared.u64 t, %1; cvt.u32.u64 %0, t; }"
        : "=r"(a) : "l"(p));
    return a;
}
static __device__ __forceinline__ uint32_t swz128(uint32_t o) {
    return o ^ ((o >> 3) & 0x70);
}
static __device__ __forceinline__ uint32_t swzf(uint32_t row, uint32_t colbyte) {
    return row * 256u + (colbyte ^ ((row & 7u) << 4));
}
__device__ __forceinline__ void cp16(uint32_t saddr, const void* gptr) {
    asm volatile("cp.async.cg.shared.global [%0], [%1], 16;"
                 :: "r"(saddr), "l"(gptr) : "memory");
}
#define CP_COMMIT() asm volatile("cp.async.commit_group;" ::: "memory")

__device__ __forceinline__ void ldsm_x4(uint32_t a, uint32_t* r) {
    asm volatile("ldmatrix.sync.aligned.m8n8.x4.shared.b16 {%0,%1,%2,%3}, [%4];"
                 : "=r"(r[0]), "=r"(r[1]), "=r"(r[2]), "=r"(r[3]) : "r"(a));
}
__device__ __forceinline__ void ldsm_x4t(uint32_t a, uint32_t* r) {
    asm volatile("ldmatrix.sync.aligned.m8n8.x4.trans.shared.b16 {%0,%1,%2,%3}, [%4];"
                 : "=r"(r[0]), "=r"(r[1]), "=r"(r[2]), "=r"(r[3]) : "r"(a));
}
__device__ __forceinline__ void mma16816(float* d, const uint32_t* a, const uint32_t* b) {
    asm volatile(
        "mma.sync.aligned.m16n8k16.row.col.f32.bf16.bf16.f32 "
        "{%0,%1,%2,%3}, {%4,%5,%6,%7}, {%8,%9}, {%0,%1,%2,%3};"
        : "+f"(d[0]), "+f"(d[1]), "+f"(d[2]), "+f"(d[3])
        : "r"(a[0]), "r"(a[1]), "r"(a[2]), "r"(a[3]), "r"(b[0]), "r"(b[1]));
}
__device__ __forceinline__ void mma16816h(float* d, const uint32_t* a, const uint32_t* b) {
    asm volatile(
        "mma.sync.aligned.m16n8k16.row.col.f32.f16.f16.f32 "
        "{%0,%1,%2,%3}, {%4,%5,%6,%7}, {%8,%9}, {%0,%1,%2,%3};"
        : "+f"(d[0]), "+f"(d[1]), "+f"(d[2]), "+f"(d[3])
        : "r"(a[0]), "r"(a[1]), "r"(a[2]), "r"(a[3]), "r"(b[0]), "r"(b[1]));
}
__device__ __forceinline__ uint32_t packh2(float x, float y) {
    half2 t = __floats2half2_rn(x, y);
    return *(uint32_t*)&t;
}
__device__ __forceinline__ void split1(float x, __nv_bfloat16& h, __nv_bfloat16& l) {
    h = __float2bfloat16(x);
    l = __float2bfloat16(x - __bfloat162float(h));
}

// ---------------------------------------------------------------------------
// RoPE tables (once; double math)
// ---------------------------------------------------------------------------
__global__ void rope_table_kernel()
{
    int idx = blockIdx.x * blockDim.x + threadIdx.x;
    if (idx >= S_ * 64) return;
    const int i = idx & 63;
    const int s = idx >> 6;
    const float inv_freq = (float)pow(10000.0, -(double)i * (1.0 / 64.0));
    const double ang = (double)s * (double)inv_freq;
    double sd, cd;
    sincos(ang, &sd, &cd);
    g_cos[idx] = (float)cd;
    g_sin[idx] = (float)sd;
}

// ---------------------------------------------------------------------------
// x: fp32 -> bf16 hi/lo AND fp16 (one pass)
// ---------------------------------------------------------------------------
__global__ void split_x(const float* __restrict__ in,
                        __nv_bfloat16* __restrict__ hi,
                        __nv_bfloat16* __restrict__ lo,
                        __half* __restrict__ x16, int n4)
{
    int i = blockIdx.x * blockDim.x + threadIdx.x;
    if (i >= n4) return;
    float4 v = ((const float4*)in)[i];
    __nv_bfloat16 h0, h1, h2, h3, l0, l1, l2, l3;
    split1(v.x, h0, l0); split1(v.y, h1, l1);
    split1(v.z, h2, l2); split1(v.w, h3, l3);
    __nv_bfloat162* hi2 = (__nv_bfloat162*)hi;
    __nv_bfloat162* lo2 = (__nv_bfloat162*)lo;
    hi2[2 * i]     = __nv_bfloat162(h0, h1);
    hi2[2 * i + 1] = __nv_bfloat162(h2, h3);
    lo2[2 * i]     = __nv_bfloat162(l0, l1);
    lo2[2 * i + 1] = __nv_bfloat162(l2, l3);
    half2* o2 = (half2*)x16;
    o2[2 * i]     = __floats2half2_rn(v.x, v.y);
    o2[2 * i + 1] = __floats2half2_rn(v.z, v.w);
}

// Batched: split Wq/Wk (z = 0..1) to bf16 hi/lo
struct WSplitPtrs {
    const float* w[2];
    __nv_bfloat16* hi[2];
    __nv_bfloat16* lo[2];
};
__global__ void split_w2(WSplitPtrs P, int n4)
{
    int i = blockIdx.x * blockDim.x + threadIdx.x;
    if (i >= n4) return;
    const int z = blockIdx.y;
    float4 v = ((const float4*)P.w[z])[i];
    __nv_bfloat16 h0, h1, h2, h3, l0, l1, l2, l3;
    split1(v.x, h0, l0); split1(v.y, h1, l1);
    split1(v.z, h2, l2); split1(v.w, h3, l3);
    __nv_bfloat162* hi2 = (__nv_bfloat162*)P.hi[z];
    __nv_bfloat162* lo2 = (__nv_bfloat162*)P.lo[z];
    hi2[2 * i]     = __nv_bfloat162(h0, h1);
    hi2[2 * i + 1] = __nv_bfloat162(h2, h3);
    lo2[2 * i]     = __nv_bfloat162(l0, l1);
    lo2[2 * i + 1] = __nv_bfloat162(l2, l3);
}

// Batched: Wv/Wo fp32 -> fp16
struct WF16Ptrs {
    const float* w[2];
    __half* o[2];
};
__global__ void split_wf16(WF16Ptrs P, int n4)
{
    int i = blockIdx.x * blockDim.x + threadIdx.x;
    if (i >= n4) return;
    const int z = blockIdx.y;
    float4 v = ((const float4*)P.w[z])[i];
    half2* o2 = (half2*)P.o[z];
    o2[2 * i]     = __floats2half2_rn(v.x, v.y);
    o2[2 * i + 1] = __floats2half2_rn(v.z, v.w);
}

// ---------------------------------------------------------------------------
// Merged QK GEMM (bf16 3-product), fused rope+split epilogue. z=0:Q, z=1:K.
// ---------------------------------------------------------------------------
#define TCT16 16384u
#define TCBUF (4u * TCT16)
#define TC_SMEM_BYTES (3u * TCBUF)

struct QKPtrs {
    const __nv_bfloat16* bhi[2];
    const __nv_bfloat16* blo[2];
    __nv_bfloat16* dhi[2];
    __nv_bfloat16* dlo[2];
};

__global__ void __launch_bounds__(256, 1)
sgemm_qk(const __nv_bfloat16* __restrict__ Ahi, const __nv_bfloat16* __restrict__ Alo,
         QKPtrs P)
{
    extern __shared__ char smem[];
    const uint32_t sbase = smem_u32(smem);

    const int z = blockIdx.z;
    const __nv_bfloat16* __restrict__ Bhi = P.bhi[z];
    const __nv_bfloat16* __restrict__ Blo = P.blo[z];
    __nv_bfloat16* __restrict__ Dhi = P.dhi[z];
    __nv_bfloat16* __restrict__ Dlo = P.dlo[z];

    const int tid  = threadIdx.x;
    const int lane = tid & 31;
    const int w    = tid >> 5;
    const int m0w  = (w >> 2) * 64;
    const int n0w  = (w & 3) * 32;

    const int m0 = blockIdx.y * 128;
    const int n0 = blockIdx.x * 128;
    const int h  = blockIdx.x;

    uint32_t swofs[4];
#pragma unroll
    for (int t = 0; t < 4; t++) {
        const int u = tid + (t << 8);
        swofs[t] = swz128((uint32_t)((u >> 3) * 128 + (u & 7) * 16));
    }

    float acc[4][4][4];
#pragma unroll
    for (int i = 0; i < 4; i++)
#pragma unroll
        for (int j = 0; j < 4; j++)
#pragma unroll
            for (int r = 0; r < 4; r++) acc[i][j][r] = 0.0f;

    const uint32_t arow = (uint32_t)(m0w + (lane & 15));
    const uint32_t acol = (uint32_t)((lane >> 4) << 4);
    const uint32_t browx = (uint32_t)(n0w + (lane & 7) + ((lane >> 4) << 3));
    const uint32_t bcol  = (uint32_t)(((lane >> 3) & 1) << 4);

#define LOAD_CHUNK(c, buf)                                                     \
    {                                                                          \
        const uint32_t bofs = sbase + (uint32_t)(buf) * TCBUF;                 \
        const int k0 = (c) * 64;                                               \
        _Pragma("unroll")                                                      \
        for (int t = 0; t < 4; t++) {                                          \
            const int u = tid + (t << 8);                                      \
            const int r = u >> 3;                                              \
            const int c16 = u & 7;                                             \
            const size_t ga = (size_t)(m0 + r) * D_ + k0 + c16 * 8;            \
            const size_t gb = (size_t)(n0 + r) * D_ + k0 + c16 * 8;            \
            cp16(bofs + 0u * TCT16 + swofs[t], Ahi + ga);                      \
            cp16(bofs + 1u * TCT16 + swofs[t], Alo + ga);                      \
            cp16(bofs + 2u * TCT16 + swofs[t], Bhi + gb);                      \
            cp16(bofs + 3u * TCT16 + swofs[t], Blo + gb);                      \
        }                                                                      \
        CP_COMMIT();                                                           \
    }

    LOAD_CHUNK(0, 0);
    LOAD_CHUNK(1, 1);

    int buf = 0;
    for (int c = 0; c < 32; c++) {
        if (c < 31) {
            asm volatile("cp.async.wait_group 1;" ::: "memory");
        } else {
            asm volatile("cp.async.wait_group 0;" ::: "memory");
        }
        __syncthreads();
        if (c + 2 < 32) {
            const int nb = (buf + 2 >= 3) ? buf - 1 : buf + 2;
            LOAD_CHUNK(c + 2, nb);
        }

        const uint32_t bofs = sbase + (uint32_t)buf * TCBUF;
        const uint32_t Ab_hi = bofs + 0u * TCT16;
        const uint32_t Ab_lo = bofs + 1u * TCT16;
        const uint32_t Bb_hi = bofs + 2u * TCT16;
        const uint32_t Bb_lo = bofs + 3u * TCT16;

#pragma unroll
        for (int kk = 0; kk < 4; kk++) {
            uint32_t ah[4][4], al[4][4], bh[4][2], bl[4][2];
            const uint32_t kb = (uint32_t)(kk * 32);
#pragma unroll
            for (int mt = 0; mt < 4; mt++) {
                const uint32_t ofs = swz128((arow + mt * 16u) * 128u + acol + kb);
                ldsm_x4(Ab_hi + ofs, ah[mt]);
                ldsm_x4(Ab_lo + ofs, al[mt]);
            }
#pragma unroll
            for (int ntp = 0; ntp < 2; ntp++) {
                const uint32_t ofs = swz128((browx + ntp * 16u) * 128u + bcol + kb);
                uint32_t b4h[4], b4l[4];
                ldsm_x4(Bb_hi + ofs, b4h);
                ldsm_x4(Bb_lo + ofs, b4l);
                bh[2 * ntp][0] = b4h[0];     bh[2 * ntp][1] = b4h[1];
                bh[2 * ntp + 1][0] = b4h[2]; bh[2 * ntp + 1][1] = b4h[3];
                bl[2 * ntp][0] = b4l[0];     bl[2 * ntp][1] = b4l[1];
                bl[2 * ntp + 1][0] = b4l[2]; bl[2 * ntp + 1][1] = b4l[3];
            }
#pragma unroll
            for (int mt = 0; mt < 4; mt++)
#pragma unroll
                for (int nt = 0; nt < 4; nt++) {
                    mma16816(acc[mt][nt], ah[mt], bh[nt]);
                    mma16816(acc[mt][nt], ah[mt], bl[nt]);
                    mma16816(acc[mt][nt], al[mt], bh[nt]);
                }
        }
        __syncthreads();
        buf = (buf + 1 >= 3) ? 0 : buf + 1;
    }

    // ---- epilogue: stage fp32 tile, rope, split, store bf16 hi/lo ----
    float* Cs = (float*)smem;
    const int lr = lane >> 2;
    const int lc = (lane & 3) * 2;
#pragma unroll
    for (int mt = 0; mt < 4; mt++)
#pragma unroll
        for (int rr = 0; rr < 2; rr++) {
            const int rloc = m0w + mt * 16 + rr * 8 + lr;
            const int e = rr * 2;
#pragma unroll
            for (int nt = 0; nt < 4; nt++) {
                const int nloc = n0w + nt * 8 + lc;
                *(float2*)&Cs[rloc * 132 + nloc] =
                    make_float2(acc[mt][nt][e], acc[mt][nt][e + 1]);
            }
        }
    __syncthreads();

    const float scq = (z == 0) ? 0.08838834764831845f : 1.0f;
    for (int i = tid; i < 128 * 32; i += 256) {
        const int r  = i >> 5;
        const int c0 = (i & 31) * 2;
        const int m  = m0 + r;
        const int s  = m & (S_ - 1);
        const int bb = m >> 11;
        const float2 v1 = *(float2*)&Cs[r * 132 + c0];
        const float2 v2 = *(float2*)&Cs[r * 132 + c0 + 64];
        const int ti = (s << 6) + c0;
        const float c_0 = g_cos[ti],     s_0 = g_sin[ti];
        const float c_1 = g_cos[ti + 1], s_1 = g_sin[ti + 1];
        const float o1_0 = (v1.x * c_0 - v2.x * s_0) * scq;
        const float o1_1 = (v1.y * c_1 - v2.y * s_1) * scq;
        const float o2_0 = (v1.x * s_0 + v2.x * c_0) * scq;
        const float o2_1 = (v1.y * s_1 + v2.y * c_1) * scq;

        __nv_bfloat16 h0, l0, h1, l1, h2, l2, h3, l3;
        split1(o1_0, h0, l0); split1(o1_1, h1, l1);
        split1(o2_0, h2, l2); split1(o2_1, h3, l3);

        const size_t base = ((size_t)(bb * H_ + h) * S_ + s) * HD_;
        *(__nv_bfloat162*)&Dhi[base + c0]      = __nv_bfloat162(h0, h1);
        *(__nv_bfloat162*)&Dlo[base + c0]      = __nv_bfloat162(l0, l1);
        *(__nv_bfloat162*)&Dhi[base + c0 + 64] = __nv_bfloat162(h2, h3);
        *(__nv_bfloat162*)&Dlo[base + c0 + 64] = __nv_bfloat162(l2, l3);
    }
}

// ---------------------------------------------------------------------------
// fp16 single-product GEMM (shared body):
//   head_layout=0: C fp32 row-major  (out-projection)
//   head_layout=1: C16 fp16 head layout [b][h][s][hd]  (V projection)
// ---------------------------------------------------------------------------
#define TCBUF16 (2u * TCT16)
#define TC16_SMEM_BYTES (3u * TCBUF16)

__global__ void __launch_bounds__(256)
sgemm_f16(const __half* __restrict__ A16, const __half* __restrict__ B16,
          float* __restrict__ C, __half* __restrict__ C16, int head_layout)
{
    extern __shared__ char smem[];
    const uint32_t sbase = smem_u32(smem);

    const int tid  = threadIdx.x;
    const int lane = tid & 31;
    const int w    = tid >> 5;
    const int m0w  = (w >> 2) * 64;
    const int n0w  = (w & 3) * 32;

    const int m0 = blockIdx.y * 128;
    const int n0 = blockIdx.x * 128;

    uint32_t swofs[4];
#pragma unroll
    for (int t = 0; t < 4; t++) {
        const int u = tid + (t << 8);
        swofs[t] = swz128((uint32_t)((u >> 3) * 128 + (u & 7) * 16));
    }

    float acc[4][4][4];
#pragma unroll
    for (int i = 0; i < 4; i++)
#pragma unroll
        for (int j = 0; j < 4; j++)
#pragma unroll
            for (int r = 0; r < 4; r++) acc[i][j][r] = 0.0f;

    const uint32_t arow = (uint32_t)(m0w + (lane & 15));
    const uint32_t acol = (uint32_t)((lane >> 4) << 4);
    const uint32_t browx = (uint32_t)(n0w + (lane & 7) + ((lane >> 4) << 3));
    const uint32_t bcol  = (uint32_t)(((lane >> 3) & 1) << 4);

#define LOAD_CHUNK16(c, buf)                                                   \
    {                                                                          \
        const uint32_t bofs = sbase + (uint32_t)(buf) * TCBUF16;               \
        const int k0 = (c) * 64;                                               \
        _Pragma("unroll")                                                      \
        for (int t = 0; t < 4; t++) {                                          \
            const int u = tid + (t << 8);                                      \
            const int r = u >> 3;                                              \
            const int c16 = u & 7;                                             \
            const size_t ga = (size_t)(m0 + r) * D_ + k0 + c16 * 8;            \
            const size_t gb = (size_t)(n0 + r) * D_ + k0 + c16 * 8;            \
            cp16(bofs + 0u * TCT16 + swofs[t], A16 + ga);                      \
            cp16(bofs + 1u * TCT16 + swofs[t], B16 + gb);                      \
        }                                                                      \
        CP_COMMIT();                                                           \
    }

    LOAD_CHUNK16(0, 0);
    LOAD_CHUNK16(1, 1);

    int buf = 0;
    for (int c = 0; c < 32; c++) {
        if (c < 31) {
            asm volatile("cp.async.wait_group 1;" ::: "memory");
        } else {
            asm volatile("cp.async.wait_group 0;" ::: "memory");
        }
        __syncthreads();
        if (c + 2 < 32) {
            const int nb = (buf + 2 >= 3) ? buf - 1 : buf + 2;
            LOAD_CHUNK16(c + 2, nb);
        }

        const uint32_t bofs = sbase + (uint32_t)buf * TCBUF16;
        const uint32_t Ab = bofs + 0u * TCT16;
        const uint32_t Bb = bofs + 1u * TCT16;

#pragma unroll
        for (int kk = 0; kk < 4; kk++) {
            uint32_t ah[4][4], bh[4][2];
            const uint32_t kb = (uint32_t)(kk * 32);
#pragma unroll
            for (int mt = 0; mt < 4; mt++) {
                const uint32_t ofs = swz128((arow + mt * 16u) * 128u + acol + kb);
                ldsm_x4(Ab + ofs, ah[mt]);
            }
#pragma unroll
            for (int ntp = 0; ntp < 2; ntp++) {
                const uint32_t ofs = swz128((browx + ntp * 16u) * 128u + bcol + kb);
                uint32_t b4[4];
                ldsm_x4(Bb + ofs, b4);
                bh[2 * ntp][0] = b4[0];     bh[2 * ntp][1] = b4[1];
                bh[2 * ntp + 1][0] = b4[2]; bh[2 * ntp + 1][1] = b4[3];
            }
#pragma unroll
            for (int mt = 0; mt < 4; mt++)
#pragma unroll
                for (int nt = 0; nt < 4; nt++)
                    mma16816h(acc[mt][nt], ah[mt], bh[nt]);
        }
        __syncthreads();
        buf = (buf + 1 >= 3) ? 0 : buf + 1;
    }

    const int lr = lane >> 2;
    const int lc = (lane & 3) * 2;
#pragma unroll
    for (int mt = 0; mt < 4; mt++) {
#pragma unroll
        for (int rr = 0; rr < 2; rr++) {
            const int m = m0 + m0w + mt * 16 + rr * 8 + lr;
            const int e = rr * 2;
            if (head_layout) {
                const int bb = m >> 11, s = m & (S_ - 1);
                const size_t rowoff = ((size_t)(bb * H_) * S_ + s) * HD_;
#pragma unroll
                for (int nt = 0; nt < 4; nt++) {
                    const int n = n0 + n0w + nt * 8 + lc;
                    const int h = n >> 7, hd = n & 127;
                    *(half2*)&C16[rowoff + (size_t)h * S_ * HD_ + hd] =
                        __floats2half2_rn(acc[mt][nt][e], acc[mt][nt][e + 1]);
                }
            } else {
                const size_t dstbase = (size_t)m * D_;
#pragma unroll
                for (int nt = 0; nt < 4; nt++) {
                    const int n = n0 + n0w + nt * 8 + lc;
                    *(float2*)&C[dstbase + n] =
                        make_float2(acc[mt][nt][e], acc[mt][nt][e + 1]);
                }
            }
        }
    }
}

// ---------------------------------------------------------------------------
// Tensor-core flash attention: QK bf16 3-product, PV fp16 1-product (R10).
// ---------------------------------------------------------------------------
#define KVSTAGE 49152u
#define FL_SMEM (65536 + 2 * KVSTAGE)

__global__ void __launch_bounds__(256, 1)
flash_tc(const __nv_bfloat16* __restrict__ Qhi, const __nv_bfloat16* __restrict__ Qlo,
         const __nv_bfloat16* __restrict__ Khi, const __nv_bfloat16* __restrict__ Klo,
         const __half* __restrict__ V16,
         __half* __restrict__ AO16)
{
    extern __shared__ char smem[];
    const uint32_t sb = smem_u32(smem);
    const uint32_t sQh = sb;
    const uint32_t sQl = sb + 32768u;

    const int tid  = threadIdx.x;
    const int lane = tid & 31;
    const int w    = tid >> 5;
    const int lr   = lane >> 2;
    const int lc2  = (lane & 3) * 2;

    const int qt = (int)gridDim.x - 1 - (int)blockIdx.x;
    const int h  = blockIdx.y;
    const int b  = blockIdx.z;
    const size_t bh = ((size_t)(b * H_ + h)) * S_ * HD_;

    const __nv_bfloat16* Qhg = Qhi + bh + (size_t)qt * 128 * HD_;
    const __nv_bfloat16* Qlg = Qlo + bh + (size_t)qt * 128 * HD_;

    for (int i = tid; i < 2048; i += 256) {
        const uint32_t r = (uint32_t)(i >> 4);
        const uint32_t cb = (uint32_t)((i & 15) << 4);
        const uint32_t so = swzf(r, cb);
        cp16(sQh + so, Qhg + (size_t)r * HD_ + (i & 15) * 8);
        cp16(sQl + so, Qlg + (size_t)r * HD_ + (i & 15) * 8);
    }

#define LOAD_KV(jj, buf)                                                       \
    {                                                                          \
        const uint32_t kvb = sb + 65536u + (uint32_t)(buf) * KVSTAGE;          \
        const size_t rg0 = (size_t)(jj) * 64;                                  \
        for (int i = tid; i < 1024; i += 256) {                                \
            const uint32_t r = (uint32_t)(i >> 4);                             \
            const uint32_t cb = (uint32_t)((i & 15) << 4);                     \
            const uint32_t so = swzf(r, cb);                                   \
            const size_t g = bh + (rg0 + r) * HD_ + (i & 15) * 8;              \
            cp16(kvb + so, Khi + g);                                           \
            cp16(kvb + 16384u + so, Klo + g);                                  \
            cp16(kvb + 32768u + so, V16 + g);                                  \
        }                                                                      \
    }

    LOAD_KV(0, 0);
    CP_COMMIT();

    float o[16][4];
#pragma unroll
    for (int i = 0; i < 16; i++)
#pragma unroll
        for (int e = 0; e < 4; e++) o[i][e] = 0.0f;
    float m0 = -1e30f, m1 = -1e30f, l0 = 0.0f, l1 = 0.0f;

    const int jmax = 2 * qt + 1;
    const int rbase = qt * 128 + w * 16 + lr;

    const uint32_t krowx = (uint32_t)((lane & 7) + ((lane >> 4) << 3));
    const uint32_t kcolx = (uint32_t)(((lane >> 3) & 1) << 4);

    for (int j = 0; j <= jmax; j++) {
        if (j < jmax) {
            LOAD_KV(j + 1, (j + 1) & 1);
            CP_COMMIT();
            asm volatile("cp.async.wait_group 1;" ::: "memory");
        } else {
            asm volatile("cp.async.wait_group 0;" ::: "memory");
        }
        __syncthreads();

        const bool active = !(j == jmax && w < 4);
        if (active) {
        const uint32_t kvb = sb + 65536u + (uint32_t)(j & 1) * KVSTAGE;
        const uint32_t sKh = kvb;
        const uint32_t sKl = kvb + 16384u;
        const uint32_t sV  = kvb + 32768u;

        float sacc[8][4];
#pragma unroll
        for (int nt = 0; nt < 8; nt++)
#pragma unroll
            for (int e = 0; e < 4; e++) sacc[nt][e] = 0.0f;

#pragma unroll
        for (int kc = 0; kc < 8; kc++) {
            const uint32_t ao_ = swzf((uint32_t)(w * 16 + (lane & 15)),
                                      (uint32_t)(kc * 32 + ((lane >> 4) << 4)));
            uint32_t ah[4], al[4];
            ldsm_x4(sQh + ao_, ah);
            ldsm_x4(sQl + ao_, al);
#pragma unroll
            for (int ntp = 0; ntp < 4; ntp++) {
                const uint32_t bo = swzf(krowx + ntp * 16u,
                                         (uint32_t)(kc * 32) + kcolx);
                uint32_t b4h[4], b4l[4];
                ldsm_x4(sKh + bo, b4h);
                ldsm_x4(sKl + bo, b4l);
                mma16816(sacc[2 * ntp],     ah, &b4h[0]);
                mma16816(sacc[2 * ntp],     ah, &b4l[0]);
                mma16816(sacc[2 * ntp],     al, &b4h[0]);
                mma16816(sacc[2 * ntp + 1], ah, &b4h[2]);
                mma16816(sacc[2 * ntp + 1], ah, &b4l[2]);
                mma16816(sacc[2 * ntp + 1], al, &b4h[2]);
            }
        }

        if (j >= 2 * qt) {
            const int cb0 = j * 64 + lc2;
#pragma unroll
            for (int nt = 0; nt < 8; nt++)
#pragma unroll
                for (int e = 0; e < 4; e++) {
                    const int col = cb0 + nt * 8 + (e & 1);
                    const int row = rbase + 8 * (e >> 1);
                    if (col > row) sacc[nt][e] = -1e30f;
                }
        }

        float mx0 = -1e30f, mx1 = -1e30f;
#pragma unroll
        for (int nt = 0; nt < 8; nt++) {
            mx0 = fmaxf(mx0, fmaxf(sacc[nt][0], sacc[nt][1]));
            mx1 = fmaxf(mx1, fmaxf(sacc[nt][2], sacc[nt][3]));
        }
        mx0 = fmaxf(mx0, __shfl_xor_sync(0xffffffffu, mx0, 1));
        mx0 = fmaxf(mx0, __shfl_xor_sync(0xffffffffu, mx0, 2));
        mx1 = fmaxf(mx1, __shfl_xor_sync(0xffffffffu, mx1, 1));
        mx1 = fmaxf(mx1, __shfl_xor_sync(0xffffffffu, mx1, 2));

        const float mn0 = fmaxf(m0, mx0);
        const float mn1 = fmaxf(m1, mx1);
        const float al0 = __expf(m0 - mn0);
        const float al1 = __expf(m1 - mn1);
        m0 = mn0; m1 = mn1;

        float s0 = 0.0f, s1 = 0.0f;
#pragma unroll
        for (int nt = 0; nt < 8; nt++) {
            sacc[nt][0] = __expf(sacc[nt][0] - mn0); s0 += sacc[nt][0];
            sacc[nt][1] = __expf(sacc[nt][1] - mn0); s0 += sacc[nt][1];
            sacc[nt][2] = __expf(sacc[nt][2] - mn1); s1 += sacc[nt][2];
            sacc[nt][3] = __expf(sacc[nt][3] - mn1); s1 += sacc[nt][3];
        }
        s0 += __shfl_xor_sync(0xffffffffu, s0, 1);
        s0 += __shfl_xor_sync(0xffffffffu, s0, 2);
        s1 += __shfl_xor_sync(0xffffffffu, s1, 1);
        s1 += __shfl_xor_sync(0xffffffffu, s1, 2);
        l0 = l0 * al0 + s0;
        l1 = l1 * al1 + s1;

#pragma unroll
        for (int dt = 0; dt < 16; dt++) {
            o[dt][0] *= al0; o[dt][1] *= al0;
            o[dt][2] *= al1; o[dt][3] *= al1;
        }

#pragma unroll
        for (int t = 0; t < 4; t++) {
            uint32_t ph[4];
#pragma unroll
            for (int q2 = 0; q2 < 2; q2++)
#pragma unroll
                for (int rr = 0; rr < 2; rr++)
                    ph[q2 * 2 + rr] = packh2(sacc[2 * t + q2][2 * rr],
                                             sacc[2 * t + q2][2 * rr + 1]);
#pragma unroll
            for (int dtp = 0; dtp < 8; dtp++) {
                const uint32_t bo = swzf((uint32_t)(t * 16 + (lane & 15)),
                                         (uint32_t)((2 * dtp + (lane >> 4)) * 16));
                uint32_t b4[4];
                ldsm_x4t(sV + bo, b4);
                mma16816h(o[2 * dtp],     ph, &b4[0]);
                mma16816h(o[2 * dtp + 1], ph, &b4[2]);
            }
        }
        } // active
        __syncthreads();
    }

    const float inv0 = 1.0f / l0;
    const float inv1 = 1.0f / l1;
    const int srow0 = qt * 128 + w * 16 + lr;
    const size_t d0 = ((size_t)(b * S_ + srow0)) * D_ + h * HD_;
    const size_t d1 = ((size_t)(b * S_ + srow0 + 8)) * D_ + h * HD_;
#pragma unroll
    for (int dt = 0; dt < 16; dt++) {
        *(half2*)&AO16[d0 + dt * 8 + lc2] =
            __floats2half2_rn(o[dt][0] * inv0, o[dt][1] * inv0);
        *(half2*)&AO16[d1 + dt * 8 + lc2] =
            __floats2half2_rn(o[dt][2] * inv1, o[dt][3] * inv1);
    }
}

// ---------------------------------------------------------------------------
extern "C" void kernel_launch(void* const* d_in, const int* in_sizes, int n_in,
                              void* d_out, int out_size)
{
    (void)in_sizes; (void)n_in; (void)out_size;
    const float* x  = (const float*)d_in[0];
    const float* Wq = (const float*)d_in[2];
    const float* Wk = (const float*)d_in[3];
    const float* Wv = (const float*)d_in[4];
    const float* Wo = (const float*)d_in[5];
    float* out = (float*)d_out;

    __nv_bfloat16 *xhi, *xlo;
    __nv_bfloat16 *wqhi, *wqlo, *wkhi, *wklo;
    __nv_bfloat16 *qh, *ql, *kh, *kl;
    __half *x16, *wv16, *wo16, *ao16, *v16;
    cudaGetSymbolAddress((void**)&xhi, g_xhi);
    cudaGetSymbolAddress((void**)&xlo, g_xlo);
    cudaGetSymbolAddress((void**)&x16, g_x16);
    cudaGetSymbolAddress((void**)&wqhi, g_wqhi);
    cudaGetSymbolAddress((void**)&wqlo, g_wqlo);
    cudaGetSymbolAddress((void**)&wkhi, g_wkhi);
    cudaGetSymbolAddress((void**)&wklo, g_wklo);
    cudaGetSymbolAddress((void**)&wv16, g_wv16);
    cudaGetSymbolAddress((void**)&wo16, g_wo16);
    cudaGetSymbolAddress((void**)&ao16, g_ao16);
    cudaGetSymbolAddress((void**)&v16, g_v16);
    cudaGetSymbolAddress((void**)&qh, g_qh);
    cudaGetSymbolAddress((void**)&ql, g_ql);
    cudaGetSymbolAddress((void**)&kh, g_kh);
    cudaGetSymbolAddress((void**)&kl, g_kl);

    cudaFuncSetAttribute(sgemm_qk,
                         cudaFuncAttributeMaxDynamicSharedMemorySize, TC_SMEM_BYTES);
    cudaFuncSetAttribute(sgemm_f16,
                         cudaFuncAttributeMaxDynamicSharedMemorySize, TC16_SMEM_BYTES);
    cudaFuncSetAttribute(flash_tc,
                         cudaFuncAttributeMaxDynamicSharedMemorySize, FL_SMEM);

    const int xn4 = (B_ * S_ * D_) / 4;
    const int wn4 = (D_ * D_) / 4;

    rope_table_kernel<<<(S_ * 64 + 255) / 256, 256>>>();
    split_x<<<(xn4 + 255) / 256, 256>>>(x, xhi, xlo, x16, xn4);

    WSplitPtrs WS;
    WS.w[0] = Wq; WS.hi[0] = wqhi; WS.lo[0] = wqlo;
    WS.w[1] = Wk; WS.hi[1] = wkhi; WS.lo[1] = wklo;
    split_w2<<<dim3((wn4 + 255) / 256, 2), 256>>>(WS, wn4);

    WF16Ptrs WF;
    WF.w[0] = Wv; WF.o[0] = wv16;
    WF.w[1] = Wo; WF.o[1] = wo16;
    split_wf16<<<dim3((wn4 + 255) / 256, 2), 256>>>(WF, wn4);

    dim3 ggrid(D_ / 128, (B_ * S_) / 128);

    // V projection (fp16 single-product, head-layout fp16 epilogue)
    sgemm_f16<<<ggrid, 256, TC16_SMEM_BYTES>>>(x16, wv16, nullptr, v16, 1);

    // Q/K projections (bf16 3-product, fused rope+split epilogue)
    QKPtrs P;
    P.bhi[0] = wqhi; P.blo[0] = wqlo; P.dhi[0] = qh; P.dlo[0] = ql;
    P.bhi[1] = wkhi; P.blo[1] = wklo; P.dhi[1] = kh; P.dlo[1] = kl;
    dim3 qkgrid(D_ / 128, (B_ * S_) / 128, 2);
    sgemm_qk<<<qkgrid, 256, TC_SMEM_BYTES>>>(xhi, xlo, P);

    // attention
    flash_tc<<<dim3(S_ / 128, H_, B_), 256, FL_SMEM>>>(qh, ql, kh, kl, v16, ao16);

    // output projection (fp16 single-product, fp32 row-major epilogue)
    sgemm_f16<<<ggrid, 256, TC16_SMEM_BYTES>>>(ao16, wo16, out, nullptr, 0);
}

// round 12
// speedup vs baseline: 2.2311x; 1.0788x over previous
#include <cuda_runtime.h>
#include <cuda_bf16.h>
#include <cuda_fp16.h>
#include <math.h>
#include <stdint.h>

#define B_ 2
#define S_ 2048
#define D_ 2048
#define H_ 16
#define HD_ 128

// ---------------- device scratch (no runtime allocation) ----------------
__device__ __nv_bfloat16 g_xhi[B_ * S_ * D_];
__device__ __nv_bfloat16 g_xlo[B_ * S_ * D_];
__device__ __half g_x16[B_ * S_ * D_];
__device__ __nv_bfloat16 g_wqhi[D_ * D_], g_wqlo[D_ * D_];
__device__ __nv_bfloat16 g_wkhi[D_ * D_], g_wklo[D_ * D_];
__device__ __half g_wv16[D_ * D_];
__device__ __half g_wo16[D_ * D_];
__device__ __half g_ao16[B_ * S_ * D_];

// attention operands (head layout [b][h][s][hd])
__device__ __nv_bfloat16 g_qh[B_ * H_ * S_ * HD_], g_ql[B_ * H_ * S_ * HD_];
__device__ __nv_bfloat16 g_kh[B_ * H_ * S_ * HD_], g_kl[B_ * H_ * S_ * HD_];
__device__ __half g_v16[B_ * H_ * S_ * HD_];

__device__ float g_cos[S_ * 64];
__device__ float g_sin[S_ * 64];

// ---------------- helpers ----------------
__device__ __forceinline__ uint32_t smem_u32(const void* p) {
    uint32_t a;
    asm("{ .reg .u64 t; cvta.to.shared.u64 t, %1; cvt.u32.u64 %0, t; }"
        : "=r"(a) : "l"(p));
    return a;
}
static __device__ __forceinline__ uint32_t swz128(uint32_t o) {
    return o ^ ((o >> 3) & 0x70);
}
static __device__ __forceinline__ uint32_t swzf(uint32_t row, uint32_t colbyte) {
    return row * 256u + (colbyte ^ ((row & 7u) << 4));
}
__device__ __forceinline__ void cp16(uint32_t saddr, const void* gptr) {
    asm volatile("cp.async.cg.shared.global [%0], [%1], 16;"
                 :: "r"(saddr), "l"(gptr) : "memory");
}
#define CP_COMMIT() asm volatile("cp.async.commit_group;" ::: "memory")

__device__ __forceinline__ void ldsm_x4(uint32_t a, uint32_t* r) {
    asm volatile("ldmatrix.sync.aligned.m8n8.x4.shared.b16 {%0,%1,%2,%3}, [%4];"
                 : "=r"(r[0]), "=r"(r[1]), "=r"(r[2]), "=r"(r[3]) : "r"(a));
}
__device__ __forceinline__ void ldsm_x4t(uint32_t a, uint32_t* r) {
    asm volatile("ldmatrix.sync.aligned.m8n8.x4.trans.shared.b16 {%0,%1,%2,%3}, [%4];"
                 : "=r"(r[0]), "=r"(r[1]), "=r"(r[2]), "=r"(r[3]) : "r"(a));
}
__device__ __forceinline__ void mma16816(float* d, const uint32_t* a, const uint32_t* b) {
    asm volatile(
        "mma.sync.aligned.m16n8k16.row.col.f32.bf16.bf16.f32 "
        "{%0,%1,%2,%3}, {%4,%5,%6,%7}, {%8,%9}, {%0,%1,%2,%3};"
        : "+f"(d[0]), "+f"(d[1]), "+f"(d[2]), "+f"(d[3])
        : "r"(a[0]), "r"(a[1]), "r"(a[2]), "r"(a[3]), "r"(b[0]), "r"(b[1]));
}
__device__ __forceinline__ void mma16816h(float* d, const uint32_t* a, const uint32_t* b) {
    asm volatile(
        "mma.sync.aligned.m16n8k16.row.col.f32.f16.f16.f32 "
        "{%0,%1,%2,%3}, {%4,%5,%6,%7}, {%8,%9}, {%0,%1,%2,%3};"
        : "+f"(d[0]), "+f"(d[1]), "+f"(d[2]), "+f"(d[3])
        : "r"(a[0]), "r"(a[1]), "r"(a[2]), "r"(a[3]), "r"(b[0]), "r"(b[1]));
}
__device__ __forceinline__ uint32_t packh2(float x, float y) {
    half2 t = __floats2half2_rn(x, y);
    return *(uint32_t*)&t;
}
__device__ __forceinline__ void split1(float x, __nv_bfloat16& h, __nv_bfloat16& l) {
    h = __float2bfloat16(x);
    l = __float2bfloat16(x - __bfloat162float(h));
}

// ---------------------------------------------------------------------------
// Mega prep kernel: rope tables + all splits/casts, block-range dispatched.
//   [0,512)            rope table (131072 entries)
//   [512, 8704)        x -> bf16 hi/lo + fp16       (2097152 float4)
//   [8704, 12800)      Wq -> bf16 hi/lo             (1048576 float4)
//   [12800, 16896)     Wk -> bf16 hi/lo
//   [16896, 20992)     Wv -> fp16
//   [20992, 25088)     Wo -> fp16
// ---------------------------------------------------------------------------
#define PREP_BLOCKS 25088

__global__ void prep_all(const float* __restrict__ x,
                         const float* __restrict__ Wq, const float* __restrict__ Wk,
                         const float* __restrict__ Wv, const float* __restrict__ Wo)
{
    const int bid = blockIdx.x;
    const int t   = threadIdx.x;

    if (bid < 512) {
        const int idx = bid * 256 + t;
        const int i = idx & 63;
        const int s = idx >> 6;
        const float inv_freq = (float)pow(10000.0, -(double)i * (1.0 / 64.0));
        const double ang = (double)s * (double)inv_freq;
        double sd, cd;
        sincos(ang, &sd, &cd);
        g_cos[idx] = (float)cd;
        g_sin[idx] = (float)sd;
        return;
    }
    if (bid < 8704) {
        const int i = (bid - 512) * 256 + t;
        float4 v = ((const float4*)x)[i];
        __nv_bfloat16 h0, h1, h2, h3, l0, l1, l2, l3;
        split1(v.x, h0, l0); split1(v.y, h1, l1);
        split1(v.z, h2, l2); split1(v.w, h3, l3);
        ((__nv_bfloat162*)g_xhi)[2 * i]     = __nv_bfloat162(h0, h1);
        ((__nv_bfloat162*)g_xhi)[2 * i + 1] = __nv_bfloat162(h2, h3);
        ((__nv_bfloat162*)g_xlo)[2 * i]     = __nv_bfloat162(l0, l1);
        ((__nv_bfloat162*)g_xlo)[2 * i + 1] = __nv_bfloat162(l2, l3);
        ((half2*)g_x16)[2 * i]     = __floats2half2_rn(v.x, v.y);
        ((half2*)g_x16)[2 * i + 1] = __floats2half2_rn(v.z, v.w);
        return;
    }
    if (bid < 16896) {
        const bool is_q = bid < 12800;
        const int i = (bid - (is_q ? 8704 : 12800)) * 256 + t;
        const float* w = is_q ? Wq : Wk;
        __nv_bfloat16* hi = is_q ? g_wqhi : g_wkhi;
        __nv_bfloat16* lo = is_q ? g_wqlo : g_wklo;
        float4 v = ((const float4*)w)[i];
        __nv_bfloat16 h0, h1, h2, h3, l0, l1, l2, l3;
        split1(v.x, h0, l0); split1(v.y, h1, l1);
        split1(v.z, h2, l2); split1(v.w, h3, l3);
        ((__nv_bfloat162*)hi)[2 * i]     = __nv_bfloat162(h0, h1);
        ((__nv_bfloat162*)hi)[2 * i + 1] = __nv_bfloat162(h2, h3);
        ((__nv_bfloat162*)lo)[2 * i]     = __nv_bfloat162(l0, l1);
        ((__nv_bfloat162*)lo)[2 * i + 1] = __nv_bfloat162(l2, l3);
        return;
    }
    {
        const bool is_v = bid < 20992;
        const int i = (bid - (is_v ? 16896 : 20992)) * 256 + t;
        const float* w = is_v ? Wv : Wo;
        __half* o = is_v ? g_wv16 : g_wo16;
        float4 v = ((const float4*)w)[i];
        ((half2*)o)[2 * i]     = __floats2half2_rn(v.x, v.y);
        ((half2*)o)[2 * i + 1] = __floats2half2_rn(v.z, v.w);
    }
}

// ---------------------------------------------------------------------------
// Merged QKV GEMM. z=0:Q (bf16 3-prod + rope), z=1:K (same), z=2:V (fp16 1-prod).
// ---------------------------------------------------------------------------
#define TCT16 16384u
#define TCBUF (4u * TCT16)
#define TC_SMEM_BYTES (3u * TCBUF)

struct QKVPtrs {
    const __nv_bfloat16* bhi[2];
    const __nv_bfloat16* blo[2];
    __nv_bfloat16* dhi[2];
    __nv_bfloat16* dlo[2];
    const __half* a16;
    const __half* wv16;
    __half* v16;
};

__global__ void __launch_bounds__(256, 1)
sgemm_qkv(const __nv_bfloat16* __restrict__ Ahi, const __nv_bfloat16* __restrict__ Alo,
          QKVPtrs P)
{
    extern __shared__ char smem[];
    const uint32_t sbase = smem_u32(smem);

    const int z = blockIdx.z;
    const int tid  = threadIdx.x;
    const int lane = tid & 31;
    const int w    = tid >> 5;
    const int m0w  = (w >> 2) * 64;
    const int n0w  = (w & 3) * 32;

    const int m0 = blockIdx.y * 128;
    const int n0 = blockIdx.x * 128;
    const int h  = blockIdx.x;

    uint32_t swofs[4];
#pragma unroll
    for (int t = 0; t < 4; t++) {
        const int u = tid + (t << 8);
        swofs[t] = swz128((uint32_t)((u >> 3) * 128 + (u & 7) * 16));
    }

    float acc[4][4][4];
#pragma unroll
    for (int i = 0; i < 4; i++)
#pragma unroll
        for (int j = 0; j < 4; j++)
#pragma unroll
            for (int r = 0; r < 4; r++) acc[i][j][r] = 0.0f;

    const uint32_t arow = (uint32_t)(m0w + (lane & 15));
    const uint32_t acol = (uint32_t)((lane >> 4) << 4);
    const uint32_t browx = (uint32_t)(n0w + (lane & 7) + ((lane >> 4) << 3));
    const uint32_t bcol  = (uint32_t)(((lane >> 3) & 1) << 4);

    if (z == 2) {
        // ---------------- V path: fp16 single-product ----------------
        const __half* __restrict__ A16 = P.a16;
        const __half* __restrict__ B16 = P.wv16;

#define LOAD_CHUNK16(c, buf)                                                   \
    {                                                                          \
        const uint32_t bofs = sbase + (uint32_t)(buf) * TCBUF;                 \
        const int k0 = (c) * 64;                                               \
        _Pragma("unroll")                                                      \
        for (int t = 0; t < 4; t++) {                                          \
            const int u = tid + (t << 8);                                      \
            const int r = u >> 3;                                              \
            const int c16 = u & 7;                                             \
            const size_t ga = (size_t)(m0 + r) * D_ + k0 + c16 * 8;            \
            const size_t gb = (size_t)(n0 + r) * D_ + k0 + c16 * 8;            \
            cp16(bofs + 0u * TCT16 + swofs[t], A16 + ga);                      \
            cp16(bofs + 1u * TCT16 + swofs[t], B16 + gb);                      \
        }                                                                      \
        CP_COMMIT();                                                           \
    }

        LOAD_CHUNK16(0, 0);
        LOAD_CHUNK16(1, 1);

        int buf = 0;
        for (int c = 0; c < 32; c++) {
            if (c < 31) {
                asm volatile("cp.async.wait_group 1;" ::: "memory");
            } else {
                asm volatile("cp.async.wait_group 0;" ::: "memory");
            }
            __syncthreads();
            if (c + 2 < 32) {
                const int nb = (buf + 2 >= 3) ? buf - 1 : buf + 2;
                LOAD_CHUNK16(c + 2, nb);
            }

            const uint32_t bofs = sbase + (uint32_t)buf * TCBUF;
            const uint32_t Ab = bofs + 0u * TCT16;
            const uint32_t Bb = bofs + 1u * TCT16;

#pragma unroll
            for (int kk = 0; kk < 4; kk++) {
                uint32_t ah[4][4], bh[4][2];
                const uint32_t kb = (uint32_t)(kk * 32);
#pragma unroll
                for (int mt = 0; mt < 4; mt++) {
                    const uint32_t ofs = swz128((arow + mt * 16u) * 128u + acol + kb);
                    ldsm_x4(Ab + ofs, ah[mt]);
                }
#pragma unroll
                for (int ntp = 0; ntp < 2; ntp++) {
                    const uint32_t ofs = swz128((browx + ntp * 16u) * 128u + bcol + kb);
                    uint32_t b4[4];
                    ldsm_x4(Bb + ofs, b4);
                    bh[2 * ntp][0] = b4[0];     bh[2 * ntp][1] = b4[1];
                    bh[2 * ntp + 1][0] = b4[2]; bh[2 * ntp + 1][1] = b4[3];
                }
#pragma unroll
                for (int mt = 0; mt < 4; mt++)
#pragma unroll
                    for (int nt = 0; nt < 4; nt++)
                        mma16816h(acc[mt][nt], ah[mt], bh[nt]);
            }
            __syncthreads();
            buf = (buf + 1 >= 3) ? 0 : buf + 1;
        }

        // epilogue: fp16 head layout
        __half* __restrict__ C16 = P.v16;
        const int lr = lane >> 2;
        const int lc = (lane & 3) * 2;
#pragma unroll
        for (int mt = 0; mt < 4; mt++)
#pragma unroll
            for (int rr = 0; rr < 2; rr++) {
                const int m = m0 + m0w + mt * 16 + rr * 8 + lr;
                const int e = rr * 2;
                const int bb = m >> 11, s = m & (S_ - 1);
                const size_t rowoff = ((size_t)(bb * H_) * S_ + s) * HD_;
#pragma unroll
                for (int nt = 0; nt < 4; nt++) {
                    const int n = n0 + n0w + nt * 8 + lc;
                    const int hh = n >> 7, hd = n & 127;
                    *(half2*)&C16[rowoff + (size_t)hh * S_ * HD_ + hd] =
                        __floats2half2_rn(acc[mt][nt][e], acc[mt][nt][e + 1]);
                }
            }
        return;
    }

    // ---------------- Q/K path: bf16 3-product + rope epilogue ----------------
    const __nv_bfloat16* __restrict__ Bhi = P.bhi[z];
    const __nv_bfloat16* __restrict__ Blo = P.blo[z];
    __nv_bfloat16* __restrict__ Dhi = P.dhi[z];
    __nv_bfloat16* __restrict__ Dlo = P.dlo[z];

#define LOAD_CHUNK(c, buf)                                                     \
    {                                                                          \
        const uint32_t bofs = sbase + (uint32_t)(buf) * TCBUF;                 \
        const int k0 = (c) * 64;                                               \
        _Pragma("unroll")                                                      \
        for (int t = 0; t < 4; t++) {                                          \
            const int u = tid + (t << 8);                                      \
            const int r = u >> 3;                                              \
            const int c16 = u & 7;                                             \
            const size_t ga = (size_t)(m0 + r) * D_ + k0 + c16 * 8;            \
            const size_t gb = (size_t)(n0 + r) * D_ + k0 + c16 * 8;            \
            cp16(bofs + 0u * TCT16 + swofs[t], Ahi + ga);                      \
            cp16(bofs + 1u * TCT16 + swofs[t], Alo + ga);                      \
            cp16(bofs + 2u * TCT16 + swofs[t], Bhi + gb);                      \
            cp16(bofs + 3u * TCT16 + swofs[t], Blo + gb);                      \
        }                                                                      \
        CP_COMMIT();                                                           \
    }

    LOAD_CHUNK(0, 0);
    LOAD_CHUNK(1, 1);

    int buf = 0;
    for (int c = 0; c < 32; c++) {
        if (c < 31) {
            asm volatile("cp.async.wait_group 1;" ::: "memory");
        } else {
            asm volatile("cp.async.wait_group 0;" ::: "memory");
        }
        __syncthreads();
        if (c + 2 < 32) {
            const int nb = (buf + 2 >= 3) ? buf - 1 : buf + 2;
            LOAD_CHUNK(c + 2, nb);
        }

        const uint32_t bofs = sbase + (uint32_t)buf * TCBUF;
        const uint32_t Ab_hi = bofs + 0u * TCT16;
        const uint32_t Ab_lo = bofs + 1u * TCT16;
        const uint32_t Bb_hi = bofs + 2u * TCT16;
        const uint32_t Bb_lo = bofs + 3u * TCT16;

#pragma unroll
        for (int kk = 0; kk < 4; kk++) {
            uint32_t ah[4][4], al[4][4], bh[4][2], bl[4][2];
            const uint32_t kb = (uint32_t)(kk * 32);
#pragma unroll
            for (int mt = 0; mt < 4; mt++) {
                const uint32_t ofs = swz128((arow + mt * 16u) * 128u + acol + kb);
                ldsm_x4(Ab_hi + ofs, ah[mt]);
                ldsm_x4(Ab_lo + ofs, al[mt]);
            }
#pragma unroll
            for (int ntp = 0; ntp < 2; ntp++) {
                const uint32_t ofs = swz128((browx + ntp * 16u) * 128u + bcol + kb);
                uint32_t b4h[4], b4l[4];
                ldsm_x4(Bb_hi + ofs, b4h);
                ldsm_x4(Bb_lo + ofs, b4l);
                bh[2 * ntp][0] = b4h[0];     bh[2 * ntp][1] = b4h[1];
                bh[2 * ntp + 1][0] = b4h[2]; bh[2 * ntp + 1][1] = b4h[3];
                bl[2 * ntp][0] = b4l[0];     bl[2 * ntp][1] = b4l[1];
                bl[2 * ntp + 1][0] = b4l[2]; bl[2 * ntp + 1][1] = b4l[3];
            }
#pragma unroll
            for (int mt = 0; mt < 4; mt++)
#pragma unroll
                for (int nt = 0; nt < 4; nt++) {
                    mma16816(acc[mt][nt], ah[mt], bh[nt]);
                    mma16816(acc[mt][nt], ah[mt], bl[nt]);
                    mma16816(acc[mt][nt], al[mt], bh[nt]);
                }
        }
        __syncthreads();
        buf = (buf + 1 >= 3) ? 0 : buf + 1;
    }

    // epilogue: stage fp32 tile, rope, split, store bf16 hi/lo
    float* Cs = (float*)smem;
    const int lr = lane >> 2;
    const int lc = (lane & 3) * 2;
#pragma unroll
    for (int mt = 0; mt < 4; mt++)
#pragma unroll
        for (int rr = 0; rr < 2; rr++) {
            const int rloc = m0w + mt * 16 + rr * 8 + lr;
            const int e = rr * 2;
#pragma unroll
            for (int nt = 0; nt < 4; nt++) {
                const int nloc = n0w + nt * 8 + lc;
                *(float2*)&Cs[rloc * 132 + nloc] =
                    make_float2(acc[mt][nt][e], acc[mt][nt][e + 1]);
            }
        }
    __syncthreads();

    const float scq = (z == 0) ? 0.08838834764831845f : 1.0f;
    for (int i = tid; i < 128 * 32; i += 256) {
        const int r  = i >> 5;
        const int c0 = (i & 31) * 2;
        const int m  = m0 + r;
        const int s  = m & (S_ - 1);
        const int bb = m >> 11;
        const float2 v1 = *(float2*)&Cs[r * 132 + c0];
        const float2 v2 = *(float2*)&Cs[r * 132 + c0 + 64];
        const int ti = (s << 6) + c0;
        const float c_0 = g_cos[ti],     s_0 = g_sin[ti];
        const float c_1 = g_cos[ti + 1], s_1 = g_sin[ti + 1];
        const float o1_0 = (v1.x * c_0 - v2.x * s_0) * scq;
        const float o1_1 = (v1.y * c_1 - v2.y * s_1) * scq;
        const float o2_0 = (v1.x * s_0 + v2.x * c_0) * scq;
        const float o2_1 = (v1.y * s_1 + v2.y * c_1) * scq;

        __nv_bfloat16 h0, l0, h1, l1, h2, l2, h3, l3;
        split1(o1_0, h0, l0); split1(o1_1, h1, l1);
        split1(o2_0, h2, l2); split1(o2_1, h3, l3);

        const size_t base = ((size_t)(bb * H_ + h) * S_ + s) * HD_;
        *(__nv_bfloat162*)&Dhi[base + c0]      = __nv_bfloat162(h0, h1);
        *(__nv_bfloat162*)&Dlo[base + c0]      = __nv_bfloat162(l0, l1);
        *(__nv_bfloat162*)&Dhi[base + c0 + 64] = __nv_bfloat162(h2, h3);
        *(__nv_bfloat162*)&Dlo[base + c0 + 64] = __nv_bfloat162(l2, l3);
    }
}

// ---------------------------------------------------------------------------
// Output projection: fp16 single-product GEMM, fp32 row-major epilogue.
// ---------------------------------------------------------------------------
#define TCBUF16o (2u * TCT16)
#define TC16_SMEM_BYTES (3u * TCBUF16o)

__global__ void __launch_bounds__(256)
sgemm_out_f16(const __half* __restrict__ A16, const __half* __restrict__ B16,
              float* __restrict__ C)
{
    extern __shared__ char smem[];
    const uint32_t sbase = smem_u32(smem);

    const int tid  = threadIdx.x;
    const int lane = tid & 31;
    const int w    = tid >> 5;
    const int m0w  = (w >> 2) * 64;
    const int n0w  = (w & 3) * 32;

    const int m0 = blockIdx.y * 128;
    const int n0 = blockIdx.x * 128;

    uint32_t swofs[4];
#pragma unroll
    for (int t = 0; t < 4; t++) {
        const int u = tid + (t << 8);
        swofs[t] = swz128((uint32_t)((u >> 3) * 128 + (u & 7) * 16));
    }

    float acc[4][4][4];
#pragma unroll
    for (int i = 0; i < 4; i++)
#pragma unroll
        for (int j = 0; j < 4; j++)
#pragma unroll
            for (int r = 0; r < 4; r++) acc[i][j][r] = 0.0f;

    const uint32_t arow = (uint32_t)(m0w + (lane & 15));
    const uint32_t acol = (uint32_t)((lane >> 4) << 4);
    const uint32_t browx = (uint32_t)(n0w + (lane & 7) + ((lane >> 4) << 3));
    const uint32_t bcol  = (uint32_t)(((lane >> 3) & 1) << 4);

#define LOAD_CHUNKO(c, buf)                                                    \
    {                                                                          \
        const uint32_t bofs = sbase + (uint32_t)(buf) * TCBUF16o;              \
        const int k0 = (c) * 64;                                               \
        _Pragma("unroll")                                                      \
        for (int t = 0; t < 4; t++) {                                          \
            const int u = tid + (t << 8);                                      \
            const int r = u >> 3;                                              \
            const int c16 = u & 7;                                             \
            const size_t ga = (size_t)(m0 + r) * D_ + k0 + c16 * 8;            \
            const size_t gb = (size_t)(n0 + r) * D_ + k0 + c16 * 8;            \
            cp16(bofs + 0u * TCT16 + swofs[t], A16 + ga);                      \
            cp16(bofs + 1u * TCT16 + swofs[t], B16 + gb);                      \
        }                                                                      \
        CP_COMMIT();                                                           \
    }

    LOAD_CHUNKO(0, 0);
    LOAD_CHUNKO(1, 1);

    int buf = 0;
    for (int c = 0; c < 32; c++) {
        if (c < 31) {
            asm volatile("cp.async.wait_group 1;" ::: "memory");
        } else {
            asm volatile("cp.async.wait_group 0;" ::: "memory");
        }
        __syncthreads();
        if (c + 2 < 32) {
            const int nb = (buf + 2 >= 3) ? buf - 1 : buf + 2;
            LOAD_CHUNKO(c + 2, nb);
        }

        const uint32_t bofs = sbase + (uint32_t)buf * TCBUF16o;
        const uint32_t Ab = bofs + 0u * TCT16;
        const uint32_t Bb = bofs + 1u * TCT16;

#pragma unroll
        for (int kk = 0; kk < 4; kk++) {
            uint32_t ah[4][4], bh[4][2];
            const uint32_t kb = (uint32_t)(kk * 32);
#pragma unroll
            for (int mt = 0; mt < 4; mt++) {
                const uint32_t ofs = swz128((arow + mt * 16u) * 128u + acol + kb);
                ldsm_x4(Ab + ofs, ah[mt]);
            }
#pragma unroll
            for (int ntp = 0; ntp < 2; ntp++) {
                const uint32_t ofs = swz128((browx + ntp * 16u) * 128u + bcol + kb);
                uint32_t b4[4];
                ldsm_x4(Bb + ofs, b4);
                bh[2 * ntp][0] = b4[0];     bh[2 * ntp][1] = b4[1];
                bh[2 * ntp + 1][0] = b4[2]; bh[2 * ntp + 1][1] = b4[3];
            }
#pragma unroll
            for (int mt = 0; mt < 4; mt++)
#pragma unroll
                for (int nt = 0; nt < 4; nt++)
                    mma16816h(acc[mt][nt], ah[mt], bh[nt]);
        }
        __syncthreads();
        buf = (buf + 1 >= 3) ? 0 : buf + 1;
    }

    const int lr = lane >> 2;
    const int lc = (lane & 3) * 2;
#pragma unroll
    for (int mt = 0; mt < 4; mt++) {
#pragma unroll
        for (int rr = 0; rr < 2; rr++) {
            const int m = m0 + m0w + mt * 16 + rr * 8 + lr;
            const int e = rr * 2;
            const size_t dstbase = (size_t)m * D_;
#pragma unroll
            for (int nt = 0; nt < 4; nt++) {
                const int n = n0 + n0w + nt * 8 + lc;
                *(float2*)&C[dstbase + n] =
                    make_float2(acc[mt][nt][e], acc[mt][nt][e + 1]);
            }
        }
    }
}

// ---------------------------------------------------------------------------
// Flash attention: QK bf16 3-prod (Q frags hoisted to registers), PV fp16.
// ---------------------------------------------------------------------------
#define KVSTAGE 49152u
#define FL_SMEM (65536 + 2 * KVSTAGE)

__global__ void __launch_bounds__(256, 1)
flash_tc(const __nv_bfloat16* __restrict__ Qhi, const __nv_bfloat16* __restrict__ Qlo,
         const __nv_bfloat16* __restrict__ Khi, const __nv_bfloat16* __restrict__ Klo,
         const __half* __restrict__ V16,
         __half* __restrict__ AO16)
{
    extern __shared__ char smem[];
    const uint32_t sb = smem_u32(smem);
    const uint32_t sQh = sb;
    const uint32_t sQl = sb + 32768u;

    const int tid  = threadIdx.x;
    const int lane = tid & 31;
    const int w    = tid >> 5;
    const int lr   = lane >> 2;
    const int lc2  = (lane & 3) * 2;

    const int qt = (int)gridDim.x - 1 - (int)blockIdx.x;
    const int h  = blockIdx.y;
    const int b  = blockIdx.z;
    const size_t bh = ((size_t)(b * H_ + h)) * S_ * HD_;

    const __nv_bfloat16* Qhg = Qhi + bh + (size_t)qt * 128 * HD_;
    const __nv_bfloat16* Qlg = Qlo + bh + (size_t)qt * 128 * HD_;

    for (int i = tid; i < 2048; i += 256) {
        const uint32_t r = (uint32_t)(i >> 4);
        const uint32_t cb = (uint32_t)((i & 15) << 4);
        const uint32_t so = swzf(r, cb);
        cp16(sQh + so, Qhg + (size_t)r * HD_ + (i & 15) * 8);
        cp16(sQl + so, Qlg + (size_t)r * HD_ + (i & 15) * 8);
    }
    CP_COMMIT();   // group: Q

#define LOAD_KV(jj, buf)                                                       \
    {                                                                          \
        const uint32_t kvb = sb + 65536u + (uint32_t)(buf) * KVSTAGE;          \
        const size_t rg0 = (size_t)(jj) * 64;                                  \
        for (int i = tid; i < 1024; i += 256) {                                \
            const uint32_t r = (uint32_t)(i >> 4);                             \
            const uint32_t cb = (uint32_t)((i & 15) << 4);                     \
            const uint32_t so = swzf(r, cb);                                   \
            const size_t g = bh + (rg0 + r) * HD_ + (i & 15) * 8;              \
            cp16(kvb + so, Khi + g);                                           \
            cp16(kvb + 16384u + so, Klo + g);                                  \
            cp16(kvb + 32768u + so, V16 + g);                                  \
        }                                                                      \
    }

    LOAD_KV(0, 0);
    CP_COMMIT();   // group: KV0

    // ---- hoist Q fragments (j-invariant) into registers ----
    asm volatile("cp.async.wait_group 1;" ::: "memory");   // Q done
    __syncthreads();
    uint32_t qfh[8][4], qfl[8][4];
#pragma unroll
    for (int kc = 0; kc < 8; kc++) {
        const uint32_t ao_ = swzf((uint32_t)(w * 16 + (lane & 15)),
                                  (uint32_t)(kc * 32 + ((lane >> 4) << 4)));
        ldsm_x4(sQh + ao_, qfh[kc]);
        ldsm_x4(sQl + ao_, qfl[kc]);
    }

    float o[16][4];
#pragma unroll
    for (int i = 0; i < 16; i++)
#pragma unroll
        for (int e = 0; e < 4; e++) o[i][e] = 0.0f;
    float m0 = -1e30f, m1 = -1e30f, l0 = 0.0f, l1 = 0.0f;

    const int jmax = 2 * qt + 1;
    const int rbase = qt * 128 + w * 16 + lr;

    const uint32_t krowx = (uint32_t)((lane & 7) + ((lane >> 4) << 3));
    const uint32_t kcolx = (uint32_t)(((lane >> 3) & 1) << 4);

    for (int j = 0; j <= jmax; j++) {
        if (j < jmax) {
            LOAD_KV(j + 1, (j + 1) & 1);
            CP_COMMIT();
            asm volatile("cp.async.wait_group 1;" ::: "memory");
        } else {
            asm volatile("cp.async.wait_group 0;" ::: "memory");
        }
        __syncthreads();

        const bool active = !(j == jmax && w < 4);
        if (active) {
        const uint32_t kvb = sb + 65536u + (uint32_t)(j & 1) * KVSTAGE;
        const uint32_t sKh = kvb;
        const uint32_t sKl = kvb + 16384u;
        const uint32_t sV  = kvb + 32768u;

        float sacc[8][4];
#pragma unroll
        for (int nt = 0; nt < 8; nt++)
#pragma unroll
            for (int e = 0; e < 4; e++) sacc[nt][e] = 0.0f;

#pragma unroll
        for (int kc = 0; kc < 8; kc++) {
#pragma unroll
            for (int ntp = 0; ntp < 4; ntp++) {
                const uint32_t bo = swzf(krowx + ntp * 16u,
                                         (uint32_t)(kc * 32) + kcolx);
                uint32_t b4h[4], b4l[4];
                ldsm_x4(sKh + bo, b4h);
                ldsm_x4(sKl + bo, b4l);
                mma16816(sacc[2 * ntp],     qfh[kc], &b4h[0]);
                mma16816(sacc[2 * ntp],     qfh[kc], &b4l[0]);
                mma16816(sacc[2 * ntp],     qfl[kc], &b4h[0]);
                mma16816(sacc[2 * ntp + 1], qfh[kc], &b4h[2]);
                mma16816(sacc[2 * ntp + 1], qfh[kc], &b4l[2]);
                mma16816(sacc[2 * ntp + 1], qfl[kc], &b4h[2]);
            }
        }

        if (j >= 2 * qt) {
            const int cb0 = j * 64 + lc2;
#pragma unroll
            for (int nt = 0; nt < 8; nt++)
#pragma unroll
                for (int e = 0; e < 4; e++) {
                    const int col = cb0 + nt * 8 + (e & 1);
                    const int row = rbase + 8 * (e >> 1);
                    if (col > row) sacc[nt][e] = -1e30f;
                }
        }

        float mx0 = -1e30f, mx1 = -1e30f;
#pragma unroll
        for (int nt = 0; nt < 8; nt++) {
            mx0 = fmaxf(mx0, fmaxf(sacc[nt][0], sacc[nt][1]));
            mx1 = fmaxf(mx1, fmaxf(sacc[nt][2], sacc[nt][3]));
        }
        mx0 = fmaxf(mx0, __shfl_xor_sync(0xffffffffu, mx0, 1));
        mx0 = fmaxf(mx0, __shfl_xor_sync(0xffffffffu, mx0, 2));
        mx1 = fmaxf(mx1, __shfl_xor_sync(0xffffffffu, mx1, 1));
        mx1 = fmaxf(mx1, __shfl_xor_sync(0xffffffffu, mx1, 2));

        const float mn0 = fmaxf(m0, mx0);
        const float mn1 = fmaxf(m1, mx1);
        const float al0 = __expf(m0 - mn0);
        const float al1 = __expf(m1 - mn1);
        m0 = mn0; m1 = mn1;

        float s0 = 0.0f, s1 = 0.0f;
#pragma unroll
        for (int nt = 0; nt < 8; nt++) {
            sacc[nt][0] = __expf(sacc[nt][0] - mn0); s0 += sacc[nt][0];
            sacc[nt][1] = __expf(sacc[nt][1] - mn0); s0 += sacc[nt][1];
            sacc[nt][2] = __expf(sacc[nt][2] - mn1); s1 += sacc[nt][2];
            sacc[nt][3] = __expf(sacc[nt][3] - mn1); s1 += sacc[nt][3];
        }
        s0 += __shfl_xor_sync(0xffffffffu, s0, 1);
        s0 += __shfl_xor_sync(0xffffffffu, s0, 2);
        s1 += __shfl_xor_sync(0xffffffffu, s1, 1);
        s1 += __shfl_xor_sync(0xffffffffu, s1, 2);
        l0 = l0 * al0 + s0;
        l1 = l1 * al1 + s1;

#pragma unroll
        for (int dt = 0; dt < 16; dt++) {
            o[dt][0] *= al0; o[dt][1] *= al0;
            o[dt][2] *= al1; o[dt][3] *= al1;
        }

#pragma unroll
        for (int t = 0; t < 4; t++) {
            uint32_t ph[4];
#pragma unroll
            for (int q2 = 0; q2 < 2; q2++)
#pragma unroll
                for (int rr = 0; rr < 2; rr++)
                    ph[q2 * 2 + rr] = packh2(sacc[2 * t + q2][2 * rr],
                                             sacc[2 * t + q2][2 * rr + 1]);
#pragma unroll
            for (int dtp = 0; dtp < 8; dtp++) {
                const uint32_t bo = swzf((uint32_t)(t * 16 + (lane & 15)),
                                         (uint32_t)((2 * dtp + (lane >> 4)) * 16));
                uint32_t b4[4];
                ldsm_x4t(sV + bo, b4);
                mma16816h(o[2 * dtp],     ph, &b4[0]);
                mma16816h(o[2 * dtp + 1], ph, &b4[2]);
            }
        }
        } // active
        __syncthreads();
    }

    const float inv0 = 1.0f / l0;
    const float inv1 = 1.0f / l1;
    const int srow0 = qt * 128 + w * 16 + lr;
    const size_t d0 = ((size_t)(b * S_ + srow0)) * D_ + h * HD_;
    const size_t d1 = ((size_t)(b * S_ + srow0 + 8)) * D_ + h * HD_;
#pragma unroll
    for (int dt = 0; dt < 16; dt++) {
        *(half2*)&AO16[d0 + dt * 8 + lc2] =
            __floats2half2_rn(o[dt][0] * inv0, o[dt][1] * inv0);
        *(half2*)&AO16[d1 + dt * 8 + lc2] =
            __floats2half2_rn(o[dt][2] * inv1, o[dt][3] * inv1);
    }
}

// ---------------------------------------------------------------------------
extern "C" void kernel_launch(void* const* d_in, const int* in_sizes, int n_in,
                              void* d_out, int out_size)
{
    (void)in_sizes; (void)n_in; (void)out_size;
    const float* x  = (const float*)d_in[0];
    const float* Wq = (const float*)d_in[2];
    const float* Wk = (const float*)d_in[3];
    const float* Wv = (const float*)d_in[4];
    const float* Wo = (const float*)d_in[5];
    float* out = (float*)d_out;

    __nv_bfloat16 *xhi, *xlo;
    __nv_bfloat16 *wqhi, *wqlo, *wkhi, *wklo;
    __nv_bfloat16 *qh, *ql, *kh, *kl;
    __half *x16, *wv16, *wo16, *ao16, *v16;
    cudaGetSymbolAddress((void**)&xhi, g_xhi);
    cudaGetSymbolAddress((void**)&xlo, g_xlo);
    cudaGetSymbolAddress((void**)&x16, g_x16);
    cudaGetSymbolAddress((void**)&wqhi, g_wqhi);
    cudaGetSymbolAddress((void**)&wqlo, g_wqlo);
    cudaGetSymbolAddress((void**)&wkhi, g_wkhi);
    cudaGetSymbolAddress((void**)&wklo, g_wklo);
    cudaGetSymbolAddress((void**)&wv16, g_wv16);
    cudaGetSymbolAddress((void**)&wo16, g_wo16);
    cudaGetSymbolAddress((void**)&ao16, g_ao16);
    cudaGetSymbolAddress((void**)&v16, g_v16);
    cudaGetSymbolAddress((void**)&qh, g_qh);
    cudaGetSymbolAddress((void**)&ql, g_ql);
    cudaGetSymbolAddress((void**)&kh, g_kh);
    cudaGetSymbolAddress((void**)&kl, g_kl);

    cudaFuncSetAttribute(sgemm_qkv,
                         cudaFuncAttributeMaxDynamicSharedMemorySize, TC_SMEM_BYTES);
    cudaFuncSetAttribute(sgemm_out_f16,
                         cudaFuncAttributeMaxDynamicSharedMemorySize, TC16_SMEM_BYTES);
    cudaFuncSetAttribute(flash_tc,
                         cudaFuncAttributeMaxDynamicSharedMemorySize, FL_SMEM);

    // 1) all prep (rope tables + splits) in one launch
    prep_all<<<PREP_BLOCKS, 256>>>(x, Wq, Wk, Wv, Wo);

    // 2) merged QKV projections (Q,K bf16 3-prod + rope; V fp16 1-prod)
    QKVPtrs P;
    P.bhi[0] = wqhi; P.blo[0] = wqlo; P.dhi[0] = qh; P.dlo[0] = ql;
    P.bhi[1] = wkhi; P.blo[1] = wklo; P.dhi[1] = kh; P.dlo[1] = kl;
    P.a16 = x16; P.wv16 = wv16; P.v16 = v16;
    dim3 qkvgrid(D_ / 128, (B_ * S_) / 128, 3);
    sgemm_qkv<<<qkvgrid, 256, TC_SMEM_BYTES>>>(xhi, xlo, P);

    // 3) attention
    flash_tc<<<dim3(S_ / 128, H_, B_), 256, FL_SMEM>>>(qh, ql, kh, kl, v16, ao16);

    // 4) output projection
    dim3 ggrid(D_ / 128, (B_ * S_) / 128);
    sgemm_out_f16<<<ggrid, 256, TC16_SMEM_BYTES>>>(ao16, wo16, out);
}

// round 14
// speedup vs baseline: 2.3855x; 1.0692x over previous
#include <cuda_runtime.h>
#include <cuda_bf16.h>
#include <cuda_fp16.h>
#include <math.h>
#include <stdint.h>

#define B_ 2
#define S_ 2048
#define D_ 2048
#define H_ 16
#define HD_ 128

// ---------------- device scratch (no runtime allocation) ----------------
__device__ __nv_bfloat16 g_xhi[B_ * S_ * D_];
__device__ __nv_bfloat16 g_xlo[B_ * S_ * D_];
__device__ __half g_x16[B_ * S_ * D_];
__device__ __nv_bfloat16 g_wqhi[D_ * D_], g_wqlo[D_ * D_];
__device__ __nv_bfloat16 g_wkhi[D_ * D_], g_wklo[D_ * D_];
__device__ __half g_wv16[D_ * D_];
__device__ __half g_wo16[D_ * D_];
__device__ __half g_ao16[B_ * S_ * D_];

// attention operands (head layout [b][h][s][hd])
__device__ __nv_bfloat16 g_qh[B_ * H_ * S_ * HD_], g_ql[B_ * H_ * S_ * HD_];
__device__ __nv_bfloat16 g_kh[B_ * H_ * S_ * HD_], g_kl[B_ * H_ * S_ * HD_];
__device__ __half g_v16[B_ * H_ * S_ * HD_];

__device__ float g_cos[S_ * 64];
__device__ float g_sin[S_ * 64];

// ---------------- helpers ----------------
__device__ __forceinline__ uint32_t smem_u32(const void* p) {
    uint32_t a;
    asm("{ .reg .u64 t; cvta.to.shared.u64 t, %1; cvt.u32.u64 %0, t; }"
        : "=r"(a) : "l"(p));
    return a;
}
static __device__ __forceinline__ uint32_t swz128(uint32_t o) {
    return o ^ ((o >> 3) & 0x70);
}
static __device__ __forceinline__ uint32_t swz64(uint32_t o) {
    return o ^ ((o >> 3) & 0x30);
}
static __device__ __forceinline__ uint32_t swzf(uint32_t row, uint32_t colbyte) {
    return row * 256u + (colbyte ^ ((row & 7u) << 4));
}
__device__ __forceinline__ void cp16(uint32_t saddr, const void* gptr) {
    asm volatile("cp.async.cg.shared.global [%0], [%1], 16;"
                 :: "r"(saddr), "l"(gptr) : "memory");
}
#define CP_COMMIT() asm volatile("cp.async.commit_group;" ::: "memory")

__device__ __forceinline__ void ldsm_x4(uint32_t a, uint32_t* r) {
    asm volatile("ldmatrix.sync.aligned.m8n8.x4.shared.b16 {%0,%1,%2,%3}, [%4];"
                 : "=r"(r[0]), "=r"(r[1]), "=r"(r[2]), "=r"(r[3]) : "r"(a));
}
__device__ __forceinline__ void ldsm_x4t(uint32_t a, uint32_t* r) {
    asm volatile("ldmatrix.sync.aligned.m8n8.x4.trans.shared.b16 {%0,%1,%2,%3}, [%4];"
                 : "=r"(r[0]), "=r"(r[1]), "=r"(r[2]), "=r"(r[3]) : "r"(a));
}
__device__ __forceinline__ void mma16816(float* d, const uint32_t* a, const uint32_t* b) {
    asm volatile(
        "mma.sync.aligned.m16n8k16.row.col.f32.bf16.bf16.f32 "
        "{%0,%1,%2,%3}, {%4,%5,%6,%7}, {%8,%9}, {%0,%1,%2,%3};"
        : "+f"(d[0]), "+f"(d[1]), "+f"(d[2]), "+f"(d[3])
        : "r"(a[0]), "r"(a[1]), "r"(a[2]), "r"(a[3]), "r"(b[0]), "r"(b[1]));
}
__device__ __forceinline__ void mma16816h(float* d, const uint32_t* a, const uint32_t* b) {
    asm volatile(
        "mma.sync.aligned.m16n8k16.row.col.f32.f16.f16.f32 "
        "{%0,%1,%2,%3}, {%4,%5,%6,%7}, {%8,%9}, {%0,%1,%2,%3};"
        : "+f"(d[0]), "+f"(d[1]), "+f"(d[2]), "+f"(d[3])
        : "r"(a[0]), "r"(a[1]), "r"(a[2]), "r"(a[3]), "r"(b[0]), "r"(b[1]));
}
__device__ __forceinline__ uint32_t packh2(float x, float y) {
    half2 t = __floats2half2_rn(x, y);
    return *(uint32_t*)&t;
}
__device__ __forceinline__ void split1(float x, __nv_bfloat16& h, __nv_bfloat16& l) {
    h = __float2bfloat16(x);
    l = __float2bfloat16(x - __bfloat162float(h));
}

// ---------------------------------------------------------------------------
// Mega prep kernel (unchanged).
// ---------------------------------------------------------------------------
#define PREP_BLOCKS 25088

__global__ void prep_all(const float* __restrict__ x,
                         const float* __restrict__ Wq, const float* __restrict__ Wk,
                         const float* __restrict__ Wv, const float* __restrict__ Wo)
{
    const int bid = blockIdx.x;
    const int t   = threadIdx.x;

    if (bid < 512) {
        const int idx = bid * 256 + t;
        const int i = idx & 63;
        const int s = idx >> 6;
        const float inv_freq = (float)pow(10000.0, -(double)i * (1.0 / 64.0));
        const double ang = (double)s * (double)inv_freq;
        double sd, cd;
        sincos(ang, &sd, &cd);
        g_cos[idx] = (float)cd;
        g_sin[idx] = (float)sd;
        return;
    }
    if (bid < 8704) {
        const int i = (bid - 512) * 256 + t;
        float4 v = ((const float4*)x)[i];
        __nv_bfloat16 h0, h1, h2, h3, l0, l1, l2, l3;
        split1(v.x, h0, l0); split1(v.y, h1, l1);
        split1(v.z, h2, l2); split1(v.w, h3, l3);
        ((__nv_bfloat162*)g_xhi)[2 * i]     = __nv_bfloat162(h0, h1);
        ((__nv_bfloat162*)g_xhi)[2 * i + 1] = __nv_bfloat162(h2, h3);
        ((__nv_bfloat162*)g_xlo)[2 * i]     = __nv_bfloat162(l0, l1);
        ((__nv_bfloat162*)g_xlo)[2 * i + 1] = __nv_bfloat162(l2, l3);
        ((half2*)g_x16)[2 * i]     = __floats2half2_rn(v.x, v.y);
        ((half2*)g_x16)[2 * i + 1] = __floats2half2_rn(v.z, v.w);
        return;
    }
    if (bid < 16896) {
        const bool is_q = bid < 12800;
        const int i = (bid - (is_q ? 8704 : 12800)) * 256 + t;
        const float* w = is_q ? Wq : Wk;
        __nv_bfloat16* hi = is_q ? g_wqhi : g_wkhi;
        __nv_bfloat16* lo = is_q ? g_wqlo : g_wklo;
        float4 v = ((const float4*)w)[i];
        __nv_bfloat16 h0, h1, h2, h3, l0, l1, l2, l3;
        split1(v.x, h0, l0); split1(v.y, h1, l1);
        split1(v.z, h2, l2); split1(v.w, h3, l3);
        ((__nv_bfloat162*)hi)[2 * i]     = __nv_bfloat162(h0, h1);
        ((__nv_bfloat162*)hi)[2 * i + 1] = __nv_bfloat162(h2, h3);
        ((__nv_bfloat162*)lo)[2 * i]     = __nv_bfloat162(l0, l1);
        ((__nv_bfloat162*)lo)[2 * i + 1] = __nv_bfloat162(l2, l3);
        return;
    }
    {
        const bool is_v = bid < 20992;
        const int i = (bid - (is_v ? 16896 : 20992)) * 256 + t;
        const float* w = is_v ? Wv : Wo;
        __half* o = is_v ? g_wv16 : g_wo16;
        float4 v = ((const float4*)w)[i];
        ((half2*)o)[2 * i]     = __floats2half2_rn(v.x, v.y);
        ((half2*)o)[2 * i + 1] = __floats2half2_rn(v.z, v.w);
    }
}

// ---------------------------------------------------------------------------
// Merged QKV GEMM, occupancy-2.
//   stage stride 32KB, 3 stages = 96KB -> 2 CTAs/SM.
//   z=0/1 (Q/K): bf16 3-product, BK=32 (8KB tiles, swz64), 512 slots/chunk.
//   z=2   (V):   fp16 1-product, BK=64 (16KB tiles, swz128), 1024 slots/chunk.
// ---------------------------------------------------------------------------
#define TCSTAGE 32768u
#define TC_SMEM_BYTES (3u * TCSTAGE)

struct QKVPtrs {
    const __nv_bfloat16* bhi[2];
    const __nv_bfloat16* blo[2];
    __nv_bfloat16* dhi[2];
    __nv_bfloat16* dlo[2];
    const __half* a16;
    const __half* wv16;
    __half* v16;
};

__global__ void __launch_bounds__(256, 2)
sgemm_qkv(const __nv_bfloat16* __restrict__ Ahi, const __nv_bfloat16* __restrict__ Alo,
          QKVPtrs P)
{
    extern __shared__ char smem[];
    const uint32_t sbase = smem_u32(smem);

    const int z = blockIdx.z;
    const int tid  = threadIdx.x;
    const int lane = tid & 31;
    const int w    = tid >> 5;
    const int m0w  = (w >> 2) * 64;
    const int n0w  = (w & 3) * 32;

    const int m0 = blockIdx.y * 128;
    const int n0 = blockIdx.x * 128;
    const int h  = blockIdx.x;

    float acc[4][4][4];
#pragma unroll
    for (int i = 0; i < 4; i++)
#pragma unroll
        for (int j = 0; j < 4; j++)
#pragma unroll
            for (int r = 0; r < 4; r++) acc[i][j][r] = 0.0f;

    const uint32_t arow = (uint32_t)(m0w + (lane & 15));
    const uint32_t acol = (uint32_t)((lane >> 4) << 4);
    const uint32_t browx = (uint32_t)(n0w + (lane & 7) + ((lane >> 4) << 3));
    const uint32_t bcol  = (uint32_t)(((lane >> 3) & 1) << 4);

    if (z == 2) {
        // ---------------- V path: fp16 single-product, BK=64 ----------------
        const __half* __restrict__ A16 = P.a16;
        const __half* __restrict__ B16 = P.wv16;

        uint32_t swofs[4];
#pragma unroll
        for (int t = 0; t < 4; t++) {
            const int u = tid + (t << 8);
            swofs[t] = swz128((uint32_t)((u >> 3) * 128 + (u & 7) * 16));
        }

#define LOAD_CHUNK16(c, buf)                                                   \
    {                                                                          \
        const uint32_t bofs = sbase + (uint32_t)(buf) * TCSTAGE;               \
        const int k0 = (c) * 64;                                               \
        _Pragma("unroll")                                                      \
        for (int t = 0; t < 4; t++) {                                          \
            const int u = tid + (t << 8);                                      \
            const int r = u >> 3;                                              \
            const int c16 = u & 7;                                             \
            const size_t ga = (size_t)(m0 + r) * D_ + k0 + c16 * 8;            \
            const size_t gb = (size_t)(n0 + r) * D_ + k0 + c16 * 8;            \
            cp16(bofs + 0u + swofs[t], A16 + ga);                              \
            cp16(bofs + 16384u + swofs[t], B16 + gb);                          \
        }                                                                      \
        CP_COMMIT();                                                           \
    }

        LOAD_CHUNK16(0, 0);
        LOAD_CHUNK16(1, 1);

        int buf = 0;
        for (int c = 0; c < 32; c++) {
            if (c < 31) {
                asm volatile("cp.async.wait_group 1;" ::: "memory");
            } else {
                asm volatile("cp.async.wait_group 0;" ::: "memory");
            }
            __syncthreads();
            if (c + 2 < 32) {
                const int nb = (buf + 2 >= 3) ? buf - 1 : buf + 2;
                LOAD_CHUNK16(c + 2, nb);
            }

            const uint32_t bofs = sbase + (uint32_t)buf * TCSTAGE;
            const uint32_t Ab = bofs;
            const uint32_t Bb = bofs + 16384u;

#pragma unroll
            for (int kk = 0; kk < 4; kk++) {
                uint32_t ah[4][4], bh[4][2];
                const uint32_t kb = (uint32_t)(kk * 32);
#pragma unroll
                for (int mt = 0; mt < 4; mt++) {
                    const uint32_t ofs = swz128((arow + mt * 16u) * 128u + acol + kb);
                    ldsm_x4(Ab + ofs, ah[mt]);
                }
#pragma unroll
                for (int ntp = 0; ntp < 2; ntp++) {
                    const uint32_t ofs = swz128((browx + ntp * 16u) * 128u + bcol + kb);
                    uint32_t b4[4];
                    ldsm_x4(Bb + ofs, b4);
                    bh[2 * ntp][0] = b4[0];     bh[2 * ntp][1] = b4[1];
                    bh[2 * ntp + 1][0] = b4[2]; bh[2 * ntp + 1][1] = b4[3];
                }
#pragma unroll
                for (int mt = 0; mt < 4; mt++)
#pragma unroll
                    for (int nt = 0; nt < 4; nt++)
                        mma16816h(acc[mt][nt], ah[mt], bh[nt]);
            }
            __syncthreads();
            buf = (buf + 1 >= 3) ? 0 : buf + 1;
        }

        __half* __restrict__ C16 = P.v16;
        const int lr = lane >> 2;
        const int lc = (lane & 3) * 2;
#pragma unroll
        for (int mt = 0; mt < 4; mt++)
#pragma unroll
            for (int rr = 0; rr < 2; rr++) {
                const int m = m0 + m0w + mt * 16 + rr * 8 + lr;
                const int e = rr * 2;
                const int bb = m >> 11, s = m & (S_ - 1);
                const size_t rowoff = ((size_t)(bb * H_) * S_ + s) * HD_;
#pragma unroll
                for (int nt = 0; nt < 4; nt++) {
                    const int n = n0 + n0w + nt * 8 + lc;
                    const int hh = n >> 7, hd = n & 127;
                    *(half2*)&C16[rowoff + (size_t)hh * S_ * HD_ + hd] =
                        __floats2half2_rn(acc[mt][nt][e], acc[mt][nt][e + 1]);
                }
            }
        return;
    }

    // ---------------- Q/K path: bf16 3-product, BK=32 (swz64) ----------------
    const __nv_bfloat16* __restrict__ Bhi = P.bhi[z];
    const __nv_bfloat16* __restrict__ Blo = P.blo[z];
    __nv_bfloat16* __restrict__ Dhi = P.dhi[z];
    __nv_bfloat16* __restrict__ Dlo = P.dlo[z];

    uint32_t swofs2[2];
#pragma unroll
    for (int t = 0; t < 2; t++) {
        const int u = tid + (t << 8);
        swofs2[t] = swz64((uint32_t)((u >> 2) * 64 + (u & 3) * 16));
    }

#define LOAD_CHUNKQ(c, buf)                                                    \
    {                                                                          \
        const uint32_t bofs = sbase + (uint32_t)(buf) * TCSTAGE;               \
        const int k0 = (c) * 32;                                               \
        _Pragma("unroll")                                                      \
        for (int t = 0; t < 2; t++) {                                          \
            const int u = tid + (t << 8);                                      \
            const int r = u >> 2;                                              \
            const int c16 = u & 3;                                             \
            const size_t ga = (size_t)(m0 + r) * D_ + k0 + c16 * 8;            \
            const size_t gb = (size_t)(n0 + r) * D_ + k0 + c16 * 8;            \
            cp16(bofs + 0u     + swofs2[t], Ahi + ga);                         \
            cp16(bofs + 8192u  + swofs2[t], Alo + ga);                         \
            cp16(bofs + 16384u + swofs2[t], Bhi + gb);                         \
            cp16(bofs + 24576u + swofs2[t], Blo + gb);                         \
        }                                                                      \
        CP_COMMIT();                                                           \
    }

    LOAD_CHUNKQ(0, 0);
    LOAD_CHUNKQ(1, 1);

    int buf = 0;
    for (int c = 0; c < 64; c++) {
        if (c < 63) {
            asm volatile("cp.async.wait_group 1;" ::: "memory");
        } else {
            asm volatile("cp.async.wait_group 0;" ::: "memory");
        }
        __syncthreads();
        if (c + 2 < 64) {
            const int nb = (buf + 2 >= 3) ? buf - 1 : buf + 2;
            LOAD_CHUNKQ(c + 2, nb);
        }

        const uint32_t bofs = sbase + (uint32_t)buf * TCSTAGE;
        const uint32_t Ab_hi = bofs;
        const uint32_t Ab_lo = bofs + 8192u;
        const uint32_t Bb_hi = bofs + 16384u;
        const uint32_t Bb_lo = bofs + 24576u;

#pragma unroll
        for (int kk = 0; kk < 2; kk++) {
            uint32_t ah[4][4], al[4][4], bh[4][2], bl[4][2];
            const uint32_t kb = (uint32_t)(kk * 32);
#pragma unroll
            for (int mt = 0; mt < 4; mt++) {
                const uint32_t ofs = swz64((arow + mt * 16u) * 64u + acol + kb);
                ldsm_x4(Ab_hi + ofs, ah[mt]);
                ldsm_x4(Ab_lo + ofs, al[mt]);
            }
#pragma unroll
            for (int ntp = 0; ntp < 2; ntp++) {
                const uint32_t ofs = swz64((browx + ntp * 16u) * 64u + bcol + kb);
                uint32_t b4h[4], b4l[4];
                ldsm_x4(Bb_hi + ofs, b4h);
                ldsm_x4(Bb_lo + ofs, b4l);
                bh[2 * ntp][0] = b4h[0];     bh[2 * ntp][1] = b4h[1];
                bh[2 * ntp + 1][0] = b4h[2]; bh[2 * ntp + 1][1] = b4h[3];
                bl[2 * ntp][0] = b4l[0];     bl[2 * ntp][1] = b4l[1];
                bl[2 * ntp + 1][0] = b4l[2]; bl[2 * ntp + 1][1] = b4l[3];
            }
#pragma unroll
            for (int mt = 0; mt < 4; mt++)
#pragma unroll
                for (int nt = 0; nt < 4; nt++) {
                    mma16816(acc[mt][nt], ah[mt], bh[nt]);
                    mma16816(acc[mt][nt], ah[mt], bl[nt]);
                    mma16816(acc[mt][nt], al[mt], bh[nt]);
                }
        }
        __syncthreads();
        buf = (buf + 1 >= 3) ? 0 : buf + 1;
    }

    // epilogue: stage fp32 tile, rope, split, store bf16 hi/lo
    float* Cs = (float*)smem;
    const int lr = lane >> 2;
    const int lc = (lane & 3) * 2;
#pragma unroll
    for (int mt = 0; mt < 4; mt++)
#pragma unroll
        for (int rr = 0; rr < 2; rr++) {
            const int rloc = m0w + mt * 16 + rr * 8 + lr;
            const int e = rr * 2;
#pragma unroll
            for (int nt = 0; nt < 4; nt++) {
                const int nloc = n0w + nt * 8 + lc;
                *(float2*)&Cs[rloc * 132 + nloc] =
                    make_float2(acc[mt][nt][e], acc[mt][nt][e + 1]);
            }
        }
    __syncthreads();

    const float scq = (z == 0) ? 0.08838834764831845f : 1.0f;
    for (int i = tid; i < 128 * 32; i += 256) {
        const int r  = i >> 5;
        const int c0 = (i & 31) * 2;
        const int m  = m0 + r;
        const int s  = m & (S_ - 1);
        const int bb = m >> 11;
        const float2 v1 = *(float2*)&Cs[r * 132 + c0];
        const float2 v2 = *(float2*)&Cs[r * 132 + c0 + 64];
        const int ti = (s << 6) + c0;
        const float c_0 = g_cos[ti],     s_0 = g_sin[ti];
        const float c_1 = g_cos[ti + 1], s_1 = g_sin[ti + 1];
        const float o1_0 = (v1.x * c_0 - v2.x * s_0) * scq;
        const float o1_1 = (v1.y * c_1 - v2.y * s_1) * scq;
        const float o2_0 = (v1.x * s_0 + v2.x * c_0) * scq;
        const float o2_1 = (v1.y * s_1 + v2.y * c_1) * scq;

        __nv_bfloat16 h0, l0, h1, l1, h2, l2, h3, l3;
        split1(o1_0, h0, l0); split1(o1_1, h1, l1);
        split1(o2_0, h2, l2); split1(o2_1, h3, l3);

        const size_t base = ((size_t)(bb * H_ + h) * S_ + s) * HD_;
        *(__nv_bfloat162*)&Dhi[base + c0]      = __nv_bfloat162(h0, h1);
        *(__nv_bfloat162*)&Dlo[base + c0]      = __nv_bfloat162(l0, l1);
        *(__nv_bfloat162*)&Dhi[base + c0 + 64] = __nv_bfloat162(h2, h3);
        *(__nv_bfloat162*)&Dlo[base + c0 + 64] = __nv_bfloat162(l2, l3);
    }
}

// ---------------------------------------------------------------------------
// Output projection: fp16 single-product GEMM, occupancy 2.
// ---------------------------------------------------------------------------
#define TC16_SMEM_BYTES (3u * TCSTAGE)

__global__ void __launch_bounds__(256, 2)
sgemm_out_f16(const __half* __restrict__ A16, const __half* __restrict__ B16,
              float* __restrict__ C)
{
    extern __shared__ char smem[];
    const uint32_t sbase = smem_u32(smem);

    const int tid  = threadIdx.x;
    const int lane = tid & 31;
    const int w    = tid >> 5;
    const int m0w  = (w >> 2) * 64;
    const int n0w  = (w & 3) * 32;

    const int m0 = blockIdx.y * 128;
    const int n0 = blockIdx.x * 128;

    uint32_t swofs[4];
#pragma unroll
    for (int t = 0; t < 4; t++) {
        const int u = tid + (t << 8);
        swofs[t] = swz128((uint32_t)((u >> 3) * 128 + (u & 7) * 16));
    }

    float acc[4][4][4];
#pragma unroll
    for (int i = 0; i < 4; i++)
#pragma unroll
        for (int j = 0; j < 4; j++)
#pragma unroll
            for (int r = 0; r < 4; r++) acc[i][j][r] = 0.0f;

    const uint32_t arow = (uint32_t)(m0w + (lane & 15));
    const uint32_t acol = (uint32_t)((lane >> 4) << 4);
    const uint32_t browx = (uint32_t)(n0w + (lane & 7) + ((lane >> 4) << 3));
    const uint32_t bcol  = (uint32_t)(((lane >> 3) & 1) << 4);

#define LOAD_CHUNKO(c, buf)                                                    \
    {                                                                          \
        const uint32_t bofs = sbase + (uint32_t)(buf) * TCSTAGE;               \
        const int k0 = (c) * 64;                                               \
        _Pragma("unroll")                                                      \
        for (int t = 0; t < 4; t++) {                                          \
            const int u = tid + (t << 8);                                      \
            const int r = u >> 3;                                              \
            const int c16 = u & 7;                                             \
            const size_t ga = (size_t)(m0 + r) * D_ + k0 + c16 * 8;            \
            const size_t gb = (size_t)(n0 + r) * D_ + k0 + c16 * 8;            \
            cp16(bofs + 0u + swofs[t], A16 + ga);                              \
            cp16(bofs + 16384u + swofs[t], B16 + gb);                          \
        }                                                                      \
        CP_COMMIT();                                                           \
    }

    LOAD_CHUNKO(0, 0);
    LOAD_CHUNKO(1, 1);

    int buf = 0;
    for (int c = 0; c < 32; c++) {
        if (c < 31) {
            asm volatile("cp.async.wait_group 1;" ::: "memory");
        } else {
            asm volatile("cp.async.wait_group 0;" ::: "memory");
        }
        __syncthreads();
        if (c + 2 < 32) {
            const int nb = (buf + 2 >= 3) ? buf - 1 : buf + 2;
            LOAD_CHUNKO(c + 2, nb);
        }

        const uint32_t bofs = sbase + (uint32_t)buf * TCSTAGE;
        const uint32_t Ab = bofs;
        const uint32_t Bb = bofs + 16384u;

#pragma unroll
        for (int kk = 0; kk < 4; kk++) {
            uint32_t ah[4][4], bh[4][2];
            const uint32_t kb = (uint32_t)(kk * 32);
#pragma unroll
            for (int mt = 0; mt < 4; mt++) {
                const uint32_t ofs = swz128((arow + mt * 16u) * 128u + acol + kb);
                ldsm_x4(Ab + ofs, ah[mt]);
            }
#pragma unroll
            for (int ntp = 0; ntp < 2; ntp++) {
                const uint32_t ofs = swz128((browx + ntp * 16u) * 128u + bcol + kb);
                uint32_t b4[4];
                ldsm_x4(Bb + ofs, b4);
                bh[2 * ntp][0] = b4[0];     bh[2 * ntp][1] = b4[1];
                bh[2 * ntp + 1][0] = b4[2]; bh[2 * ntp + 1][1] = b4[3];
            }
#pragma unroll
            for (int mt = 0; mt < 4; mt++)
#pragma unroll
                for (int nt = 0; nt < 4; nt++)
                    mma16816h(acc[mt][nt], ah[mt], bh[nt]);
        }
        __syncthreads();
        buf = (buf + 1 >= 3) ? 0 : buf + 1;
    }

    const int lr = lane >> 2;
    const int lc = (lane & 3) * 2;
#pragma unroll
    for (int mt = 0; mt < 4; mt++) {
#pragma unroll
        for (int rr = 0; rr < 2; rr++) {
            const int m = m0 + m0w + mt * 16 + rr * 8 + lr;
            const int e = rr * 2;
            const size_t dstbase = (size_t)m * D_;
#pragma unroll
            for (int nt = 0; nt < 4; nt++) {
                const int n = n0 + n0w + nt * 8 + lc;
                *(float2*)&C[dstbase + n] =
                    make_float2(acc[mt][nt][e], acc[mt][nt][e + 1]);
            }
        }
    }
}

// ---------------------------------------------------------------------------
// Flash attention (unchanged — known good at 4.83e-4 / R12 speed).
// ---------------------------------------------------------------------------
#define KVSTAGE 49152u
#define FL_SMEM (65536 + 2 * KVSTAGE)

__global__ void __launch_bounds__(256, 1)
flash_tc(const __nv_bfloat16* __restrict__ Qhi, const __nv_bfloat16* __restrict__ Qlo,
         const __nv_bfloat16* __restrict__ Khi, const __nv_bfloat16* __restrict__ Klo,
         const __half* __restrict__ V16,
         __half* __restrict__ AO16)
{
    extern __shared__ char smem[];
    const uint32_t sb = smem_u32(smem);
    const uint32_t sQh = sb;
    const uint32_t sQl = sb + 32768u;

    const int tid  = threadIdx.x;
    const int lane = tid & 31;
    const int w    = tid >> 5;
    const int lr   = lane >> 2;
    const int lc2  = (lane & 3) * 2;

    const int qt = (int)gridDim.x - 1 - (int)blockIdx.x;
    const int h  = blockIdx.y;
    const int b  = blockIdx.z;
    const size_t bh = ((size_t)(b * H_ + h)) * S_ * HD_;

    const __nv_bfloat16* Qhg = Qhi + bh + (size_t)qt * 128 * HD_;
    const __nv_bfloat16* Qlg = Qlo + bh + (size_t)qt * 128 * HD_;

    for (int i = tid; i < 2048; i += 256) {
        const uint32_t r = (uint32_t)(i >> 4);
        const uint32_t cb = (uint32_t)((i & 15) << 4);
        const uint32_t so = swzf(r, cb);
        cp16(sQh + so, Qhg + (size_t)r * HD_ + (i & 15) * 8);
        cp16(sQl + so, Qlg + (size_t)r * HD_ + (i & 15) * 8);
    }
    CP_COMMIT();

#define LOAD_KV(jj, buf)                                                       \
    {                                                                          \
        const uint32_t kvb = sb + 65536u + (uint32_t)(buf) * KVSTAGE;          \
        const size_t rg0 = (size_t)(jj) * 64;                                  \
        for (int i = tid; i < 1024; i += 256) {                                \
            const uint32_t r = (uint32_t)(i >> 4);                             \
            const uint32_t cb = (uint32_t)((i & 15) << 4);                     \
            const uint32_t so = swzf(r, cb);                                   \
            const size_t g = bh + (rg0 + r) * HD_ + (i & 15) * 8;              \
            cp16(kvb + so, Khi + g);                                           \
            cp16(kvb + 16384u + so, Klo + g);                                  \
            cp16(kvb + 32768u + so, V16 + g);                                  \
        }                                                                      \
    }

    LOAD_KV(0, 0);
    CP_COMMIT();

    asm volatile("cp.async.wait_group 1;" ::: "memory");
    __syncthreads();
    uint32_t qfh[8][4], qfl[8][4];
#pragma unroll
    for (int kc = 0; kc < 8; kc++) {
        const uint32_t ao_ = swzf((uint32_t)(w * 16 + (lane & 15)),
                                  (uint32_t)(kc * 32 + ((lane >> 4) << 4)));
        ldsm_x4(sQh + ao_, qfh[kc]);
        ldsm_x4(sQl + ao_, qfl[kc]);
    }

    float o[16][4];
#pragma unroll
    for (int i = 0; i < 16; i++)
#pragma unroll
        for (int e = 0; e < 4; e++) o[i][e] = 0.0f;
    float m0 = -1e30f, m1 = -1e30f, l0 = 0.0f, l1 = 0.0f;

    const int jmax = 2 * qt + 1;
    const int rbase = qt * 128 + w * 16 + lr;

    const uint32_t krowx = (uint32_t)((lane & 7) + ((lane >> 4) << 3));
    const uint32_t kcolx = (uint32_t)(((lane >> 3) & 1) << 4);

    for (int j = 0; j <= jmax; j++) {
        if (j < jmax) {
            LOAD_KV(j + 1, (j + 1) & 1);
            CP_COMMIT();
            asm volatile("cp.async.wait_group 1;" ::: "memory");
        } else {
            asm volatile("cp.async.wait_group 0;" ::: "memory");
        }
        __syncthreads();

        const bool active = !(j == jmax && w < 4);
        if (active) {
        const uint32_t kvb = sb + 65536u + (uint32_t)(j & 1) * KVSTAGE;
        const uint32_t sKh = kvb;
        const uint32_t sKl = kvb + 16384u;
        const uint32_t sV  = kvb + 32768u;

        float sacc[8][4];
#pragma unroll
        for (int nt = 0; nt < 8; nt++)
#pragma unroll
            for (int e = 0; e < 4; e++) sacc[nt][e] = 0.0f;

#pragma unroll
        for (int kc = 0; kc < 8; kc++) {
#pragma unroll
            for (int ntp = 0; ntp < 4; ntp++) {
                const uint32_t bo = swzf(krowx + ntp * 16u,
                                         (uint32_t)(kc * 32) + kcolx);
                uint32_t b4h[4], b4l[4];
                ldsm_x4(sKh + bo, b4h);
                ldsm_x4(sKl + bo, b4l);
                mma16816(sacc[2 * ntp],     qfh[kc], &b4h[0]);
                mma16816(sacc[2 * ntp],     qfh[kc], &b4l[0]);
                mma16816(sacc[2 * ntp],     qfl[kc], &b4h[0]);
                mma16816(sacc[2 * ntp + 1], qfh[kc], &b4h[2]);
                mma16816(sacc[2 * ntp + 1], qfh[kc], &b4l[2]);
                mma16816(sacc[2 * ntp + 1], qfl[kc], &b4h[2]);
            }
        }

        if (j >= 2 * qt) {
            const int cb0 = j * 64 + lc2;
#pragma unroll
            for (int nt = 0; nt < 8; nt++)
#pragma unroll
                for (int e = 0; e < 4; e++) {
                    const int col = cb0 + nt * 8 + (e & 1);
                    const int row = rbase + 8 * (e >> 1);
                    if (col > row) sacc[nt][e] = -1e30f;
                }
        }

        float mx0 = -1e30f, mx1 = -1e30f;
#pragma unroll
        for (int nt = 0; nt < 8; nt++) {
            mx0 = fmaxf(mx0, fmaxf(sacc[nt][0], sacc[nt][1]));
            mx1 = fmaxf(mx1, fmaxf(sacc[nt][2], sacc[nt][3]));
        }
        mx0 = fmaxf(mx0, __shfl_xor_sync(0xffffffffu, mx0, 1));
        mx0 = fmaxf(mx0, __shfl_xor_sync(0xffffffffu, mx0, 2));
        mx1 = fmaxf(mx1, __shfl_xor_sync(0xffffffffu, mx1, 1));
        mx1 = fmaxf(mx1, __shfl_xor_sync(0xffffffffu, mx1, 2));

        const float mn0 = fmaxf(m0, mx0);
        const float mn1 = fmaxf(m1, mx1);
        const float al0 = __expf(m0 - mn0);
        const float al1 = __expf(m1 - mn1);
        m0 = mn0; m1 = mn1;

        float s0 = 0.0f, s1 = 0.0f;
#pragma unroll
        for (int nt = 0; nt < 8; nt++) {
            sacc[nt][0] = __expf(sacc[nt][0] - mn0); s0 += sacc[nt][0];
            sacc[nt][1] = __expf(sacc[nt][1] - mn0); s0 += sacc[nt][1];
            sacc[nt][2] = __expf(sacc[nt][2] - mn1); s1 += sacc[nt][2];
            sacc[nt][3] = __expf(sacc[nt][3] - mn1); s1 += sacc[nt][3];
        }
        s0 += __shfl_xor_sync(0xffffffffu, s0, 1);
        s0 += __shfl_xor_sync(0xffffffffu, s0, 2);
        s1 += __shfl_xor_sync(0xffffffffu, s1, 1);
        s1 += __shfl_xor_sync(0xffffffffu, s1, 2);
        l0 = l0 * al0 + s0;
        l1 = l1 * al1 + s1;

#pragma unroll
        for (int dt = 0; dt < 16; dt++) {
            o[dt][0] *= al0; o[dt][1] *= al0;
            o[dt][2] *= al1; o[dt][3] *= al1;
        }

#pragma unroll
        for (int t = 0; t < 4; t++) {
            uint32_t ph[4];
#pragma unroll
            for (int q2 = 0; q2 < 2; q2++)
#pragma unroll
                for (int rr = 0; rr < 2; rr++)
                    ph[q2 * 2 + rr] = packh2(sacc[2 * t + q2][2 * rr],
                                             sacc[2 * t + q2][2 * rr + 1]);
#pragma unroll
            for (int dtp = 0; dtp < 8; dtp++) {
                const uint32_t bo = swzf((uint32_t)(t * 16 + (lane & 15)),
                                         (uint32_t)((2 * dtp + (lane >> 4)) * 16));
                uint32_t b4[4];
                ldsm_x4t(sV + bo, b4);
                mma16816h(o[2 * dtp],     ph, &b4[0]);
                mma16816h(o[2 * dtp + 1], ph, &b4[2]);
            }
        }
        } // active
        __syncthreads();
    }

    const float inv0 = 1.0f / l0;
    const float inv1 = 1.0f / l1;
    const int srow0 = qt * 128 + w * 16 + lr;
    const size_t d0 = ((size_t)(b * S_ + srow0)) * D_ + h * HD_;
    const size_t d1 = ((size_t)(b * S_ + srow0 + 8)) * D_ + h * HD_;
#pragma unroll
    for (int dt = 0; dt < 16; dt++) {
        *(half2*)&AO16[d0 + dt * 8 + lc2] =
            __floats2half2_rn(o[dt][0] * inv0, o[dt][1] * inv0);
        *(half2*)&AO16[d1 + dt * 8 + lc2] =
            __floats2half2_rn(o[dt][2] * inv1, o[dt][3] * inv1);
    }
}

// ---------------------------------------------------------------------------
extern "C" void kernel_launch(void* const* d_in, const int* in_sizes, int n_in,
                              void* d_out, int out_size)
{
    (void)in_sizes; (void)n_in; (void)out_size;
    const float* x  = (const float*)d_in[0];
    const float* Wq = (const float*)d_in[2];
    const float* Wk = (const float*)d_in[3];
    const float* Wv = (const float*)d_in[4];
    const float* Wo = (const float*)d_in[5];
    float* out = (float*)d_out;

    __nv_bfloat16 *xhi, *xlo;
    __nv_bfloat16 *wqhi, *wqlo, *wkhi, *wklo;
    __nv_bfloat16 *qh, *ql, *kh, *kl;
    __half *x16, *wv16, *wo16, *ao16, *v16;
    cudaGetSymbolAddress((void**)&xhi, g_xhi);
    cudaGetSymbolAddress((void**)&xlo, g_xlo);
    cudaGetSymbolAddress((void**)&x16, g_x16);
    cudaGetSymbolAddress((void**)&wqhi, g_wqhi);
    cudaGetSymbolAddress((void**)&wqlo, g_wqlo);
    cudaGetSymbolAddress((void**)&wkhi, g_wkhi);
    cudaGetSymbolAddress((void**)&wklo, g_wklo);
    cudaGetSymbolAddress((void**)&wv16, g_wv16);
    cudaGetSymbolAddress((void**)&wo16, g_wo16);
    cudaGetSymbolAddress((void**)&ao16, g_ao16);
    cudaGetSymbolAddress((void**)&v16, g_v16);
    cudaGetSymbolAddress((void**)&qh, g_qh);
    cudaGetSymbolAddress((void**)&ql, g_ql);
    cudaGetSymbolAddress((void**)&kh, g_kh);
    cudaGetSymbolAddress((void**)&kl, g_kl);

    cudaFuncSetAttribute(sgemm_qkv,
                         cudaFuncAttributeMaxDynamicSharedMemorySize, TC_SMEM_BYTES);
    cudaFuncSetAttribute(sgemm_out_f16,
                         cudaFuncAttributeMaxDynamicSharedMemorySize, TC16_SMEM_BYTES);
    cudaFuncSetAttribute(flash_tc,
                         cudaFuncAttributeMaxDynamicSharedMemorySize, FL_SMEM);

    // 1) all prep in one launch
    prep_all<<<PREP_BLOCKS, 256>>>(x, Wq, Wk, Wv, Wo);

    // 2) merged QKV projections (occupancy 2)
    QKVPtrs P;
    P.bhi[0] = wqhi; P.blo[0] = wqlo; P.dhi[0] = qh; P.dlo[0] = ql;
    P.bhi[1] = wkhi; P.blo[1] = wklo; P.dhi[1] = kh; P.dlo[1] = kl;
    P.a16 = x16; P.wv16 = wv16; P.v16 = v16;
    dim3 qkvgrid(D_ / 128, (B_ * S_) / 128, 3);
    sgemm_qkv<<<qkvgrid, 256, TC_SMEM_BYTES>>>(xhi, xlo, P);

    // 3) attention
    flash_tc<<<dim3(S_ / 128, H_, B_), 256, FL_SMEM>>>(qh, ql, kh, kl, v16, ao16);

    // 4) output projection (occupancy 2)
    dim3 ggrid(D_ / 128, (B_ * S_) / 128);
    sgemm_out_f16<<<ggrid, 256, TC16_SMEM_BYTES>>>(ao16, wo16, out);
}